// round 1
// baseline (speedup 1.0000x reference)
#include <cuda_runtime.h>
#include <cuda_bf16.h>
#include <math.h>

#define B_  2
#define L_  2048
#define D_  2048
#define H_  16
#define DH_ 128
#define M_  (B_ * L_)   // 4096

// ---------------- scratch (no allocations allowed) ----------------
__device__ float g_q[M_ * D_];
__device__ float g_k[M_ * D_];
__device__ float g_v[M_ * D_];
__device__ float g_o[M_ * D_];
__device__ float g_beta[M_ * H_];

// ---------------- generic 128x128x8 tiled SGEMM -------------------
// C[M,N] = A[M,K] @ B[K,N], M given by grid.y*128, no bounds checks
// mode: 0 = plain, 1 = silu epilogue
__global__ void __launch_bounds__(256) sgemm128(const float* __restrict__ A,
                                                const float* __restrict__ Bm,
                                                float* __restrict__ C,
                                                int N, int K, int mode)
{
    __shared__ float As[8][128];
    __shared__ float Bs[8][128];

    const int tid   = threadIdx.x;
    const int crow0 = blockIdx.y * 128;
    const int ccol0 = blockIdx.x * 128;

    const int arow = tid >> 1;
    const int acol = (tid & 1) << 2;
    const int brow = tid >> 5;
    const int bcol = (tid & 31) << 2;

    const int trow = (tid >> 4) << 3;
    const int tcol = (tid & 15) << 3;

    float acc[8][8];
#pragma unroll
    for (int i = 0; i < 8; i++)
#pragma unroll
        for (int j = 0; j < 8; j++) acc[i][j] = 0.f;

    const float* Aptr = A + (crow0 + arow) * K + acol;
    const float* Bptr = Bm + brow * N + ccol0 + bcol;

    for (int kt = 0; kt < K; kt += 8) {
        float4 av = *(const float4*)(Aptr + kt);
        float4 bv = *(const float4*)(Bptr + kt * N);
        As[acol + 0][arow] = av.x;
        As[acol + 1][arow] = av.y;
        As[acol + 2][arow] = av.z;
        As[acol + 3][arow] = av.w;
        *(float4*)&Bs[brow][bcol] = bv;
        __syncthreads();
#pragma unroll
        for (int kk = 0; kk < 8; kk++) {
            float ar[8], br[8];
            *(float4*)&ar[0] = *(const float4*)&As[kk][trow];
            *(float4*)&ar[4] = *(const float4*)&As[kk][trow + 4];
            *(float4*)&br[0] = *(const float4*)&Bs[kk][tcol];
            *(float4*)&br[4] = *(const float4*)&Bs[kk][tcol + 4];
#pragma unroll
            for (int i = 0; i < 8; i++)
#pragma unroll
                for (int j = 0; j < 8; j++) acc[i][j] += ar[i] * br[j];
        }
        __syncthreads();
    }

#pragma unroll
    for (int i = 0; i < 8; i++) {
        int row = crow0 + trow + i;
        float vals[8];
#pragma unroll
        for (int j = 0; j < 8; j++) {
            float v = acc[i][j];
            if (mode == 1) v = v / (1.f + expf(-v));  // silu
            vals[j] = v;
        }
        *(float4*)&C[row * N + ccol0 + tcol]     = *(float4*)&vals[0];
        *(float4*)&C[row * N + ccol0 + tcol + 4] = *(float4*)&vals[4];
    }
}

// ---------------- beta projection: [M,2048] @ [2048,16] + sigmoid ---
__global__ void __launch_bounds__(128) beta_kernel(const float* __restrict__ X,
                                                   const float* __restrict__ Wb,
                                                   float* __restrict__ beta)
{
    __shared__ float x_sh[D_];
    __shared__ float part[8][16];
    const int m = blockIdx.x;

    for (int i = threadIdx.x; i < D_; i += 128) x_sh[i] = X[m * D_ + i];
    __syncthreads();

    const int n     = threadIdx.x & 15;
    const int slice = threadIdx.x >> 4;  // 0..7
    float acc = 0.f;
    const int k0 = slice * (D_ / 8);
#pragma unroll 8
    for (int kk = k0; kk < k0 + (D_ / 8); kk++)
        acc += x_sh[kk] * Wb[kk * H_ + n];
    part[slice][n] = acc;
    __syncthreads();
    if (threadIdx.x < 16) {
        float s = 0.f;
#pragma unroll
        for (int i = 0; i < 8; i++) s += part[i][threadIdx.x];
        beta[m * H_ + threadIdx.x] = 1.f / (1.f + expf(-s));
    }
}

// ---------------- l2-normalize q (with dh^-0.5 scale) and k ----------
// one warp handles one (m,h) row of 128 floats for both q and k
__global__ void __launch_bounds__(128) l2norm_qk(float* __restrict__ q,
                                                 float* __restrict__ k)
{
    const int row  = blockIdx.x * 4 + (threadIdx.x >> 5);  // 0 .. M*H-1
    const int lane = threadIdx.x & 31;

    // q
    {
        float4* p = (float4*)q + row * 32;
        float4 v  = p[lane];
        float ss = v.x * v.x + v.y * v.y + v.z * v.z + v.w * v.w;
#pragma unroll
        for (int off = 16; off; off >>= 1) ss += __shfl_xor_sync(0xffffffffu, ss, off);
        float inv = 0.08838834764831845f / fmaxf(sqrtf(ss), 1e-12f);
        v.x *= inv; v.y *= inv; v.z *= inv; v.w *= inv;
        p[lane] = v;
    }
    // k
    {
        float4* p = (float4*)k + row * 32;
        float4 v  = p[lane];
        float ss = v.x * v.x + v.y * v.y + v.z * v.z + v.w * v.w;
#pragma unroll
        for (int off = 16; off; off >>= 1) ss += __shfl_xor_sync(0xffffffffu, ss, off);
        float inv = 1.0f / fmaxf(sqrtf(ss), 1e-12f);
        v.x *= inv; v.y *= inv; v.z *= inv; v.w *= inv;
        p[lane] = v;
    }
}

// ---------------- delta-rule recurrence + fused RMSNorm --------------
// one CTA per (b,h); thread j owns state column S[:, j] in registers
__global__ void __launch_bounds__(128, 1)
delta_recurrence(const float* __restrict__ q, const float* __restrict__ k,
                 const float* __restrict__ v, const float* __restrict__ beta,
                 const float* __restrict__ w, float* __restrict__ o)
{
    const int bh = blockIdx.x;
    const int b  = bh >> 4;
    const int h  = bh & 15;
    const int j  = threadIdx.x;

    __shared__ float k_sh[128];
    __shared__ float q_sh[128];
    __shared__ float red[4];

    float S[128];
#pragma unroll
    for (int i = 0; i < 128; i++) S[i] = 0.f;

    const float wj   = w[j];
    const int  base0 = b * L_ * D_ + h * DH_;

    for (int l = 0; l < L_; l++) {
        const int base = base0 + l * D_;
        k_sh[j] = k[base + j];
        q_sh[j] = q[base + j];
        const float vj = v[base + j];
        const float bt = beta[(b * L_ + l) * H_ + h];
        __syncthreads();

        // v_pred = S_col . k   (4 independent accumulator chains)
        const float4* k4 = (const float4*)k_sh;
        const float4* q4 = (const float4*)q_sh;
        float vp0 = 0.f, vp1 = 0.f, vp2 = 0.f, vp3 = 0.f;
#pragma unroll
        for (int i = 0; i < 32; i++) {
            float4 kv = k4[i];
            vp0 += S[4 * i + 0] * kv.x;
            vp1 += S[4 * i + 1] * kv.y;
            vp2 += S[4 * i + 2] * kv.z;
            vp3 += S[4 * i + 3] * kv.w;
        }
        const float delta = (vj - ((vp0 + vp1) + (vp2 + vp3))) * bt;

        // S += k * delta ; o = S_new . q  (fused)
        float o0 = 0.f, o1 = 0.f, o2 = 0.f, o3 = 0.f;
#pragma unroll
        for (int i = 0; i < 32; i++) {
            float4 kv = k4[i];
            float4 qv = q4[i];
            S[4 * i + 0] += kv.x * delta; o0 += S[4 * i + 0] * qv.x;
            S[4 * i + 1] += kv.y * delta; o1 += S[4 * i + 1] * qv.y;
            S[4 * i + 2] += kv.z * delta; o2 += S[4 * i + 2] * qv.z;
            S[4 * i + 3] += kv.w * delta; o3 += S[4 * i + 3] * qv.w;
        }
        const float oj = (o0 + o1) + (o2 + o3);

        // fused RMSNorm over the 128 head dims
        float ss = oj * oj;
#pragma unroll
        for (int off = 16; off; off >>= 1) ss += __shfl_xor_sync(0xffffffffu, ss, off);
        if ((j & 31) == 0) red[j >> 5] = ss;
        __syncthreads();
        const float tot = red[0] + red[1] + red[2] + red[3];
        const float r   = rsqrtf(tot * (1.0f / 128.0f) + 1e-5f);
        o[base + j] = oj * r * wj;
    }
}

// ---------------- launch -------------------------------------------
extern "C" void kernel_launch(void* const* d_in, const int* in_sizes, int n_in,
                              void* d_out, int out_size)
{
    const float* X  = (const float*)d_in[0];
    const float* Wq = (const float*)d_in[1];
    const float* Wk = (const float*)d_in[2];
    const float* Wv = (const float*)d_in[3];
    const float* Wb = (const float*)d_in[4];
    const float* wn = (const float*)d_in[5];
    const float* Wo = (const float*)d_in[6];
    float* out = (float*)d_out;

    float *gq, *gk, *gv, *go, *gb;
    cudaGetSymbolAddress((void**)&gq, g_q);
    cudaGetSymbolAddress((void**)&gk, g_k);
    cudaGetSymbolAddress((void**)&gv, g_v);
    cudaGetSymbolAddress((void**)&go, g_o);
    cudaGetSymbolAddress((void**)&gb, g_beta);

    dim3 grid(D_ / 128, M_ / 128);  // (16, 32)

    sgemm128<<<grid, 256>>>(X, Wq, gq, D_, D_, 0);
    sgemm128<<<grid, 256>>>(X, Wk, gk, D_, D_, 0);
    sgemm128<<<grid, 256>>>(X, Wv, gv, D_, D_, 1);   // silu fused
    beta_kernel<<<M_, 128>>>(X, Wb, gb);
    l2norm_qk<<<(M_ * H_) / 4, 128>>>(gq, gk);
    delta_recurrence<<<B_ * H_, 128>>>(gq, gk, gv, gb, wn, go);
    sgemm128<<<grid, 256>>>(go, Wo, out, D_, D_, 0);
}

// round 3
// speedup vs baseline: 1.3131x; 1.3131x over previous
#include <cuda_runtime.h>
#include <cuda_bf16.h>
#include <math.h>
#include <stdint.h>

#define B_  2
#define L_  2048
#define D_  2048
#define H_  16
#define DH_ 128
#define M_  (B_ * L_)   // 4096

// ================= scratch (device globals; no allocations) =================
__device__ float g_q[M_ * D_];
__device__ float g_k[M_ * D_];
__device__ float g_v[M_ * D_];
__device__ float g_o[M_ * D_];
__device__ float g_beta[M_ * H_];
__device__ __nv_bfloat16 g_Ahi[M_ * D_];       // hi/lo split of GEMM A operand (X, then o)
__device__ __nv_bfloat16 g_Alo[M_ * D_];
__device__ __nv_bfloat16 g_Whi[4 * D_ * D_];   // transposed weights [N,K], order q,k,v,o
__device__ __nv_bfloat16 g_Wlo[4 * D_ * D_];

// ================= helpers =================
__device__ __forceinline__ uint32_t smem_u32(const void* p) {
    uint32_t a;
    asm("{ .reg .u64 t; cvta.to.shared.u64 t, %1; cvt.u32.u64 %0, t; }" : "=r"(a) : "l"(p));
    return a;
}
__device__ __forceinline__ void cp16(uint32_t dst, const void* src) {
    asm volatile("cp.async.cg.shared.global [%0], [%1], 16;" :: "r"(dst), "l"(src));
}
#define CP_COMMIT() asm volatile("cp.async.commit_group;" ::: "memory")
#define CP_WAIT(n)  asm volatile("cp.async.wait_group %0;" :: "n"(n) : "memory")

#define LDSM_X4(r0, r1, r2, r3, addr)                                            \
    asm volatile("ldmatrix.sync.aligned.m8n8.x4.shared.b16 {%0,%1,%2,%3}, [%4];" \
        : "=r"(r0), "=r"(r1), "=r"(r2), "=r"(r3) : "r"(addr))
#define LDSM_X2(r0, r1, addr)                                                    \
    asm volatile("ldmatrix.sync.aligned.m8n8.x2.shared.b16 {%0,%1}, [%2];"       \
        : "=r"(r0), "=r"(r1) : "r"(addr))

__device__ __forceinline__ void mma_bf16(float* d, const uint32_t* a, const uint32_t* b) {
    asm volatile(
        "mma.sync.aligned.m16n8k16.row.col.f32.bf16.bf16.f32 "
        "{%0,%1,%2,%3}, {%4,%5,%6,%7}, {%8,%9}, {%0,%1,%2,%3};"
        : "+f"(d[0]), "+f"(d[1]), "+f"(d[2]), "+f"(d[3])
        : "r"(a[0]), "r"(a[1]), "r"(a[2]), "r"(a[3]), "r"(b[0]), "r"(b[1]));
}

// ================= split fp32 -> bf16 hi/lo =================
__global__ void __launch_bounds__(256) split_rows(const float4* __restrict__ X,
                                                  uint2* __restrict__ hi,
                                                  uint2* __restrict__ lo) {
    int i = blockIdx.x * 256 + threadIdx.x;
    float4 x = X[i];
    __nv_bfloat16 h0 = __float2bfloat16(x.x), h1 = __float2bfloat16(x.y);
    __nv_bfloat16 h2 = __float2bfloat16(x.z), h3 = __float2bfloat16(x.w);
    __nv_bfloat16 l0 = __float2bfloat16(x.x - __bfloat162float(h0));
    __nv_bfloat16 l1 = __float2bfloat16(x.y - __bfloat162float(h1));
    __nv_bfloat16 l2 = __float2bfloat16(x.z - __bfloat162float(h2));
    __nv_bfloat16 l3 = __float2bfloat16(x.w - __bfloat162float(h3));
    uint2 hv, lv;
    hv.x = ((uint32_t)__bfloat16_as_ushort(h1) << 16) | __bfloat16_as_ushort(h0);
    hv.y = ((uint32_t)__bfloat16_as_ushort(h3) << 16) | __bfloat16_as_ushort(h2);
    lv.x = ((uint32_t)__bfloat16_as_ushort(l1) << 16) | __bfloat16_as_ushort(l0);
    lv.y = ((uint32_t)__bfloat16_as_ushort(l3) << 16) | __bfloat16_as_ushort(l2);
    hi[i] = hv;
    lo[i] = lv;
}

// transpose + split: W[k][n] fp32 -> Wt_hi/lo[n][k] bf16  (grid.z selects matrix)
__global__ void __launch_bounds__(256) split_transpose(
    const float* __restrict__ W0, const float* __restrict__ W1,
    const float* __restrict__ W2, const float* __restrict__ W3,
    __nv_bfloat16* __restrict__ hi, __nv_bfloat16* __restrict__ lo) {
    __shared__ float t[32][33];
    const float* W = (blockIdx.z == 0) ? W0 : (blockIdx.z == 1) ? W1
                   : (blockIdx.z == 2) ? W2 : W3;
    __nv_bfloat16* ho = hi + (size_t)blockIdx.z * D_ * D_;
    __nv_bfloat16* lw = lo + (size_t)blockIdx.z * D_ * D_;
    const int n = blockIdx.x * 32 + threadIdx.x;
    const int k0 = blockIdx.y * 32;
#pragma unroll
    for (int i = threadIdx.y; i < 32; i += 8)
        t[i][threadIdx.x] = W[(size_t)(k0 + i) * D_ + n];
    __syncthreads();
#pragma unroll
    for (int i = threadIdx.y; i < 32; i += 8) {
        const int nn = blockIdx.x * 32 + i;
        float x = t[threadIdx.x][i];
        __nv_bfloat16 hv = __float2bfloat16(x);
        ho[(size_t)nn * D_ + k0 + threadIdx.x] = hv;
        lw[(size_t)nn * D_ + k0 + threadIdx.x] = __float2bfloat16(x - __bfloat162float(hv));
    }
}

// ================= mma.sync bf16-split GEMM =================
// C[M,N] = A[M,K] @ W[K,N]; A hi/lo [M,K] bf16; W hi/lo transposed [N,K] bf16
#define BM 128
#define BN 128
#define BK 32
#define LDS_ 40                     // padded row stride (elements): conflict-free ldmatrix
#define TILE_B (128 * LDS_ * 2)     // bytes per operand tile = 10240
#define STAGE_B (4 * TILE_B)        // Ahi, Alo, Bhi, Blo = 40960
#define SMEM_DYN (2 * STAGE_B)      // 81920
#define NCHUNK (D_ / BK)            // 64

struct GemmArgs {
    const __nv_bfloat16* Bhi[3];
    const __nv_bfloat16* Blo[3];
    float* C[3];
    int mode[3];   // 0 = plain, 1 = silu
};

// each thread: 2 cp16 per operand tile (row = tid/2, chunk pair = tid&1)
__device__ __forceinline__ void load_chunk(uint32_t sbase, int stage,
    const __nv_bfloat16* Ahi, const __nv_bfloat16* Alo,
    const __nv_bfloat16* Bhi, const __nv_bfloat16* Blo,
    int m0, int n0, int kc, int tid) {
    const int r  = tid >> 1;
    const int c0 = (tid & 1) * 2;           // chunks {0,1} or {2,3}
    const uint32_t st = sbase + stage * STAGE_B;
    const size_t koff = (size_t)kc * BK;
    const __nv_bfloat16* srcs[4] = {
        Ahi + (size_t)(m0 + r) * D_ + koff,
        Alo + (size_t)(m0 + r) * D_ + koff,
        Bhi + (size_t)(n0 + r) * D_ + koff,
        Blo + (size_t)(n0 + r) * D_ + koff };
#pragma unroll
    for (int t = 0; t < 4; t++) {
        uint32_t rowb = st + t * TILE_B + r * (LDS_ * 2);
        cp16(rowb + (c0 + 0) * 16, srcs[t] + (c0 + 0) * 8);
        cp16(rowb + (c0 + 1) * 16, srcs[t] + (c0 + 1) * 8);
    }
    CP_COMMIT();
}

__global__ void __launch_bounds__(256, 1) gemm_bf16split(
    const __nv_bfloat16* __restrict__ Ahi, const __nv_bfloat16* __restrict__ Alo,
    GemmArgs args) {
    extern __shared__ char smem_raw[];

    const int z = blockIdx.z;
    const __nv_bfloat16* Bhi = args.Bhi[z];
    const __nv_bfloat16* Blo = args.Blo[z];
    float* C = args.C[z];
    const int mode = args.mode[z];

    const int m0 = blockIdx.y * BM;
    const int n0 = blockIdx.x * BN;
    const int tid = threadIdx.x;
    const int wid = tid >> 5;
    const int lane = tid & 31;

    const int wm = (wid & 1) * 64;   // warp row offset in tile
    const int wn = (wid >> 1) * 32;  // warp col offset in tile

    const uint32_t sbase = smem_u32(smem_raw);

    // per-thread ldmatrix base offsets (bytes, within a tile)
    const uint32_t a_row  = wm + (lane & 15);
    const uint32_t a_colb = ((lane >> 4) << 4);          // 0 or 16 bytes
    const uint32_t b_row  = wn + (lane & 7);
    const uint32_t b_colb = (((lane >> 3) & 1) << 4);    // 0 or 16 bytes

    float acc[4][4][4];
#pragma unroll
    for (int mi = 0; mi < 4; mi++)
#pragma unroll
        for (int ni = 0; ni < 4; ni++)
#pragma unroll
            for (int t = 0; t < 4; t++) acc[mi][ni][t] = 0.f;

    load_chunk(sbase, 0, Ahi, Alo, Bhi, Blo, m0, n0, 0, tid);

    for (int c = 0; c < NCHUNK; c++) {
        const int s = c & 1;
        if (c + 1 < NCHUNK)
            load_chunk(sbase, 1 - s, Ahi, Alo, Bhi, Blo, m0, n0, c + 1, tid);
        if (c + 1 < NCHUNK) { CP_WAIT(1); } else { CP_WAIT(0); }
        __syncthreads();

        const uint32_t st   = sbase + s * STAGE_B;
        const uint32_t tAh  = st;
        const uint32_t tAl  = st + TILE_B;
        const uint32_t tBh  = st + 2 * TILE_B;
        const uint32_t tBl  = st + 3 * TILE_B;

#pragma unroll
        for (int ks = 0; ks < 2; ks++) {
            const uint32_t kb = ks * 32;  // 16 elems = 32 bytes
            uint32_t ah[4][4], al[4][4], bh[4][2], bl[4][2];
#pragma unroll
            for (int mi = 0; mi < 4; mi++) {
                uint32_t off = (a_row + mi * 16) * (LDS_ * 2) + a_colb + kb;
                LDSM_X4(ah[mi][0], ah[mi][1], ah[mi][2], ah[mi][3], tAh + off);
                LDSM_X4(al[mi][0], al[mi][1], al[mi][2], al[mi][3], tAl + off);
            }
#pragma unroll
            for (int ni = 0; ni < 4; ni++) {
                uint32_t off = (b_row + ni * 8) * (LDS_ * 2) + b_colb + kb;
                LDSM_X2(bh[ni][0], bh[ni][1], tBh + off);
                LDSM_X2(bl[ni][0], bl[ni][1], tBl + off);
            }
#pragma unroll
            for (int mi = 0; mi < 4; mi++)
#pragma unroll
                for (int ni = 0; ni < 4; ni++) {
                    mma_bf16(acc[mi][ni], ah[mi], bh[ni]);
                    mma_bf16(acc[mi][ni], ah[mi], bl[ni]);
                    mma_bf16(acc[mi][ni], al[mi], bh[ni]);
                }
        }
        __syncthreads();
    }

    // epilogue
    const int orow = m0 + wm + (lane >> 2);
    const int ocol = n0 + wn + 2 * (lane & 3);
#pragma unroll
    for (int mi = 0; mi < 4; mi++)
#pragma unroll
        for (int ni = 0; ni < 4; ni++) {
            float v0 = acc[mi][ni][0], v1 = acc[mi][ni][1];
            float v2 = acc[mi][ni][2], v3 = acc[mi][ni][3];
            if (mode == 1) {
                v0 = v0 / (1.f + expf(-v0));
                v1 = v1 / (1.f + expf(-v1));
                v2 = v2 / (1.f + expf(-v2));
                v3 = v3 / (1.f + expf(-v3));
            }
            float* p0 = C + (size_t)(orow + mi * 16) * D_ + ocol + ni * 8;
            float* p1 = C + (size_t)(orow + mi * 16 + 8) * D_ + ocol + ni * 8;
            *(float2*)p0 = make_float2(v0, v1);
            *(float2*)p1 = make_float2(v2, v3);
        }
}

// ================= beta projection =================
__global__ void __launch_bounds__(128) beta_kernel(const float* __restrict__ X,
                                                   const float* __restrict__ Wb,
                                                   float* __restrict__ beta) {
    __shared__ float x_sh[D_];
    __shared__ float part[8][16];
    const int m = blockIdx.x;
    for (int i = threadIdx.x; i < D_; i += 128) x_sh[i] = X[(size_t)m * D_ + i];
    __syncthreads();
    const int n = threadIdx.x & 15;
    const int slice = threadIdx.x >> 4;
    float acc = 0.f;
    const int k0 = slice * (D_ / 8);
#pragma unroll 8
    for (int kk = k0; kk < k0 + (D_ / 8); kk++) acc += x_sh[kk] * Wb[kk * H_ + n];
    part[slice][n] = acc;
    __syncthreads();
    if (threadIdx.x < 16) {
        float s = 0.f;
#pragma unroll
        for (int i = 0; i < 8; i++) s += part[i][threadIdx.x];
        beta[(size_t)m * H_ + threadIdx.x] = 1.f / (1.f + expf(-s));
    }
}

// ================= l2-normalize q (with dh^-0.5) and k =================
__global__ void __launch_bounds__(128) l2norm_qk(float* __restrict__ q,
                                                 float* __restrict__ k) {
    const int row = blockIdx.x * 4 + (threadIdx.x >> 5);
    const int lane = threadIdx.x & 31;
    {
        float4* p = (float4*)q + (size_t)row * 32;
        float4 v = p[lane];
        float ss = v.x * v.x + v.y * v.y + v.z * v.z + v.w * v.w;
#pragma unroll
        for (int off = 16; off; off >>= 1) ss += __shfl_xor_sync(0xffffffffu, ss, off);
        float inv = 0.08838834764831845f / fmaxf(sqrtf(ss), 1e-12f);
        v.x *= inv; v.y *= inv; v.z *= inv; v.w *= inv;
        p[lane] = v;
    }
    {
        float4* p = (float4*)k + (size_t)row * 32;
        float4 v = p[lane];
        float ss = v.x * v.x + v.y * v.y + v.z * v.z + v.w * v.w;
#pragma unroll
        for (int off = 16; off; off >>= 1) ss += __shfl_xor_sync(0xffffffffu, ss, off);
        float inv = 1.0f / fmaxf(sqrtf(ss), 1e-12f);
        v.x *= inv; v.y *= inv; v.z *= inv; v.w *= inv;
        p[lane] = v;
    }
}

// ================= delta-rule recurrence + fused RMSNorm =================
__global__ void __launch_bounds__(128, 1)
delta_recurrence(const float* __restrict__ q, const float* __restrict__ k,
                 const float* __restrict__ v, const float* __restrict__ beta,
                 const float* __restrict__ w, float* __restrict__ o) {
    const int bh = blockIdx.x;
    const int b = bh >> 4;
    const int h = bh & 15;
    const int j = threadIdx.x;

    __shared__ float ksh[2][128], qsh[2][128];
    __shared__ float red[2][4];

    float S[128];
#pragma unroll
    for (int i = 0; i < 128; i++) S[i] = 0.f;

    const float wj = w[j];
    const int base0 = b * L_ * D_ + h * DH_;
    const int bb = (b * L_) * H_ + h;

    ksh[0][j] = k[base0 + j];
    qsh[0][j] = q[base0 + j];
    float vr = v[base0 + j];
    float btr = beta[bb];
    float kn = k[base0 + D_ + j];
    float qn = q[base0 + D_ + j];
    float vn = v[base0 + D_ + j];
    float btn = beta[bb + H_];
    __syncthreads();

    for (int l = 0; l < L_; l++) {
        const int buf = l & 1;
        const float4* k4 = (const float4*)ksh[buf];
        const float4* q4 = (const float4*)qsh[buf];

        float vp0 = 0.f, vp1 = 0.f, vp2 = 0.f, vp3 = 0.f;
#pragma unroll
        for (int i = 0; i < 32; i++) {
            float4 kv = k4[i];
            vp0 += S[4 * i + 0] * kv.x;
            vp1 += S[4 * i + 1] * kv.y;
            vp2 += S[4 * i + 2] * kv.z;
            vp3 += S[4 * i + 3] * kv.w;
        }
        const float delta = (vr - ((vp0 + vp1) + (vp2 + vp3))) * btr;

        float o0 = 0.f, o1 = 0.f, o2 = 0.f, o3 = 0.f;
#pragma unroll
        for (int i = 0; i < 32; i++) {
            float4 kv = k4[i], qv = q4[i];
            S[4 * i + 0] += kv.x * delta; o0 += S[4 * i + 0] * qv.x;
            S[4 * i + 1] += kv.y * delta; o1 += S[4 * i + 1] * qv.y;
            S[4 * i + 2] += kv.z * delta; o2 += S[4 * i + 2] * qv.z;
            S[4 * i + 3] += kv.w * delta; o3 += S[4 * i + 3] * qv.w;
        }
        const float oj = (o0 + o1) + (o2 + o3);

        float ss = oj * oj;
#pragma unroll
        for (int off = 16; off; off >>= 1) ss += __shfl_xor_sync(0xffffffffu, ss, off);
        if ((j & 31) == 0) red[buf][j >> 5] = ss;

        if (l + 1 < L_) { ksh[buf ^ 1][j] = kn; qsh[buf ^ 1][j] = qn; }
        __syncthreads();

        const float tot = red[buf][0] + red[buf][1] + red[buf][2] + red[buf][3];
        const float r = rsqrtf(tot * (1.0f / 128.0f) + 1e-5f);
        o[base0 + l * D_ + j] = oj * r * wj;

        vr = vn; btr = btn;
        if (l + 2 < L_) {
            kn = k[base0 + (l + 2) * D_ + j];
            qn = q[base0 + (l + 2) * D_ + j];
            vn = v[base0 + (l + 2) * D_ + j];
            btn = beta[bb + (l + 2) * H_];
        }
    }
}

// ================= launch =================
extern "C" void kernel_launch(void* const* d_in, const int* in_sizes, int n_in,
                              void* d_out, int out_size) {
    const float* X  = (const float*)d_in[0];
    const float* Wq = (const float*)d_in[1];
    const float* Wk = (const float*)d_in[2];
    const float* Wv = (const float*)d_in[3];
    const float* Wb = (const float*)d_in[4];
    const float* wn = (const float*)d_in[5];
    const float* Wo = (const float*)d_in[6];
    float* out = (float*)d_out;

    float *gq, *gk, *gv, *go, *gb;
    __nv_bfloat16 *ahi, *alo, *whi, *wlo;
    cudaGetSymbolAddress((void**)&gq, g_q);
    cudaGetSymbolAddress((void**)&gk, g_k);
    cudaGetSymbolAddress((void**)&gv, g_v);
    cudaGetSymbolAddress((void**)&go, g_o);
    cudaGetSymbolAddress((void**)&gb, g_beta);
    cudaGetSymbolAddress((void**)&ahi, g_Ahi);
    cudaGetSymbolAddress((void**)&alo, g_Alo);
    cudaGetSymbolAddress((void**)&whi, g_Whi);
    cudaGetSymbolAddress((void**)&wlo, g_Wlo);

    cudaFuncSetAttribute(gemm_bf16split, cudaFuncAttributeMaxDynamicSharedMemorySize, SMEM_DYN);

    const int NSPLIT = M_ * D_ / 4 / 256;  // 8192 blocks

    // 1) split X -> bf16 hi/lo ; transpose+split weights
    split_rows<<<NSPLIT, 256>>>((const float4*)X, (uint2*)ahi, (uint2*)alo);
    split_transpose<<<dim3(D_ / 32, D_ / 32, 4), dim3(32, 8)>>>(Wq, Wk, Wv, Wo, whi, wlo);

    // 2) fused q/k/v GEMMs (tensor cores), silu on v
    GemmArgs qa;
    qa.Bhi[0] = whi;                       qa.Blo[0] = wlo;
    qa.Bhi[1] = whi + (size_t)D_ * D_;     qa.Blo[1] = wlo + (size_t)D_ * D_;
    qa.Bhi[2] = whi + (size_t)2 * D_ * D_; qa.Blo[2] = wlo + (size_t)2 * D_ * D_;
    qa.C[0] = gq; qa.C[1] = gk; qa.C[2] = gv;
    qa.mode[0] = 0; qa.mode[1] = 0; qa.mode[2] = 1;
    gemm_bf16split<<<dim3(D_ / BN, M_ / BM, 3), 256, SMEM_DYN>>>(ahi, alo, qa);

    // 3) beta + norms
    beta_kernel<<<M_, 128>>>(X, Wb, gb);
    l2norm_qk<<<(M_ * H_) / 4, 128>>>(gq, gk);

    // 4) sequential delta rule
    delta_recurrence<<<B_ * H_, 128>>>(gq, gk, gv, gb, wn, go);

    // 5) output projection (reuse A split buffers)
    split_rows<<<NSPLIT, 256>>>((const float4*)go, (uint2*)ahi, (uint2*)alo);
    GemmArgs oa;
    oa.Bhi[0] = whi + (size_t)3 * D_ * D_; oa.Blo[0] = wlo + (size_t)3 * D_ * D_;
    oa.Bhi[1] = oa.Bhi[0]; oa.Blo[1] = oa.Blo[0];
    oa.Bhi[2] = oa.Bhi[0]; oa.Blo[2] = oa.Blo[0];
    oa.C[0] = out; oa.C[1] = out; oa.C[2] = out;
    oa.mode[0] = 0; oa.mode[1] = 0; oa.mode[2] = 0;
    gemm_bf16split<<<dim3(D_ / BN, M_ / BM, 1), 256, SMEM_DYN>>>(ahi, alo, oa);
}

// round 4
// speedup vs baseline: 2.3605x; 1.7977x over previous
#include <cuda_runtime.h>
#include <cuda_bf16.h>
#include <math.h>
#include <stdint.h>

#define B_  2
#define L_  2048
#define D_  2048
#define H_  16
#define DH_ 128
#define M_  (B_ * L_)   // 4096
#define C_  32          // chunk length
#define NC_ (L_ / C_)   // 64 chunks per (b,h)
#define NCH_ (B_ * H_ * NC_)  // 2048 chunk-heads

// ================= scratch (device globals; no allocations) =================
__device__ float g_q[M_ * D_];
__device__ float g_k[M_ * D_];
__device__ float g_v[M_ * D_];
__device__ float g_o[M_ * D_];
__device__ float g_beta[M_ * H_];
__device__ __nv_bfloat16 g_Ahi[M_ * D_];
__device__ __nv_bfloat16 g_Alo[M_ * D_];
__device__ __nv_bfloat16 g_Whi[4 * D_ * D_];
__device__ __nv_bfloat16 g_Wlo[4 * D_ * D_];
// chunked delta-rule precompute
__device__ float g_W0[NCH_ * C_ * DH_];           // T(beta*V)  [32][128]
__device__ __nv_bfloat16 g_TKh[NCH_ * C_ * DH_];  // T(beta*K)  [32][128]
__device__ __nv_bfloat16 g_TKl[NCH_ * C_ * DH_];
__device__ __nv_bfloat16 g_Qch[NCH_ * C_ * DH_];  // Q chunk    [32][128]
__device__ __nv_bfloat16 g_Qcl[NCH_ * C_ * DH_];
__device__ __nv_bfloat16 g_KTh[NCH_ * DH_ * C_];  // K^T chunk  [128][32]
__device__ __nv_bfloat16 g_KTl[NCH_ * DH_ * C_];
__device__ __nv_bfloat16 g_Ph[NCH_ * C_ * C_];    // tril(QK^T) [32][32]
__device__ __nv_bfloat16 g_Pl[NCH_ * C_ * C_];

// ================= helpers =================
__device__ __forceinline__ uint32_t smem_u32(const void* p) {
    uint32_t a;
    asm("{ .reg .u64 t; cvta.to.shared.u64 t, %1; cvt.u32.u64 %0, t; }" : "=r"(a) : "l"(p));
    return a;
}
__device__ __forceinline__ void cp16(uint32_t dst, const void* src) {
    asm volatile("cp.async.cg.shared.global [%0], [%1], 16;" :: "r"(dst), "l"(src));
}
#define CP_COMMIT() asm volatile("cp.async.commit_group;" ::: "memory")
#define CP_WAIT(n)  asm volatile("cp.async.wait_group %0;" :: "n"(n) : "memory")

#define LDSM_X4(r0, r1, r2, r3, addr)                                            \
    asm volatile("ldmatrix.sync.aligned.m8n8.x4.shared.b16 {%0,%1,%2,%3}, [%4];" \
        : "=r"(r0), "=r"(r1), "=r"(r2), "=r"(r3) : "r"(addr))
#define LDSM_X2(r0, r1, addr)                                                    \
    asm volatile("ldmatrix.sync.aligned.m8n8.x2.shared.b16 {%0,%1}, [%2];"       \
        : "=r"(r0), "=r"(r1) : "r"(addr))

__device__ __forceinline__ void mma_bf16(float* d, const uint32_t* a, const uint32_t* b) {
    asm volatile(
        "mma.sync.aligned.m16n8k16.row.col.f32.bf16.bf16.f32 "
        "{%0,%1,%2,%3}, {%4,%5,%6,%7}, {%8,%9}, {%0,%1,%2,%3};"
        : "+f"(d[0]), "+f"(d[1]), "+f"(d[2]), "+f"(d[3])
        : "r"(a[0]), "r"(a[1]), "r"(a[2]), "r"(a[3]), "r"(b[0]), "r"(b[1]));
}
__device__ __forceinline__ uint32_t pack_split(float v0, float v1, uint32_t& lo) {
    __nv_bfloat16 h0 = __float2bfloat16(v0), h1 = __float2bfloat16(v1);
    __nv_bfloat16 l0 = __float2bfloat16(v0 - __bfloat162float(h0));
    __nv_bfloat16 l1 = __float2bfloat16(v1 - __bfloat162float(h1));
    lo = ((uint32_t)__bfloat16_as_ushort(l1) << 16) | __bfloat16_as_ushort(l0);
    return ((uint32_t)__bfloat16_as_ushort(h1) << 16) | __bfloat16_as_ushort(h0);
}

// ================= split fp32 -> bf16 hi/lo =================
__global__ void __launch_bounds__(256) split_rows(const float4* __restrict__ X,
                                                  uint2* __restrict__ hi,
                                                  uint2* __restrict__ lo) {
    int i = blockIdx.x * 256 + threadIdx.x;
    float4 x = X[i];
    __nv_bfloat16 h0 = __float2bfloat16(x.x), h1 = __float2bfloat16(x.y);
    __nv_bfloat16 h2 = __float2bfloat16(x.z), h3 = __float2bfloat16(x.w);
    __nv_bfloat16 l0 = __float2bfloat16(x.x - __bfloat162float(h0));
    __nv_bfloat16 l1 = __float2bfloat16(x.y - __bfloat162float(h1));
    __nv_bfloat16 l2 = __float2bfloat16(x.z - __bfloat162float(h2));
    __nv_bfloat16 l3 = __float2bfloat16(x.w - __bfloat162float(h3));
    uint2 hv, lv;
    hv.x = ((uint32_t)__bfloat16_as_ushort(h1) << 16) | __bfloat16_as_ushort(h0);
    hv.y = ((uint32_t)__bfloat16_as_ushort(h3) << 16) | __bfloat16_as_ushort(h2);
    lv.x = ((uint32_t)__bfloat16_as_ushort(l1) << 16) | __bfloat16_as_ushort(l0);
    lv.y = ((uint32_t)__bfloat16_as_ushort(l3) << 16) | __bfloat16_as_ushort(l2);
    hi[i] = hv;
    lo[i] = lv;
}

// transpose + split weights
__global__ void __launch_bounds__(256) split_transpose(
    const float* __restrict__ W0, const float* __restrict__ W1,
    const float* __restrict__ W2, const float* __restrict__ W3,
    __nv_bfloat16* __restrict__ hi, __nv_bfloat16* __restrict__ lo) {
    __shared__ float t[32][33];
    const float* W = (blockIdx.z == 0) ? W0 : (blockIdx.z == 1) ? W1
                   : (blockIdx.z == 2) ? W2 : W3;
    __nv_bfloat16* ho = hi + (size_t)blockIdx.z * D_ * D_;
    __nv_bfloat16* lw = lo + (size_t)blockIdx.z * D_ * D_;
    const int n = blockIdx.x * 32 + threadIdx.x;
    const int k0 = blockIdx.y * 32;
#pragma unroll
    for (int i = threadIdx.y; i < 32; i += 8)
        t[i][threadIdx.x] = W[(size_t)(k0 + i) * D_ + n];
    __syncthreads();
#pragma unroll
    for (int i = threadIdx.y; i < 32; i += 8) {
        const int nn = blockIdx.x * 32 + i;
        float x = t[threadIdx.x][i];
        __nv_bfloat16 hv = __float2bfloat16(x);
        ho[(size_t)nn * D_ + k0 + threadIdx.x] = hv;
        lw[(size_t)nn * D_ + k0 + threadIdx.x] = __float2bfloat16(x - __bfloat162float(hv));
    }
}

// ================= mma.sync bf16-split GEMM (unchanged from R3) =================
#define BM 128
#define BN 128
#define BK 32
#define LDS_ 40
#define TILE_B (128 * LDS_ * 2)
#define STAGE_B (4 * TILE_B)
#define SMEM_DYN (2 * STAGE_B)
#define NCHUNK (D_ / BK)

struct GemmArgs {
    const __nv_bfloat16* Bhi[3];
    const __nv_bfloat16* Blo[3];
    float* C[3];
    int mode[3];
};

__device__ __forceinline__ void load_chunk(uint32_t sbase, int stage,
    const __nv_bfloat16* Ahi, const __nv_bfloat16* Alo,
    const __nv_bfloat16* Bhi, const __nv_bfloat16* Blo,
    int m0, int n0, int kc, int tid) {
    const int r  = tid >> 1;
    const int c0 = (tid & 1) * 2;
    const uint32_t st = sbase + stage * STAGE_B;
    const size_t koff = (size_t)kc * BK;
    const __nv_bfloat16* srcs[4] = {
        Ahi + (size_t)(m0 + r) * D_ + koff,
        Alo + (size_t)(m0 + r) * D_ + koff,
        Bhi + (size_t)(n0 + r) * D_ + koff,
        Blo + (size_t)(n0 + r) * D_ + koff };
#pragma unroll
    for (int t = 0; t < 4; t++) {
        uint32_t rowb = st + t * TILE_B + r * (LDS_ * 2);
        cp16(rowb + (c0 + 0) * 16, srcs[t] + (c0 + 0) * 8);
        cp16(rowb + (c0 + 1) * 16, srcs[t] + (c0 + 1) * 8);
    }
    CP_COMMIT();
}

__global__ void __launch_bounds__(256, 1) gemm_bf16split(
    const __nv_bfloat16* __restrict__ Ahi, const __nv_bfloat16* __restrict__ Alo,
    GemmArgs args) {
    extern __shared__ char smem_raw[];
    const int z = blockIdx.z;
    const __nv_bfloat16* Bhi = args.Bhi[z];
    const __nv_bfloat16* Blo = args.Blo[z];
    float* C = args.C[z];
    const int mode = args.mode[z];

    const int m0 = blockIdx.y * BM;
    const int n0 = blockIdx.x * BN;
    const int tid = threadIdx.x;
    const int wid = tid >> 5;
    const int lane = tid & 31;
    const int wm = (wid & 1) * 64;
    const int wn = (wid >> 1) * 32;
    const uint32_t sbase = smem_u32(smem_raw);

    const uint32_t a_row  = wm + (lane & 15);
    const uint32_t a_colb = ((lane >> 4) << 4);
    const uint32_t b_row  = wn + (lane & 7);
    const uint32_t b_colb = (((lane >> 3) & 1) << 4);

    float acc[4][4][4];
#pragma unroll
    for (int mi = 0; mi < 4; mi++)
#pragma unroll
        for (int ni = 0; ni < 4; ni++)
#pragma unroll
            for (int t = 0; t < 4; t++) acc[mi][ni][t] = 0.f;

    load_chunk(sbase, 0, Ahi, Alo, Bhi, Blo, m0, n0, 0, tid);

    for (int c = 0; c < NCHUNK; c++) {
        const int s = c & 1;
        if (c + 1 < NCHUNK)
            load_chunk(sbase, 1 - s, Ahi, Alo, Bhi, Blo, m0, n0, c + 1, tid);
        if (c + 1 < NCHUNK) { CP_WAIT(1); } else { CP_WAIT(0); }
        __syncthreads();

        const uint32_t st  = sbase + s * STAGE_B;
        const uint32_t tAh = st;
        const uint32_t tAl = st + TILE_B;
        const uint32_t tBh = st + 2 * TILE_B;
        const uint32_t tBl = st + 3 * TILE_B;

#pragma unroll
        for (int ks = 0; ks < 2; ks++) {
            const uint32_t kb = ks * 32;
            uint32_t ah[4][4], al[4][4], bh[4][2], bl[4][2];
#pragma unroll
            for (int mi = 0; mi < 4; mi++) {
                uint32_t off = (a_row + mi * 16) * (LDS_ * 2) + a_colb + kb;
                LDSM_X4(ah[mi][0], ah[mi][1], ah[mi][2], ah[mi][3], tAh + off);
                LDSM_X4(al[mi][0], al[mi][1], al[mi][2], al[mi][3], tAl + off);
            }
#pragma unroll
            for (int ni = 0; ni < 4; ni++) {
                uint32_t off = (b_row + ni * 8) * (LDS_ * 2) + b_colb + kb;
                LDSM_X2(bh[ni][0], bh[ni][1], tBh + off);
                LDSM_X2(bl[ni][0], bl[ni][1], tBl + off);
            }
#pragma unroll
            for (int mi = 0; mi < 4; mi++)
#pragma unroll
                for (int ni = 0; ni < 4; ni++) {
                    mma_bf16(acc[mi][ni], ah[mi], bh[ni]);
                    mma_bf16(acc[mi][ni], ah[mi], bl[ni]);
                    mma_bf16(acc[mi][ni], al[mi], bh[ni]);
                }
        }
        __syncthreads();
    }

    const int orow = m0 + wm + (lane >> 2);
    const int ocol = n0 + wn + 2 * (lane & 3);
#pragma unroll
    for (int mi = 0; mi < 4; mi++)
#pragma unroll
        for (int ni = 0; ni < 4; ni++) {
            float v0 = acc[mi][ni][0], v1 = acc[mi][ni][1];
            float v2 = acc[mi][ni][2], v3 = acc[mi][ni][3];
            if (mode == 1) {
                v0 = v0 / (1.f + expf(-v0));
                v1 = v1 / (1.f + expf(-v1));
                v2 = v2 / (1.f + expf(-v2));
                v3 = v3 / (1.f + expf(-v3));
            }
            float* p0 = C + (size_t)(orow + mi * 16) * D_ + ocol + ni * 8;
            float* p1 = C + (size_t)(orow + mi * 16 + 8) * D_ + ocol + ni * 8;
            *(float2*)p0 = make_float2(v0, v1);
            *(float2*)p1 = make_float2(v2, v3);
        }
}

// ================= beta projection =================
__global__ void __launch_bounds__(128) beta_kernel(const float* __restrict__ X,
                                                   const float* __restrict__ Wb,
                                                   float* __restrict__ beta) {
    __shared__ float x_sh[D_];
    __shared__ float part[8][16];
    const int m = blockIdx.x;
    for (int i = threadIdx.x; i < D_; i += 128) x_sh[i] = X[(size_t)m * D_ + i];
    __syncthreads();
    const int n = threadIdx.x & 15;
    const int slice = threadIdx.x >> 4;
    float acc = 0.f;
    const int k0 = slice * (D_ / 8);
#pragma unroll 8
    for (int kk = k0; kk < k0 + (D_ / 8); kk++) acc += x_sh[kk] * Wb[kk * H_ + n];
    part[slice][n] = acc;
    __syncthreads();
    if (threadIdx.x < 16) {
        float s = 0.f;
#pragma unroll
        for (int i = 0; i < 8; i++) s += part[i][threadIdx.x];
        beta[(size_t)m * H_ + threadIdx.x] = 1.f / (1.f + expf(-s));
    }
}

// ================= l2-normalize q (with dh^-0.5) and k =================
__global__ void __launch_bounds__(128) l2norm_qk(float* __restrict__ q,
                                                 float* __restrict__ k) {
    const int row = blockIdx.x * 4 + (threadIdx.x >> 5);
    const int lane = threadIdx.x & 31;
    {
        float4* p = (float4*)q + (size_t)row * 32;
        float4 v = p[lane];
        float ss = v.x * v.x + v.y * v.y + v.z * v.z + v.w * v.w;
#pragma unroll
        for (int off = 16; off; off >>= 1) ss += __shfl_xor_sync(0xffffffffu, ss, off);
        float inv = 0.08838834764831845f / fmaxf(sqrtf(ss), 1e-12f);
        v.x *= inv; v.y *= inv; v.z *= inv; v.w *= inv;
        p[lane] = v;
    }
    {
        float4* p = (float4*)k + (size_t)row * 32;
        float4 v = p[lane];
        float ss = v.x * v.x + v.y * v.y + v.z * v.z + v.w * v.w;
#pragma unroll
        for (int off = 16; off; off >>= 1) ss += __shfl_xor_sync(0xffffffffu, ss, off);
        float inv = 1.0f / fmaxf(sqrtf(ss), 1e-12f);
        v.x *= inv; v.y *= inv; v.z *= inv; v.w *= inv;
        p[lane] = v;
    }
}

// ================= PRE: per-chunk WY precompute (parallel) =================
// per chunk-head: A = tril(diag(b)KK^T,-1); solve (I+A)[W0|TK] = diag(b)[V|K];
// P = tril(QK^T) incl diag. Outputs W0 fp32, TK/Q/KT/P bf16 hi+lo.
__global__ void __launch_bounds__(128) pre_chunk(
    const float* __restrict__ q, const float* __restrict__ k,
    const float* __restrict__ v, const float* __restrict__ beta,
    float* __restrict__ W0g,
    __nv_bfloat16* __restrict__ TKh, __nv_bfloat16* __restrict__ TKl,
    __nv_bfloat16* __restrict__ Qh,  __nv_bfloat16* __restrict__ Ql,
    __nv_bfloat16* __restrict__ KTh, __nv_bfloat16* __restrict__ KTl,
    __nv_bfloat16* __restrict__ Ph,  __nv_bfloat16* __restrict__ Pl) {
    extern __shared__ float sm[];
    float* Kc  = sm;               // [32][128]
    float* Qc  = Kc + 32 * 128;    // [32][128]
    float* X   = Qc + 32 * 128;    // [32][256]  [bV | bK]
    float* Asm = X + 32 * 256;     // [32][32]
    float* bsm = Asm + 32 * 32;    // [32]

    const int ch = blockIdx.x;
    const int c  = ch & (NC_ - 1);
    const int bh = ch >> 6;
    const int b  = bh >> 4;
    const int h  = bh & 15;
    const int t0 = c * C_;
    const int tid = threadIdx.x;
    const size_t base0 = (size_t)b * L_ * D_ + (size_t)h * DH_;

    if (tid < 32) bsm[tid] = beta[((size_t)b * L_ + t0 + tid) * H_ + h];
    for (int i = tid; i < 32 * 32; i += 128) {
        int r = i >> 5, c4 = (i & 31) * 4;
        const size_t g = base0 + (size_t)(t0 + r) * D_ + c4;
        float4 kv = *(const float4*)(k + g);
        float4 qv = *(const float4*)(q + g);
        float4 vv = *(const float4*)(v + g);
        *(float4*)(Kc + r * 128 + c4) = kv;
        *(float4*)(Qc + r * 128 + c4) = qv;
        *(float4*)(X + r * 256 + c4) = vv;
        *(float4*)(X + r * 256 + 128 + c4) = kv;
    }
    __syncthreads();

    // scale X rows by beta
    for (int i = tid; i < 32 * 64; i += 128) {
        int r = i >> 6, c4 = (i & 63) * 4;
        float bt = bsm[r];
        float4* p = (float4*)(X + r * 256 + c4);
        float4 x = *p;
        x.x *= bt; x.y *= bt; x.z *= bt; x.w *= bt;
        *p = x;
    }

    // A and P: thread t -> row i = t/4, cols j = (t%4)*8 .. +7
    const int i_ = tid >> 2, j0 = (tid & 3) * 8;
    float accA[8], accP[8];
#pragma unroll
    for (int e = 0; e < 8; e++) { accA[e] = 0.f; accP[e] = 0.f; }
    for (int d4 = 0; d4 < 128; d4 += 4) {
        float4 ki = *(const float4*)(Kc + i_ * 128 + d4);
        float4 qi = *(const float4*)(Qc + i_ * 128 + d4);
#pragma unroll
        for (int e = 0; e < 8; e++) {
            float4 kj = *(const float4*)(Kc + (j0 + e) * 128 + d4);
            accA[e] += ki.x * kj.x + ki.y * kj.y + ki.z * kj.z + ki.w * kj.w;
            accP[e] += qi.x * kj.x + qi.y * kj.y + qi.z * kj.z + qi.w * kj.w;
        }
    }
    const float bi = bsm[i_];
#pragma unroll
    for (int e = 0; e < 8; e++) {
        int j = j0 + e;
        Asm[i_ * 32 + j] = (j < i_) ? bi * accA[e] : 0.f;
        float pv = (j <= i_) ? accP[e] : 0.f;
        __nv_bfloat16 phv = __float2bfloat16(pv);
        Ph[(size_t)ch * 1024 + i_ * 32 + j] = phv;
        Pl[(size_t)ch * 1024 + i_ * 32 + j] = __float2bfloat16(pv - __bfloat162float(phv));
    }
    __syncthreads();

    // forward substitution: (I+A) X = rhs  -> X (rows sequential)
    for (int i = 1; i < 32; i++) {
        float f0 = 0.f, f1 = 0.f;
        for (int j = 0; j < i; j++) {
            float a = Asm[i * 32 + j];
            f0 += a * X[j * 256 + tid];
            f1 += a * X[j * 256 + 128 + tid];
        }
        X[i * 256 + tid]       -= f0;
        X[i * 256 + 128 + tid] -= f1;
        __syncthreads();
    }

    // outputs
    for (int i = tid; i < 32 * 128; i += 128) {
        int n = i >> 7, m = i & 127;
        W0g[(size_t)ch * 4096 + i] = X[n * 256 + m];
        float tkv = X[n * 256 + 128 + m];
        __nv_bfloat16 th_ = __float2bfloat16(tkv);
        TKh[(size_t)ch * 4096 + i] = th_;
        TKl[(size_t)ch * 4096 + i] = __float2bfloat16(tkv - __bfloat162float(th_));
        float qv = Qc[n * 128 + m];
        __nv_bfloat16 qh_ = __float2bfloat16(qv);
        Qh[(size_t)ch * 4096 + i] = qh_;
        Ql[(size_t)ch * 4096 + i] = __float2bfloat16(qv - __bfloat162float(qh_));
    }
#pragma unroll
    for (int n = 0; n < 32; n++) {
        float kv = Kc[n * 128 + tid];
        __nv_bfloat16 kh_ = __float2bfloat16(kv);
        KTh[(size_t)ch * 4096 + tid * 32 + n] = kh_;
        KTl[(size_t)ch * 4096 + tid * 32 + n] = __float2bfloat16(kv - __bfloat162float(kh_));
    }
}

// ================= SEQ: sequential chunk chain, MMA-based =================
// one CTA (256 thr) per (b,h). S^T [dv=128][dk=128] lives in step-3 fp32
// accumulator registers; re-split to smem hi/lo each chunk.
// smem layout (bytes):
#define OS_SHI 0
#define OS_SLO 34816
#define OS_WTH 69632
#define OS_WTL 79872
#define OS_TKH 90112
#define OS_TKL 98816
#define OS_QH  107520
#define OS_QL  116224
#define OS_KTH 124928
#define OS_KTL 135168
#define OS_PH  145408
#define OS_PL  147968
#define OS_W0  150528
#define OS_CS  166912
#define SEQ_SMEM 167040
#define SST 272   // S / TK / Q row stride bytes (136 bf16)
#define WST 80    // Wt / KT / P row stride bytes (40 bf16)

__global__ void __launch_bounds__(256, 1) seq_chunk(
    const float* __restrict__ W0g,
    const __nv_bfloat16* __restrict__ TKh, const __nv_bfloat16* __restrict__ TKl,
    const __nv_bfloat16* __restrict__ Qh,  const __nv_bfloat16* __restrict__ Ql,
    const __nv_bfloat16* __restrict__ KTh, const __nv_bfloat16* __restrict__ KTl,
    const __nv_bfloat16* __restrict__ Ph,  const __nv_bfloat16* __restrict__ Pl,
    const float* __restrict__ wnorm, float* __restrict__ o) {
    extern __shared__ char smraw[];
    const int bh = blockIdx.x;
    const int b = bh >> 4, h = bh & 15;
    const int tid = threadIdx.x, wid = tid >> 5, lane = tid & 31;
    const uint32_t sb = smem_u32(smraw);
    float* W0s = (float*)(smraw + OS_W0);
    float* colsum = (float*)(smraw + OS_CS);

    // zero S hi/lo
    for (int i = tid; i < (OS_WTH) / 16; i += 256)
        ((uint4*)smraw)[i] = make_uint4(0, 0, 0, 0);

    float Sfr[2][8][4];
#pragma unroll
    for (int mi = 0; mi < 2; mi++)
#pragma unroll
        for (int ni = 0; ni < 8; ni++)
#pragma unroll
            for (int e = 0; e < 4; e++) Sfr[mi][ni][e] = 0.f;

    const int wm = (wid & 3) * 32;
    const int wn16 = (wid >> 2) * 16;
    const int wn64 = (wid >> 2) * 64;
    const int a_r = lane & 15, a_cB = (lane >> 4) << 4;
    const int b_r = lane & 7,  b_cB = ((lane >> 3) & 1) << 4;
    const int fr = lane >> 2, fc = (lane & 3) * 2;

    float wnr[2][2];
#pragma unroll
    for (int mi = 0; mi < 2; mi++)
#pragma unroll
        for (int pp = 0; pp < 2; pp++)
            wnr[mi][pp] = wnorm[wm + mi * 16 + pp * 8 + fr];

    for (int c = 0; c < NC_; c++) {
        const size_t ch = (size_t)bh * NC_ + c;
        __syncthreads();

        // ---- load chunk operands ----
        {
            const uint4* gtkh = (const uint4*)(TKh + ch * 4096);
            const uint4* gtkl = (const uint4*)(TKl + ch * 4096);
            const uint4* gqh  = (const uint4*)(Qh + ch * 4096);
            const uint4* gql  = (const uint4*)(Ql + ch * 4096);
            for (int i = tid; i < 512; i += 256) {
                int r = i >> 4, qq = (i & 15) * 16;
                *(uint4*)(smraw + OS_TKH + r * SST + qq) = gtkh[i];
                *(uint4*)(smraw + OS_TKL + r * SST + qq) = gtkl[i];
                *(uint4*)(smraw + OS_QH + r * SST + qq) = gqh[i];
                *(uint4*)(smraw + OS_QL + r * SST + qq) = gql[i];
            }
            const uint4* gkth = (const uint4*)(KTh + ch * 4096);
            const uint4* gktl = (const uint4*)(KTl + ch * 4096);
            for (int i = tid; i < 512; i += 256) {
                int r = i >> 2, qq = (i & 3) * 16;
                *(uint4*)(smraw + OS_KTH + r * WST + qq) = gkth[i];
                *(uint4*)(smraw + OS_KTL + r * WST + qq) = gktl[i];
            }
            const uint4* gph = (const uint4*)(Ph + ch * 1024);
            const uint4* gpl = (const uint4*)(Pl + ch * 1024);
            if (tid < 128) {
                int r = tid >> 2, qq = (tid & 3) * 16;
                *(uint4*)(smraw + OS_PH + r * WST + qq) = gph[tid];
                *(uint4*)(smraw + OS_PL + r * WST + qq) = gpl[tid];
            }
            const uint4* gw0 = (const uint4*)(W0g + ch * 4096);
            for (int i = tid; i < 1024; i += 256)
                ((uint4*)(smraw + OS_W0))[i] = gw0[i];
            if (tid < 32) colsum[tid] = 0.f;
        }
        __syncthreads();

        // ---- step 1: Wt = W0^T - Ssm @ TK^T ----
        float acc[2][2][4];
#pragma unroll
        for (int mi = 0; mi < 2; mi++)
#pragma unroll
            for (int ni = 0; ni < 2; ni++)
#pragma unroll
                for (int e = 0; e < 4; e++) acc[mi][ni][e] = 0.f;
#pragma unroll
        for (int ks = 0; ks < 8; ks++) {
            uint32_t ah[2][4], al[2][4], bhf[2][2], blf[2][2];
#pragma unroll
            for (int mi = 0; mi < 2; mi++) {
                uint32_t off = (wm + mi * 16 + a_r) * SST + a_cB + ks * 32;
                LDSM_X4(ah[mi][0], ah[mi][1], ah[mi][2], ah[mi][3], sb + OS_SHI + off);
                LDSM_X4(al[mi][0], al[mi][1], al[mi][2], al[mi][3], sb + OS_SLO + off);
            }
#pragma unroll
            for (int ni = 0; ni < 2; ni++) {
                uint32_t off = (wn16 + ni * 8 + b_r) * SST + b_cB + ks * 32;
                LDSM_X2(bhf[ni][0], bhf[ni][1], sb + OS_TKH + off);
                LDSM_X2(blf[ni][0], blf[ni][1], sb + OS_TKL + off);
            }
#pragma unroll
            for (int mi = 0; mi < 2; mi++)
#pragma unroll
                for (int ni = 0; ni < 2; ni++) {
                    mma_bf16(acc[mi][ni], ah[mi], bhf[ni]);
                    mma_bf16(acc[mi][ni], ah[mi], blf[ni]);
                    mma_bf16(acc[mi][ni], al[mi], bhf[ni]);
                }
        }
        // Wt split -> smem
#pragma unroll
        for (int mi = 0; mi < 2; mi++)
#pragma unroll
            for (int ni = 0; ni < 2; ni++)
#pragma unroll
                for (int pp = 0; pp < 2; pp++) {
                    int m = wm + mi * 16 + fr + pp * 8;
                    int n0 = wn16 + ni * 8 + fc;
                    float v0 = W0s[n0 * 128 + m] - acc[mi][ni][pp * 2 + 0];
                    float v1 = W0s[(n0 + 1) * 128 + m] - acc[mi][ni][pp * 2 + 1];
                    uint32_t lo, hi = pack_split(v0, v1, lo);
                    *(uint32_t*)(smraw + OS_WTH + m * WST + n0 * 2) = hi;
                    *(uint32_t*)(smraw + OS_WTL + m * WST + n0 * 2) = lo;
                }
        __syncthreads();

        // ---- step 2: Ot = Ssm @ Q^T + Wt @ P^T ----
        float oacc[2][2][4];
#pragma unroll
        for (int mi = 0; mi < 2; mi++)
#pragma unroll
            for (int ni = 0; ni < 2; ni++)
#pragma unroll
                for (int e = 0; e < 4; e++) oacc[mi][ni][e] = 0.f;
#pragma unroll
        for (int ks = 0; ks < 8; ks++) {
            uint32_t ah[2][4], al[2][4], bhf[2][2], blf[2][2];
#pragma unroll
            for (int mi = 0; mi < 2; mi++) {
                uint32_t off = (wm + mi * 16 + a_r) * SST + a_cB + ks * 32;
                LDSM_X4(ah[mi][0], ah[mi][1], ah[mi][2], ah[mi][3], sb + OS_SHI + off);
                LDSM_X4(al[mi][0], al[mi][1], al[mi][2], al[mi][3], sb + OS_SLO + off);
            }
#pragma unroll
            for (int ni = 0; ni < 2; ni++) {
                uint32_t off = (wn16 + ni * 8 + b_r) * SST + b_cB + ks * 32;
                LDSM_X2(bhf[ni][0], bhf[ni][1], sb + OS_QH + off);
                LDSM_X2(blf[ni][0], blf[ni][1], sb + OS_QL + off);
            }
#pragma unroll
            for (int mi = 0; mi < 2; mi++)
#pragma unroll
                for (int ni = 0; ni < 2; ni++) {
                    mma_bf16(oacc[mi][ni], ah[mi], bhf[ni]);
                    mma_bf16(oacc[mi][ni], ah[mi], blf[ni]);
                    mma_bf16(oacc[mi][ni], al[mi], bhf[ni]);
                }
        }
#pragma unroll
        for (int ks = 0; ks < 2; ks++) {
            uint32_t ah[2][4], al[2][4], bhf[2][2], blf[2][2];
#pragma unroll
            for (int mi = 0; mi < 2; mi++) {
                uint32_t off = (wm + mi * 16 + a_r) * WST + a_cB + ks * 32;
                LDSM_X4(ah[mi][0], ah[mi][1], ah[mi][2], ah[mi][3], sb + OS_WTH + off);
                LDSM_X4(al[mi][0], al[mi][1], al[mi][2], al[mi][3], sb + OS_WTL + off);
            }
#pragma unroll
            for (int ni = 0; ni < 2; ni++) {
                uint32_t off = (wn16 + ni * 8 + b_r) * WST + b_cB + ks * 32;
                LDSM_X2(bhf[ni][0], bhf[ni][1], sb + OS_PH + off);
                LDSM_X2(blf[ni][0], blf[ni][1], sb + OS_PL + off);
            }
#pragma unroll
            for (int mi = 0; mi < 2; mi++)
#pragma unroll
                for (int ni = 0; ni < 2; ni++) {
                    mma_bf16(oacc[mi][ni], ah[mi], bhf[ni]);
                    mma_bf16(oacc[mi][ni], ah[mi], blf[ni]);
                    mma_bf16(oacc[mi][ni], al[mi], bhf[ni]);
                }
        }
        // column sums (per-token sumsq over dv)
#pragma unroll
        for (int ni = 0; ni < 2; ni++) {
            float s0 = oacc[0][ni][0] * oacc[0][ni][0] + oacc[0][ni][2] * oacc[0][ni][2]
                     + oacc[1][ni][0] * oacc[1][ni][0] + oacc[1][ni][2] * oacc[1][ni][2];
            float s1 = oacc[0][ni][1] * oacc[0][ni][1] + oacc[0][ni][3] * oacc[0][ni][3]
                     + oacc[1][ni][1] * oacc[1][ni][1] + oacc[1][ni][3] * oacc[1][ni][3];
#pragma unroll
            for (int off = 4; off <= 16; off <<= 1) {
                s0 += __shfl_xor_sync(0xffffffffu, s0, off);
                s1 += __shfl_xor_sync(0xffffffffu, s1, off);
            }
            if (lane < 4) {
                atomicAdd(&colsum[wn16 + ni * 8 + 2 * lane], s0);
                atomicAdd(&colsum[wn16 + ni * 8 + 2 * lane + 1], s1);
            }
        }
        __syncthreads();

        // scale + store o (layout [b][l][h*DH+dv])
        {
            const size_t obase = (size_t)b * L_ * D_ + (size_t)h * DH_ + (size_t)(c * C_) * D_;
#pragma unroll
            for (int ni = 0; ni < 2; ni++) {
                int n0 = wn16 + ni * 8 + fc;
                float r0 = rsqrtf(colsum[n0] * (1.f / 128.f) + 1e-5f);
                float r1 = rsqrtf(colsum[n0 + 1] * (1.f / 128.f) + 1e-5f);
#pragma unroll
                for (int mi = 0; mi < 2; mi++)
#pragma unroll
                    for (int pp = 0; pp < 2; pp++) {
                        int m = wm + mi * 16 + fr + pp * 8;
                        o[obase + (size_t)n0 * D_ + m] = oacc[mi][ni][pp * 2] * r0 * wnr[mi][pp];
                        o[obase + (size_t)(n0 + 1) * D_ + m] = oacc[mi][ni][pp * 2 + 1] * r1 * wnr[mi][pp];
                    }
            }
        }

        // ---- step 3: Ssm += Wt @ K  (B = KT) ----
#pragma unroll
        for (int ks = 0; ks < 2; ks++) {
            uint32_t ah[2][4], al[2][4];
#pragma unroll
            for (int mi = 0; mi < 2; mi++) {
                uint32_t off = (wm + mi * 16 + a_r) * WST + a_cB + ks * 32;
                LDSM_X4(ah[mi][0], ah[mi][1], ah[mi][2], ah[mi][3], sb + OS_WTH + off);
                LDSM_X4(al[mi][0], al[mi][1], al[mi][2], al[mi][3], sb + OS_WTL + off);
            }
#pragma unroll
            for (int ni = 0; ni < 8; ni++) {
                uint32_t bhf[2], blf[2];
                uint32_t off = (wn64 + ni * 8 + b_r) * WST + b_cB + ks * 32;
                LDSM_X2(bhf[0], bhf[1], sb + OS_KTH + off);
                LDSM_X2(blf[0], blf[1], sb + OS_KTL + off);
#pragma unroll
                for (int mi = 0; mi < 2; mi++) {
                    mma_bf16(Sfr[mi][ni], ah[mi], bhf);
                    mma_bf16(Sfr[mi][ni], ah[mi], blf);
                    mma_bf16(Sfr[mi][ni], al[mi], bhf);
                }
            }
        }
        // split S -> smem hi/lo for next chunk
#pragma unroll
        for (int mi = 0; mi < 2; mi++)
#pragma unroll
            for (int ni = 0; ni < 8; ni++)
#pragma unroll
                for (int pp = 0; pp < 2; pp++) {
                    int m = wm + mi * 16 + fr + pp * 8;
                    int n0 = wn64 + ni * 8 + fc;
                    uint32_t lo, hi = pack_split(Sfr[mi][ni][pp * 2], Sfr[mi][ni][pp * 2 + 1], lo);
                    *(uint32_t*)(smraw + OS_SHI + m * SST + n0 * 2) = hi;
                    *(uint32_t*)(smraw + OS_SLO + m * SST + n0 * 2) = lo;
                }
    }
}

// ================= launch =================
extern "C" void kernel_launch(void* const* d_in, const int* in_sizes, int n_in,
                              void* d_out, int out_size) {
    const float* X  = (const float*)d_in[0];
    const float* Wq = (const float*)d_in[1];
    const float* Wk = (const float*)d_in[2];
    const float* Wv = (const float*)d_in[3];
    const float* Wb = (const float*)d_in[4];
    const float* wn = (const float*)d_in[5];
    const float* Wo = (const float*)d_in[6];
    float* out = (float*)d_out;

    float *gq, *gk, *gv, *go, *gb, *gW0;
    __nv_bfloat16 *ahi, *alo, *whi, *wlo;
    __nv_bfloat16 *tkh, *tkl, *qch, *qcl, *kth, *ktl, *ph, *pl;
    cudaGetSymbolAddress((void**)&gq, g_q);
    cudaGetSymbolAddress((void**)&gk, g_k);
    cudaGetSymbolAddress((void**)&gv, g_v);
    cudaGetSymbolAddress((void**)&go, g_o);
    cudaGetSymbolAddress((void**)&gb, g_beta);
    cudaGetSymbolAddress((void**)&ahi, g_Ahi);
    cudaGetSymbolAddress((void**)&alo, g_Alo);
    cudaGetSymbolAddress((void**)&whi, g_Whi);
    cudaGetSymbolAddress((void**)&wlo, g_Wlo);
    cudaGetSymbolAddress((void**)&gW0, g_W0);
    cudaGetSymbolAddress((void**)&tkh, g_TKh);
    cudaGetSymbolAddress((void**)&tkl, g_TKl);
    cudaGetSymbolAddress((void**)&qch, g_Qch);
    cudaGetSymbolAddress((void**)&qcl, g_Qcl);
    cudaGetSymbolAddress((void**)&kth, g_KTh);
    cudaGetSymbolAddress((void**)&ktl, g_KTl);
    cudaGetSymbolAddress((void**)&ph, g_Ph);
    cudaGetSymbolAddress((void**)&pl, g_Pl);

    cudaFuncSetAttribute(gemm_bf16split, cudaFuncAttributeMaxDynamicSharedMemorySize, SMEM_DYN);
    cudaFuncSetAttribute(pre_chunk, cudaFuncAttributeMaxDynamicSharedMemorySize, 69760);
    cudaFuncSetAttribute(seq_chunk, cudaFuncAttributeMaxDynamicSharedMemorySize, SEQ_SMEM);

    const int NSPLIT = M_ * D_ / 4 / 256;

    split_rows<<<NSPLIT, 256>>>((const float4*)X, (uint2*)ahi, (uint2*)alo);
    split_transpose<<<dim3(D_ / 32, D_ / 32, 4), dim3(32, 8)>>>(Wq, Wk, Wv, Wo, whi, wlo);

    GemmArgs qa;
    qa.Bhi[0] = whi;                       qa.Blo[0] = wlo;
    qa.Bhi[1] = whi + (size_t)D_ * D_;     qa.Blo[1] = wlo + (size_t)D_ * D_;
    qa.Bhi[2] = whi + (size_t)2 * D_ * D_; qa.Blo[2] = wlo + (size_t)2 * D_ * D_;
    qa.C[0] = gq; qa.C[1] = gk; qa.C[2] = gv;
    qa.mode[0] = 0; qa.mode[1] = 0; qa.mode[2] = 1;
    gemm_bf16split<<<dim3(D_ / BN, M_ / BM, 3), 256, SMEM_DYN>>>(ahi, alo, qa);

    beta_kernel<<<M_, 128>>>(X, Wb, gb);
    l2norm_qk<<<(M_ * H_) / 4, 128>>>(gq, gk);

    pre_chunk<<<NCH_, 128, 69760>>>(gq, gk, gv, gb, gW0, tkh, tkl, qch, qcl, kth, ktl, ph, pl);
    seq_chunk<<<B_ * H_, 256, SEQ_SMEM>>>(gW0, tkh, tkl, qch, qcl, kth, ktl, ph, pl, wn, go);

    split_rows<<<NSPLIT, 256>>>((const float4*)go, (uint2*)ahi, (uint2*)alo);
    GemmArgs oa;
    oa.Bhi[0] = whi + (size_t)3 * D_ * D_; oa.Blo[0] = wlo + (size_t)3 * D_ * D_;
    oa.Bhi[1] = oa.Bhi[0]; oa.Blo[1] = oa.Blo[0];
    oa.Bhi[2] = oa.Bhi[0]; oa.Blo[2] = oa.Blo[0];
    oa.C[0] = out; oa.C[1] = out; oa.C[2] = out;
    oa.mode[0] = 0; oa.mode[1] = 0; oa.mode[2] = 0;
    gemm_bf16split<<<dim3(D_ / BN, M_ / BM, 1), 256, SMEM_DYN>>>(ahi, alo, oa);
}

// round 5
// speedup vs baseline: 2.4342x; 1.0312x over previous
#include <cuda_runtime.h>
#include <cuda_bf16.h>
#include <math.h>
#include <stdint.h>

#define B_  2
#define L_  2048
#define D_  2048
#define H_  16
#define DH_ 128
#define M_  (B_ * L_)   // 4096
#define C_  32          // chunk length
#define NC_ (L_ / C_)   // 64 chunks per (b,h)
#define NCH_ (B_ * H_ * NC_)  // 2048 chunk-heads

// ================= scratch (device globals; no allocations) =================
__device__ float g_q[M_ * D_];
__device__ float g_k[M_ * D_];
__device__ float g_v[M_ * D_];
__device__ float g_o[M_ * D_];
__device__ float g_beta[M_ * H_];
__device__ __nv_bfloat16 g_Ahi[M_ * D_];
__device__ __nv_bfloat16 g_Alo[M_ * D_];
__device__ __nv_bfloat16 g_Whi[4 * D_ * D_];
__device__ __nv_bfloat16 g_Wlo[4 * D_ * D_];
// chunked delta-rule precompute
__device__ float g_W0[NCH_ * C_ * DH_];
__device__ __nv_bfloat16 g_TKh[NCH_ * C_ * DH_];
__device__ __nv_bfloat16 g_TKl[NCH_ * C_ * DH_];
__device__ __nv_bfloat16 g_Qch[NCH_ * C_ * DH_];
__device__ __nv_bfloat16 g_Qcl[NCH_ * C_ * DH_];
__device__ __nv_bfloat16 g_KTh[NCH_ * DH_ * C_];
__device__ __nv_bfloat16 g_KTl[NCH_ * DH_ * C_];
__device__ __nv_bfloat16 g_Ph[NCH_ * C_ * C_];
__device__ __nv_bfloat16 g_Pl[NCH_ * C_ * C_];

// ================= helpers =================
__device__ __forceinline__ uint32_t smem_u32(const void* p) {
    uint32_t a;
    asm("{ .reg .u64 t; cvta.to.shared.u64 t, %1; cvt.u32.u64 %0, t; }" : "=r"(a) : "l"(p));
    return a;
}
__device__ __forceinline__ void cp16(uint32_t dst, const void* src) {
    asm volatile("cp.async.cg.shared.global [%0], [%1], 16;" :: "r"(dst), "l"(src));
}
#define CP_COMMIT() asm volatile("cp.async.commit_group;" ::: "memory")
#define CP_WAIT(n)  asm volatile("cp.async.wait_group %0;" :: "n"(n) : "memory")

#define LDSM_X4(r0, r1, r2, r3, addr)                                            \
    asm volatile("ldmatrix.sync.aligned.m8n8.x4.shared.b16 {%0,%1,%2,%3}, [%4];" \
        : "=r"(r0), "=r"(r1), "=r"(r2), "=r"(r3) : "r"(addr))
#define LDSM_X2(r0, r1, addr)                                                    \
    asm volatile("ldmatrix.sync.aligned.m8n8.x2.shared.b16 {%0,%1}, [%2];"       \
        : "=r"(r0), "=r"(r1) : "r"(addr))

__device__ __forceinline__ void mma_bf16(float* d, const uint32_t* a, const uint32_t* b) {
    asm volatile(
        "mma.sync.aligned.m16n8k16.row.col.f32.bf16.bf16.f32 "
        "{%0,%1,%2,%3}, {%4,%5,%6,%7}, {%8,%9}, {%0,%1,%2,%3};"
        : "+f"(d[0]), "+f"(d[1]), "+f"(d[2]), "+f"(d[3])
        : "r"(a[0]), "r"(a[1]), "r"(a[2]), "r"(a[3]), "r"(b[0]), "r"(b[1]));
}
__device__ __forceinline__ uint32_t pack_split(float v0, float v1, uint32_t& lo) {
    __nv_bfloat16 h0 = __float2bfloat16(v0), h1 = __float2bfloat16(v1);
    __nv_bfloat16 l0 = __float2bfloat16(v0 - __bfloat162float(h0));
    __nv_bfloat16 l1 = __float2bfloat16(v1 - __bfloat162float(h1));
    lo = ((uint32_t)__bfloat16_as_ushort(l1) << 16) | __bfloat16_as_ushort(l0);
    return ((uint32_t)__bfloat16_as_ushort(h1) << 16) | __bfloat16_as_ushort(h0);
}

// ================= split fp32 -> bf16 hi/lo =================
__global__ void __launch_bounds__(256) split_rows(const float4* __restrict__ X,
                                                  uint2* __restrict__ hi,
                                                  uint2* __restrict__ lo) {
    int i = blockIdx.x * 256 + threadIdx.x;
    float4 x = X[i];
    __nv_bfloat16 h0 = __float2bfloat16(x.x), h1 = __float2bfloat16(x.y);
    __nv_bfloat16 h2 = __float2bfloat16(x.z), h3 = __float2bfloat16(x.w);
    __nv_bfloat16 l0 = __float2bfloat16(x.x - __bfloat162float(h0));
    __nv_bfloat16 l1 = __float2bfloat16(x.y - __bfloat162float(h1));
    __nv_bfloat16 l2 = __float2bfloat16(x.z - __bfloat162float(h2));
    __nv_bfloat16 l3 = __float2bfloat16(x.w - __bfloat162float(h3));
    uint2 hv, lv;
    hv.x = ((uint32_t)__bfloat16_as_ushort(h1) << 16) | __bfloat16_as_ushort(h0);
    hv.y = ((uint32_t)__bfloat16_as_ushort(h3) << 16) | __bfloat16_as_ushort(h2);
    lv.x = ((uint32_t)__bfloat16_as_ushort(l1) << 16) | __bfloat16_as_ushort(l0);
    lv.y = ((uint32_t)__bfloat16_as_ushort(l3) << 16) | __bfloat16_as_ushort(l2);
    hi[i] = hv;
    lo[i] = lv;
}

// transpose + split weights
__global__ void __launch_bounds__(256) split_transpose(
    const float* __restrict__ W0, const float* __restrict__ W1,
    const float* __restrict__ W2, const float* __restrict__ W3,
    __nv_bfloat16* __restrict__ hi, __nv_bfloat16* __restrict__ lo) {
    __shared__ float t[32][33];
    const float* W = (blockIdx.z == 0) ? W0 : (blockIdx.z == 1) ? W1
                   : (blockIdx.z == 2) ? W2 : W3;
    __nv_bfloat16* ho = hi + (size_t)blockIdx.z * D_ * D_;
    __nv_bfloat16* lw = lo + (size_t)blockIdx.z * D_ * D_;
    const int n = blockIdx.x * 32 + threadIdx.x;
    const int k0 = blockIdx.y * 32;
#pragma unroll
    for (int i = threadIdx.y; i < 32; i += 8)
        t[i][threadIdx.x] = W[(size_t)(k0 + i) * D_ + n];
    __syncthreads();
#pragma unroll
    for (int i = threadIdx.y; i < 32; i += 8) {
        const int nn = blockIdx.x * 32 + i;
        float x = t[threadIdx.x][i];
        __nv_bfloat16 hv = __float2bfloat16(x);
        ho[(size_t)nn * D_ + k0 + threadIdx.x] = hv;
        lw[(size_t)nn * D_ + k0 + threadIdx.x] = __float2bfloat16(x - __bfloat162float(hv));
    }
}

// ================= mma.sync bf16-split GEMM: 4-stage, 1 sync/chunk =============
#define BM 128
#define BN 128
#define BK 32
#define LDS_ 40
#define TILE_B (128 * LDS_ * 2)
#define STAGE_B (4 * TILE_B)
#define NSTAGE 4
#define SMEM_DYN (NSTAGE * STAGE_B)   // 163840
#define NCHUNK (D_ / BK)

struct GemmArgs {
    const __nv_bfloat16* Bhi[3];
    const __nv_bfloat16* Blo[3];
    float* C[3];
    int mode[3];
};

__device__ __forceinline__ void load_chunk(uint32_t sbase, int stage,
    const __nv_bfloat16* Ahi, const __nv_bfloat16* Alo,
    const __nv_bfloat16* Bhi, const __nv_bfloat16* Blo,
    int m0, int n0, int kc, int tid) {
    const int r  = tid >> 1;
    const int c0 = (tid & 1) * 2;
    const uint32_t st = sbase + stage * STAGE_B;
    const size_t koff = (size_t)kc * BK;
    const __nv_bfloat16* srcs[4] = {
        Ahi + (size_t)(m0 + r) * D_ + koff,
        Alo + (size_t)(m0 + r) * D_ + koff,
        Bhi + (size_t)(n0 + r) * D_ + koff,
        Blo + (size_t)(n0 + r) * D_ + koff };
#pragma unroll
    for (int t = 0; t < 4; t++) {
        uint32_t rowb = st + t * TILE_B + r * (LDS_ * 2);
        cp16(rowb + (c0 + 0) * 16, srcs[t] + (c0 + 0) * 8);
        cp16(rowb + (c0 + 1) * 16, srcs[t] + (c0 + 1) * 8);
    }
    CP_COMMIT();
}

__global__ void __launch_bounds__(256, 1) gemm_bf16split(
    const __nv_bfloat16* __restrict__ Ahi, const __nv_bfloat16* __restrict__ Alo,
    GemmArgs args) {
    extern __shared__ char smem_raw[];
    const int z = blockIdx.z;
    const __nv_bfloat16* Bhi = args.Bhi[z];
    const __nv_bfloat16* Blo = args.Blo[z];
    float* C = args.C[z];
    const int mode = args.mode[z];

    const int m0 = blockIdx.y * BM;
    const int n0 = blockIdx.x * BN;
    const int tid = threadIdx.x;
    const int wid = tid >> 5;
    const int lane = tid & 31;
    const int wm = (wid & 1) * 64;
    const int wn = (wid >> 1) * 32;
    const uint32_t sbase = smem_u32(smem_raw);

    const uint32_t a_row  = wm + (lane & 15);
    const uint32_t a_colb = ((lane >> 4) << 4);
    const uint32_t b_row  = wn + (lane & 7);
    const uint32_t b_colb = (((lane >> 3) & 1) << 4);

    float acc[4][4][4];
#pragma unroll
    for (int mi = 0; mi < 4; mi++)
#pragma unroll
        for (int ni = 0; ni < 4; ni++)
#pragma unroll
            for (int t = 0; t < 4; t++) acc[mi][ni][t] = 0.f;

    // prologue: 3 chunks in flight
    load_chunk(sbase, 0, Ahi, Alo, Bhi, Blo, m0, n0, 0, tid);
    load_chunk(sbase, 1, Ahi, Alo, Bhi, Blo, m0, n0, 1, tid);
    load_chunk(sbase, 2, Ahi, Alo, Bhi, Blo, m0, n0, 2, tid);

    for (int c = 0; c < NCHUNK; c++) {
        CP_WAIT(2);          // exactly 3 groups pending each iter -> chunk c done
        __syncthreads();     // single barrier per chunk
        if (c + 3 < NCHUNK)
            load_chunk(sbase, (c + 3) & (NSTAGE - 1), Ahi, Alo, Bhi, Blo, m0, n0, c + 3, tid);
        else
            CP_COMMIT();     // keep group-count invariant

        const uint32_t st  = sbase + (c & (NSTAGE - 1)) * STAGE_B;
        const uint32_t tAh = st;
        const uint32_t tAl = st + TILE_B;
        const uint32_t tBh = st + 2 * TILE_B;
        const uint32_t tBl = st + 3 * TILE_B;

#pragma unroll
        for (int ks = 0; ks < 2; ks++) {
            const uint32_t kb = ks * 32;
            uint32_t ah[4][4], al[4][4], bh[4][2], bl[4][2];
#pragma unroll
            for (int mi = 0; mi < 4; mi++) {
                uint32_t off = (a_row + mi * 16) * (LDS_ * 2) + a_colb + kb;
                LDSM_X4(ah[mi][0], ah[mi][1], ah[mi][2], ah[mi][3], tAh + off);
                LDSM_X4(al[mi][0], al[mi][1], al[mi][2], al[mi][3], tAl + off);
            }
#pragma unroll
            for (int ni = 0; ni < 4; ni++) {
                uint32_t off = (b_row + ni * 8) * (LDS_ * 2) + b_colb + kb;
                LDSM_X2(bh[ni][0], bh[ni][1], tBh + off);
                LDSM_X2(bl[ni][0], bl[ni][1], tBl + off);
            }
#pragma unroll
            for (int mi = 0; mi < 4; mi++)
#pragma unroll
                for (int ni = 0; ni < 4; ni++) {
                    mma_bf16(acc[mi][ni], ah[mi], bh[ni]);
                    mma_bf16(acc[mi][ni], ah[mi], bl[ni]);
                    mma_bf16(acc[mi][ni], al[mi], bh[ni]);
                }
        }
    }

    const int orow = m0 + wm + (lane >> 2);
    const int ocol = n0 + wn + 2 * (lane & 3);
#pragma unroll
    for (int mi = 0; mi < 4; mi++)
#pragma unroll
        for (int ni = 0; ni < 4; ni++) {
            float v0 = acc[mi][ni][0], v1 = acc[mi][ni][1];
            float v2 = acc[mi][ni][2], v3 = acc[mi][ni][3];
            if (mode == 1) {
                v0 = v0 / (1.f + expf(-v0));
                v1 = v1 / (1.f + expf(-v1));
                v2 = v2 / (1.f + expf(-v2));
                v3 = v3 / (1.f + expf(-v3));
            }
            float* p0 = C + (size_t)(orow + mi * 16) * D_ + ocol + ni * 8;
            float* p1 = C + (size_t)(orow + mi * 16 + 8) * D_ + ocol + ni * 8;
            *(float2*)p0 = make_float2(v0, v1);
            *(float2*)p1 = make_float2(v2, v3);
        }
}

// ================= beta projection: tiled GEMM [M,2048]@[2048,16] ==========
__global__ void __launch_bounds__(256) beta_gemm(const float* __restrict__ X,
                                                 const float* __restrict__ Wb,
                                                 float* __restrict__ beta) {
    __shared__ float Xs[16][132];
    __shared__ float Ws[128][16];
    const int m0 = blockIdx.x * 16;
    const int tid = threadIdx.x;
    const int row = tid >> 4, n = tid & 15;
    float acc = 0.f;
    for (int kt = 0; kt < D_; kt += 128) {
        for (int i = tid; i < 16 * 32; i += 256) {
            int r = i >> 5, c4 = (i & 31) * 4;
            *(float4*)&Xs[r][c4] = *(const float4*)(X + (size_t)(m0 + r) * D_ + kt + c4);
        }
        for (int i = tid; i < 128 * 4; i += 256) {
            int r = i >> 2, c4 = (i & 3) * 4;
            *(float4*)&Ws[r][c4] = *(const float4*)(Wb + (size_t)(kt + r) * H_ + c4);
        }
        __syncthreads();
#pragma unroll 16
        for (int k = 0; k < 128; k++) acc += Xs[row][k] * Ws[k][n];
        __syncthreads();
    }
    beta[(size_t)(m0 + row) * H_ + n] = 1.f / (1.f + expf(-acc));
}

// ================= PRE: l2norm fused + per-chunk WY precompute ==============
__global__ void __launch_bounds__(128) pre_chunk(
    const float* __restrict__ q, const float* __restrict__ k,
    const float* __restrict__ v, const float* __restrict__ beta,
    float* __restrict__ W0g,
    __nv_bfloat16* __restrict__ TKh, __nv_bfloat16* __restrict__ TKl,
    __nv_bfloat16* __restrict__ Qh,  __nv_bfloat16* __restrict__ Ql,
    __nv_bfloat16* __restrict__ KTh, __nv_bfloat16* __restrict__ KTl,
    __nv_bfloat16* __restrict__ Ph,  __nv_bfloat16* __restrict__ Pl) {
    extern __shared__ float sm[];
    float* Kc  = sm;               // [32][128]
    float* Qc  = Kc + 32 * 128;    // [32][128]
    float* X   = Qc + 32 * 128;    // [32][256]  [bV | bK]
    float* Asm = X + 32 * 256;     // [32][32]
    float* bsm = Asm + 32 * 32;    // [32]

    const int ch = blockIdx.x;
    const int c  = ch & (NC_ - 1);
    const int bh = ch >> 6;
    const int b  = bh >> 4;
    const int h  = bh & 15;
    const int t0 = c * C_;
    const int tid = threadIdx.x;
    const size_t base0 = (size_t)b * L_ * D_ + (size_t)h * DH_;

    if (tid < 32) bsm[tid] = beta[((size_t)b * L_ + t0 + tid) * H_ + h];
    for (int i = tid; i < 32 * 32; i += 128) {
        int r = i >> 5, c4 = (i & 31) * 4;
        const size_t g = base0 + (size_t)(t0 + r) * D_ + c4;
        *(float4*)(Kc + r * 128 + c4) = *(const float4*)(k + g);
        *(float4*)(Qc + r * 128 + c4) = *(const float4*)(q + g);
        *(float4*)(X + r * 256 + c4)  = *(const float4*)(v + g);
    }
    __syncthreads();

    // fused l2norm of k rows + (l2norm * dh^-0.5) of q rows
    {
        const int w = tid >> 5, lane = tid & 31;
#pragma unroll
        for (int r = w * 8; r < w * 8 + 8; r++) {
            float4 kv = *(float4*)(Kc + r * 128 + lane * 4);
            float4 qv = *(float4*)(Qc + r * 128 + lane * 4);
            float sk = kv.x * kv.x + kv.y * kv.y + kv.z * kv.z + kv.w * kv.w;
            float sq = qv.x * qv.x + qv.y * qv.y + qv.z * qv.z + qv.w * qv.w;
#pragma unroll
            for (int off = 16; off; off >>= 1) {
                sk += __shfl_xor_sync(0xffffffffu, sk, off);
                sq += __shfl_xor_sync(0xffffffffu, sq, off);
            }
            float ik = 1.0f / fmaxf(sqrtf(sk), 1e-12f);
            float iq = 0.08838834764831845f / fmaxf(sqrtf(sq), 1e-12f);
            kv.x *= ik; kv.y *= ik; kv.z *= ik; kv.w *= ik;
            qv.x *= iq; qv.y *= iq; qv.z *= iq; qv.w *= iq;
            *(float4*)(Kc + r * 128 + lane * 4) = kv;
            *(float4*)(Qc + r * 128 + lane * 4) = qv;
        }
    }
    __syncthreads();

    // X = [beta*V | beta*Knorm]
    for (int i = tid; i < 32 * 32; i += 128) {
        int r = i >> 5, c4 = (i & 31) * 4;
        float bt = bsm[r];
        float4 kv = *(float4*)(Kc + r * 128 + c4);
        kv.x *= bt; kv.y *= bt; kv.z *= bt; kv.w *= bt;
        *(float4*)(X + r * 256 + 128 + c4) = kv;
        float4 vv = *(float4*)(X + r * 256 + c4);
        vv.x *= bt; vv.y *= bt; vv.z *= bt; vv.w *= bt;
        *(float4*)(X + r * 256 + c4) = vv;
    }

    // A = tril(diag(b)KK^T,-1), P = tril(QK^T)
    const int i_ = tid >> 2, j0 = (tid & 3) * 8;
    float accA[8], accP[8];
#pragma unroll
    for (int e = 0; e < 8; e++) { accA[e] = 0.f; accP[e] = 0.f; }
    for (int d4 = 0; d4 < 128; d4 += 4) {
        float4 ki = *(const float4*)(Kc + i_ * 128 + d4);
        float4 qi = *(const float4*)(Qc + i_ * 128 + d4);
#pragma unroll
        for (int e = 0; e < 8; e++) {
            float4 kj = *(const float4*)(Kc + (j0 + e) * 128 + d4);
            accA[e] += ki.x * kj.x + ki.y * kj.y + ki.z * kj.z + ki.w * kj.w;
            accP[e] += qi.x * kj.x + qi.y * kj.y + qi.z * kj.z + qi.w * kj.w;
        }
    }
    const float bi = bsm[i_];
#pragma unroll
    for (int e = 0; e < 8; e++) {
        int j = j0 + e;
        Asm[i_ * 32 + j] = (j < i_) ? bi * accA[e] : 0.f;
        float pv = (j <= i_) ? accP[e] : 0.f;
        __nv_bfloat16 phv = __float2bfloat16(pv);
        Ph[(size_t)ch * 1024 + i_ * 32 + j] = phv;
        Pl[(size_t)ch * 1024 + i_ * 32 + j] = __float2bfloat16(pv - __bfloat162float(phv));
    }
    __syncthreads();

    // forward substitution: (I+A) X = rhs
    for (int i = 1; i < 32; i++) {
        float f0 = 0.f, f1 = 0.f;
        for (int j = 0; j < i; j++) {
            float a = Asm[i * 32 + j];
            f0 += a * X[j * 256 + tid];
            f1 += a * X[j * 256 + 128 + tid];
        }
        X[i * 256 + tid]       -= f0;
        X[i * 256 + 128 + tid] -= f1;
        __syncthreads();
    }

    // outputs
    for (int i = tid; i < 32 * 128; i += 128) {
        int n = i >> 7, m = i & 127;
        W0g[(size_t)ch * 4096 + i] = X[n * 256 + m];
        float tkv = X[n * 256 + 128 + m];
        __nv_bfloat16 th_ = __float2bfloat16(tkv);
        TKh[(size_t)ch * 4096 + i] = th_;
        TKl[(size_t)ch * 4096 + i] = __float2bfloat16(tkv - __bfloat162float(th_));
        float qv = Qc[n * 128 + m];
        __nv_bfloat16 qh_ = __float2bfloat16(qv);
        Qh[(size_t)ch * 4096 + i] = qh_;
        Ql[(size_t)ch * 4096 + i] = __float2bfloat16(qv - __bfloat162float(qh_));
    }
#pragma unroll
    for (int n = 0; n < 32; n++) {
        float kv = Kc[n * 128 + tid];
        __nv_bfloat16 kh_ = __float2bfloat16(kv);
        KTh[(size_t)ch * 4096 + tid * 32 + n] = kh_;
        KTl[(size_t)ch * 4096 + tid * 32 + n] = __float2bfloat16(kv - __bfloat162float(kh_));
    }
}

// ================= SEQ: sequential chunk chain, MMA-based ===================
#define OS_SHI 0
#define OS_SLO 34816
#define OS_WTH 69632
#define OS_WTL 79872
#define OS_TKH 90112
#define OS_TKL 98816
#define OS_QH  107520
#define OS_QL  116224
#define OS_KTH 124928
#define OS_KTL 135168
#define OS_PH  145408
#define OS_PL  147968
#define OS_W0  150528
#define OS_CS  166912
#define SEQ_SMEM 167040
#define SST 272
#define WST 80

__global__ void __launch_bounds__(256, 1) seq_chunk(
    const float* __restrict__ W0g,
    const __nv_bfloat16* __restrict__ TKh, const __nv_bfloat16* __restrict__ TKl,
    const __nv_bfloat16* __restrict__ Qh,  const __nv_bfloat16* __restrict__ Ql,
    const __nv_bfloat16* __restrict__ KTh, const __nv_bfloat16* __restrict__ KTl,
    const __nv_bfloat16* __restrict__ Ph,  const __nv_bfloat16* __restrict__ Pl,
    const float* __restrict__ wnorm, float* __restrict__ o) {
    extern __shared__ char smraw[];
    const int bh = blockIdx.x;
    const int b = bh >> 4, h = bh & 15;
    const int tid = threadIdx.x, wid = tid >> 5, lane = tid & 31;
    const uint32_t sb = smem_u32(smraw);
    float* W0s = (float*)(smraw + OS_W0);
    float* colsum = (float*)(smraw + OS_CS);

    for (int i = tid; i < (OS_WTH) / 16; i += 256)
        ((uint4*)smraw)[i] = make_uint4(0, 0, 0, 0);

    float Sfr[2][8][4];
#pragma unroll
    for (int mi = 0; mi < 2; mi++)
#pragma unroll
        for (int ni = 0; ni < 8; ni++)
#pragma unroll
            for (int e = 0; e < 4; e++) Sfr[mi][ni][e] = 0.f;

    const int wm = (wid & 3) * 32;
    const int wn16 = (wid >> 2) * 16;
    const int wn64 = (wid >> 2) * 64;
    const int a_r = lane & 15, a_cB = (lane >> 4) << 4;
    const int b_r = lane & 7,  b_cB = ((lane >> 3) & 1) << 4;
    const int fr = lane >> 2, fc = (lane & 3) * 2;

    float wnr[2][2];
#pragma unroll
    for (int mi = 0; mi < 2; mi++)
#pragma unroll
        for (int pp = 0; pp < 2; pp++)
            wnr[mi][pp] = wnorm[wm + mi * 16 + pp * 8 + fr];

    for (int c = 0; c < NC_; c++) {
        const size_t ch = (size_t)bh * NC_ + c;
        __syncthreads();

        {
            const uint4* gtkh = (const uint4*)(TKh + ch * 4096);
            const uint4* gtkl = (const uint4*)(TKl + ch * 4096);
            const uint4* gqh  = (const uint4*)(Qh + ch * 4096);
            const uint4* gql  = (const uint4*)(Ql + ch * 4096);
            for (int i = tid; i < 512; i += 256) {
                int r = i >> 4, qq = (i & 15) * 16;
                *(uint4*)(smraw + OS_TKH + r * SST + qq) = gtkh[i];
                *(uint4*)(smraw + OS_TKL + r * SST + qq) = gtkl[i];
                *(uint4*)(smraw + OS_QH + r * SST + qq) = gqh[i];
                *(uint4*)(smraw + OS_QL + r * SST + qq) = gql[i];
            }
            const uint4* gkth = (const uint4*)(KTh + ch * 4096);
            const uint4* gktl = (const uint4*)(KTl + ch * 4096);
            for (int i = tid; i < 512; i += 256) {
                int r = i >> 2, qq = (i & 3) * 16;
                *(uint4*)(smraw + OS_KTH + r * WST + qq) = gkth[i];
                *(uint4*)(smraw + OS_KTL + r * WST + qq) = gktl[i];
            }
            const uint4* gph = (const uint4*)(Ph + ch * 1024);
            const uint4* gpl = (const uint4*)(Pl + ch * 1024);
            if (tid < 128) {
                int r = tid >> 2, qq = (tid & 3) * 16;
                *(uint4*)(smraw + OS_PH + r * WST + qq) = gph[tid];
                *(uint4*)(smraw + OS_PL + r * WST + qq) = gpl[tid];
            }
            const uint4* gw0 = (const uint4*)(W0g + ch * 4096);
            for (int i = tid; i < 1024; i += 256)
                ((uint4*)(smraw + OS_W0))[i] = gw0[i];
            if (tid < 32) colsum[tid] = 0.f;
        }
        __syncthreads();

        // ---- step 1: Wt = W0^T - Ssm @ TK^T ----
        float acc[2][2][4];
#pragma unroll
        for (int mi = 0; mi < 2; mi++)
#pragma unroll
            for (int ni = 0; ni < 2; ni++)
#pragma unroll
                for (int e = 0; e < 4; e++) acc[mi][ni][e] = 0.f;
#pragma unroll
        for (int ks = 0; ks < 8; ks++) {
            uint32_t ah[2][4], al[2][4], bhf[2][2], blf[2][2];
#pragma unroll
            for (int mi = 0; mi < 2; mi++) {
                uint32_t off = (wm + mi * 16 + a_r) * SST + a_cB + ks * 32;
                LDSM_X4(ah[mi][0], ah[mi][1], ah[mi][2], ah[mi][3], sb + OS_SHI + off);
                LDSM_X4(al[mi][0], al[mi][1], al[mi][2], al[mi][3], sb + OS_SLO + off);
            }
#pragma unroll
            for (int ni = 0; ni < 2; ni++) {
                uint32_t off = (wn16 + ni * 8 + b_r) * SST + b_cB + ks * 32;
                LDSM_X2(bhf[ni][0], bhf[ni][1], sb + OS_TKH + off);
                LDSM_X2(blf[ni][0], blf[ni][1], sb + OS_TKL + off);
            }
#pragma unroll
            for (int mi = 0; mi < 2; mi++)
#pragma unroll
                for (int ni = 0; ni < 2; ni++) {
                    mma_bf16(acc[mi][ni], ah[mi], bhf[ni]);
                    mma_bf16(acc[mi][ni], ah[mi], blf[ni]);
                    mma_bf16(acc[mi][ni], al[mi], bhf[ni]);
                }
        }
#pragma unroll
        for (int mi = 0; mi < 2; mi++)
#pragma unroll
            for (int ni = 0; ni < 2; ni++)
#pragma unroll
                for (int pp = 0; pp < 2; pp++) {
                    int m = wm + mi * 16 + fr + pp * 8;
                    int n0 = wn16 + ni * 8 + fc;
                    float v0 = W0s[n0 * 128 + m] - acc[mi][ni][pp * 2 + 0];
                    float v1 = W0s[(n0 + 1) * 128 + m] - acc[mi][ni][pp * 2 + 1];
                    uint32_t lo, hi = pack_split(v0, v1, lo);
                    *(uint32_t*)(smraw + OS_WTH + m * WST + n0 * 2) = hi;
                    *(uint32_t*)(smraw + OS_WTL + m * WST + n0 * 2) = lo;
                }
        __syncthreads();

        // ---- step 2: Ot = Ssm @ Q^T + Wt @ P^T ----
        float oacc[2][2][4];
#pragma unroll
        for (int mi = 0; mi < 2; mi++)
#pragma unroll
            for (int ni = 0; ni < 2; ni++)
#pragma unroll
                for (int e = 0; e < 4; e++) oacc[mi][ni][e] = 0.f;
#pragma unroll
        for (int ks = 0; ks < 8; ks++) {
            uint32_t ah[2][4], al[2][4], bhf[2][2], blf[2][2];
#pragma unroll
            for (int mi = 0; mi < 2; mi++) {
                uint32_t off = (wm + mi * 16 + a_r) * SST + a_cB + ks * 32;
                LDSM_X4(ah[mi][0], ah[mi][1], ah[mi][2], ah[mi][3], sb + OS_SHI + off);
                LDSM_X4(al[mi][0], al[mi][1], al[mi][2], al[mi][3], sb + OS_SLO + off);
            }
#pragma unroll
            for (int ni = 0; ni < 2; ni++) {
                uint32_t off = (wn16 + ni * 8 + b_r) * SST + b_cB + ks * 32;
                LDSM_X2(bhf[ni][0], bhf[ni][1], sb + OS_QH + off);
                LDSM_X2(blf[ni][0], blf[ni][1], sb + OS_QL + off);
            }
#pragma unroll
            for (int mi = 0; mi < 2; mi++)
#pragma unroll
                for (int ni = 0; ni < 2; ni++) {
                    mma_bf16(oacc[mi][ni], ah[mi], bhf[ni]);
                    mma_bf16(oacc[mi][ni], ah[mi], blf[ni]);
                    mma_bf16(oacc[mi][ni], al[mi], bhf[ni]);
                }
        }
#pragma unroll
        for (int ks = 0; ks < 2; ks++) {
            uint32_t ah[2][4], al[2][4], bhf[2][2], blf[2][2];
#pragma unroll
            for (int mi = 0; mi < 2; mi++) {
                uint32_t off = (wm + mi * 16 + a_r) * WST + a_cB + ks * 32;
                LDSM_X4(ah[mi][0], ah[mi][1], ah[mi][2], ah[mi][3], sb + OS_WTH + off);
                LDSM_X4(al[mi][0], al[mi][1], al[mi][2], al[mi][3], sb + OS_WTL + off);
            }
#pragma unroll
            for (int ni = 0; ni < 2; ni++) {
                uint32_t off = (wn16 + ni * 8 + b_r) * WST + b_cB + ks * 32;
                LDSM_X2(bhf[ni][0], bhf[ni][1], sb + OS_PH + off);
                LDSM_X2(blf[ni][0], blf[ni][1], sb + OS_PL + off);
            }
#pragma unroll
            for (int mi = 0; mi < 2; mi++)
#pragma unroll
                for (int ni = 0; ni < 2; ni++) {
                    mma_bf16(oacc[mi][ni], ah[mi], bhf[ni]);
                    mma_bf16(oacc[mi][ni], ah[mi], blf[ni]);
                    mma_bf16(oacc[mi][ni], al[mi], bhf[ni]);
                }
        }
#pragma unroll
        for (int ni = 0; ni < 2; ni++) {
            float s0 = oacc[0][ni][0] * oacc[0][ni][0] + oacc[0][ni][2] * oacc[0][ni][2]
                     + oacc[1][ni][0] * oacc[1][ni][0] + oacc[1][ni][2] * oacc[1][ni][2];
            float s1 = oacc[0][ni][1] * oacc[0][ni][1] + oacc[0][ni][3] * oacc[0][ni][3]
                     + oacc[1][ni][1] * oacc[1][ni][1] + oacc[1][ni][3] * oacc[1][ni][3];
#pragma unroll
            for (int off = 4; off <= 16; off <<= 1) {
                s0 += __shfl_xor_sync(0xffffffffu, s0, off);
                s1 += __shfl_xor_sync(0xffffffffu, s1, off);
            }
            if (lane < 4) {
                atomicAdd(&colsum[wn16 + ni * 8 + 2 * lane], s0);
                atomicAdd(&colsum[wn16 + ni * 8 + 2 * lane + 1], s1);
            }
        }
        __syncthreads();

        {
            const size_t obase = (size_t)b * L_ * D_ + (size_t)h * DH_ + (size_t)(c * C_) * D_;
#pragma unroll
            for (int ni = 0; ni < 2; ni++) {
                int n0 = wn16 + ni * 8 + fc;
                float r0 = rsqrtf(colsum[n0] * (1.f / 128.f) + 1e-5f);
                float r1 = rsqrtf(colsum[n0 + 1] * (1.f / 128.f) + 1e-5f);
#pragma unroll
                for (int mi = 0; mi < 2; mi++)
#pragma unroll
                    for (int pp = 0; pp < 2; pp++) {
                        int m = wm + mi * 16 + fr + pp * 8;
                        o[obase + (size_t)n0 * D_ + m] = oacc[mi][ni][pp * 2] * r0 * wnr[mi][pp];
                        o[obase + (size_t)(n0 + 1) * D_ + m] = oacc[mi][ni][pp * 2 + 1] * r1 * wnr[mi][pp];
                    }
            }
        }

        // ---- step 3: Ssm += Wt @ K ----
#pragma unroll
        for (int ks = 0; ks < 2; ks++) {
            uint32_t ah[2][4], al[2][4];
#pragma unroll
            for (int mi = 0; mi < 2; mi++) {
                uint32_t off = (wm + mi * 16 + a_r) * WST + a_cB + ks * 32;
                LDSM_X4(ah[mi][0], ah[mi][1], ah[mi][2], ah[mi][3], sb + OS_WTH + off);
                LDSM_X4(al[mi][0], al[mi][1], al[mi][2], al[mi][3], sb + OS_WTL + off);
            }
#pragma unroll
            for (int ni = 0; ni < 8; ni++) {
                uint32_t bhf[2], blf[2];
                uint32_t off = (wn64 + ni * 8 + b_r) * WST + b_cB + ks * 32;
                LDSM_X2(bhf[0], bhf[1], sb + OS_KTH + off);
                LDSM_X2(blf[0], blf[1], sb + OS_KTL + off);
#pragma unroll
                for (int mi = 0; mi < 2; mi++) {
                    mma_bf16(Sfr[mi][ni], ah[mi], bhf);
                    mma_bf16(Sfr[mi][ni], ah[mi], blf);
                    mma_bf16(Sfr[mi][ni], al[mi], bhf);
                }
            }
        }
#pragma unroll
        for (int mi = 0; mi < 2; mi++)
#pragma unroll
            for (int ni = 0; ni < 8; ni++)
#pragma unroll
                for (int pp = 0; pp < 2; pp++) {
                    int m = wm + mi * 16 + fr + pp * 8;
                    int n0 = wn64 + ni * 8 + fc;
                    uint32_t lo, hi = pack_split(Sfr[mi][ni][pp * 2], Sfr[mi][ni][pp * 2 + 1], lo);
                    *(uint32_t*)(smraw + OS_SHI + m * SST + n0 * 2) = hi;
                    *(uint32_t*)(smraw + OS_SLO + m * SST + n0 * 2) = lo;
                }
    }
}

// ================= launch =================
extern "C" void kernel_launch(void* const* d_in, const int* in_sizes, int n_in,
                              void* d_out, int out_size) {
    const float* X  = (const float*)d_in[0];
    const float* Wq = (const float*)d_in[1];
    const float* Wk = (const float*)d_in[2];
    const float* Wv = (const float*)d_in[3];
    const float* Wb = (const float*)d_in[4];
    const float* wn = (const float*)d_in[5];
    const float* Wo = (const float*)d_in[6];
    float* out = (float*)d_out;

    float *gq, *gk, *gv, *go, *gb, *gW0;
    __nv_bfloat16 *ahi, *alo, *whi, *wlo;
    __nv_bfloat16 *tkh, *tkl, *qch, *qcl, *kth, *ktl, *ph, *pl;
    cudaGetSymbolAddress((void**)&gq, g_q);
    cudaGetSymbolAddress((void**)&gk, g_k);
    cudaGetSymbolAddress((void**)&gv, g_v);
    cudaGetSymbolAddress((void**)&go, g_o);
    cudaGetSymbolAddress((void**)&gb, g_beta);
    cudaGetSymbolAddress((void**)&ahi, g_Ahi);
    cudaGetSymbolAddress((void**)&alo, g_Alo);
    cudaGetSymbolAddress((void**)&whi, g_Whi);
    cudaGetSymbolAddress((void**)&wlo, g_Wlo);
    cudaGetSymbolAddress((void**)&gW0, g_W0);
    cudaGetSymbolAddress((void**)&tkh, g_TKh);
    cudaGetSymbolAddress((void**)&tkl, g_TKl);
    cudaGetSymbolAddress((void**)&qch, g_Qch);
    cudaGetSymbolAddress((void**)&qcl, g_Qcl);
    cudaGetSymbolAddress((void**)&kth, g_KTh);
    cudaGetSymbolAddress((void**)&ktl, g_KTl);
    cudaGetSymbolAddress((void**)&ph, g_Ph);
    cudaGetSymbolAddress((void**)&pl, g_Pl);

    cudaFuncSetAttribute(gemm_bf16split, cudaFuncAttributeMaxDynamicSharedMemorySize, SMEM_DYN);
    cudaFuncSetAttribute(pre_chunk, cudaFuncAttributeMaxDynamicSharedMemorySize, 69760);
    cudaFuncSetAttribute(seq_chunk, cudaFuncAttributeMaxDynamicSharedMemorySize, SEQ_SMEM);

    const int NSPLIT = M_ * D_ / 4 / 256;

    split_rows<<<NSPLIT, 256>>>((const float4*)X, (uint2*)ahi, (uint2*)alo);
    split_transpose<<<dim3(D_ / 32, D_ / 32, 4), dim3(32, 8)>>>(Wq, Wk, Wv, Wo, whi, wlo);

    GemmArgs qa;
    qa.Bhi[0] = whi;                       qa.Blo[0] = wlo;
    qa.Bhi[1] = whi + (size_t)D_ * D_;     qa.Blo[1] = wlo + (size_t)D_ * D_;
    qa.Bhi[2] = whi + (size_t)2 * D_ * D_; qa.Blo[2] = wlo + (size_t)2 * D_ * D_;
    qa.C[0] = gq; qa.C[1] = gk; qa.C[2] = gv;
    qa.mode[0] = 0; qa.mode[1] = 0; qa.mode[2] = 1;
    gemm_bf16split<<<dim3(D_ / BN, M_ / BM, 3), 256, SMEM_DYN>>>(ahi, alo, qa);

    beta_gemm<<<M_ / 16, 256>>>(X, Wb, gb);

    pre_chunk<<<NCH_, 128, 69760>>>(gq, gk, gv, gb, gW0, tkh, tkl, qch, qcl, kth, ktl, ph, pl);
    seq_chunk<<<B_ * H_, 256, SEQ_SMEM>>>(gW0, tkh, tkl, qch, qcl, kth, ktl, ph, pl, wn, go);

    split_rows<<<NSPLIT, 256>>>((const float4*)go, (uint2*)ahi, (uint2*)alo);
    GemmArgs oa;
    oa.Bhi[0] = whi + (size_t)3 * D_ * D_; oa.Blo[0] = wlo + (size_t)3 * D_ * D_;
    oa.Bhi[1] = oa.Bhi[0]; oa.Blo[1] = oa.Blo[0];
    oa.Bhi[2] = oa.Bhi[0]; oa.Blo[2] = oa.Blo[0];
    oa.C[0] = out; oa.C[1] = out; oa.C[2] = out;
    oa.mode[0] = 0; oa.mode[1] = 0; oa.mode[2] = 0;
    gemm_bf16split<<<dim3(D_ / BN, M_ / BM, 1), 256, SMEM_DYN>>>(ahi, alo, oa);
}

// round 6
// speedup vs baseline: 2.9466x; 1.2105x over previous
#include <cuda_runtime.h>
#include <cuda_bf16.h>
#include <cuda_fp16.h>
#include <math.h>
#include <stdint.h>

#define B_  2
#define L_  2048
#define D_  2048
#define H_  16
#define DH_ 128
#define M_  (B_ * L_)   // 4096
#define C_  32          // chunk length
#define NC_ (L_ / C_)   // 64 chunks per (b,h)
#define NCH_ (B_ * H_ * NC_)  // 2048 chunk-heads

// ================= scratch (device globals; no allocations) =================
__device__ float g_q[M_ * D_];
__device__ float g_k[M_ * D_];
__device__ float g_v[M_ * D_];
__device__ float g_o[M_ * D_];
__device__ float g_beta[M_ * H_];
__device__ __half g_Ahi[M_ * D_];        // fp16 hi/lo split of GEMM A operand
__device__ __half g_Alo[M_ * D_];
__device__ __half g_Wt[4 * D_ * D_];     // transposed weights [N,K] fp16, order q,k,v,o
// chunked delta-rule precompute (bf16 3-combo; unchanged)
__device__ float g_W0[NCH_ * C_ * DH_];
__device__ __nv_bfloat16 g_TKh[NCH_ * C_ * DH_];
__device__ __nv_bfloat16 g_TKl[NCH_ * C_ * DH_];
__device__ __nv_bfloat16 g_Qch[NCH_ * C_ * DH_];
__device__ __nv_bfloat16 g_Qcl[NCH_ * C_ * DH_];
__device__ __nv_bfloat16 g_KTh[NCH_ * DH_ * C_];
__device__ __nv_bfloat16 g_KTl[NCH_ * DH_ * C_];
__device__ __nv_bfloat16 g_Ph[NCH_ * C_ * C_];
__device__ __nv_bfloat16 g_Pl[NCH_ * C_ * C_];

// ================= helpers =================
__device__ __forceinline__ uint32_t smem_u32(const void* p) {
    uint32_t a;
    asm("{ .reg .u64 t; cvta.to.shared.u64 t, %1; cvt.u32.u64 %0, t; }" : "=r"(a) : "l"(p));
    return a;
}
__device__ __forceinline__ void cp16(uint32_t dst, const void* src) {
    asm volatile("cp.async.cg.shared.global [%0], [%1], 16;" :: "r"(dst), "l"(src));
}
#define CP_COMMIT() asm volatile("cp.async.commit_group;" ::: "memory")
#define CP_WAIT(n)  asm volatile("cp.async.wait_group %0;" :: "n"(n) : "memory")

#define LDSM_X4(r0, r1, r2, r3, addr)                                            \
    asm volatile("ldmatrix.sync.aligned.m8n8.x4.shared.b16 {%0,%1,%2,%3}, [%4];" \
        : "=r"(r0), "=r"(r1), "=r"(r2), "=r"(r3) : "r"(addr))
#define LDSM_X2(r0, r1, addr)                                                    \
    asm volatile("ldmatrix.sync.aligned.m8n8.x2.shared.b16 {%0,%1}, [%2];"       \
        : "=r"(r0), "=r"(r1) : "r"(addr))

__device__ __forceinline__ void mma_bf16(float* d, const uint32_t* a, const uint32_t* b) {
    asm volatile(
        "mma.sync.aligned.m16n8k16.row.col.f32.bf16.bf16.f32 "
        "{%0,%1,%2,%3}, {%4,%5,%6,%7}, {%8,%9}, {%0,%1,%2,%3};"
        : "+f"(d[0]), "+f"(d[1]), "+f"(d[2]), "+f"(d[3])
        : "r"(a[0]), "r"(a[1]), "r"(a[2]), "r"(a[3]), "r"(b[0]), "r"(b[1]));
}
__device__ __forceinline__ void mma_f16(float* d, const uint32_t* a, const uint32_t* b) {
    asm volatile(
        "mma.sync.aligned.m16n8k16.row.col.f32.f16.f16.f32 "
        "{%0,%1,%2,%3}, {%4,%5,%6,%7}, {%8,%9}, {%0,%1,%2,%3};"
        : "+f"(d[0]), "+f"(d[1]), "+f"(d[2]), "+f"(d[3])
        : "r"(a[0]), "r"(a[1]), "r"(a[2]), "r"(a[3]), "r"(b[0]), "r"(b[1]));
}
__device__ __forceinline__ uint32_t pack_split(float v0, float v1, uint32_t& lo) {
    __nv_bfloat16 h0 = __float2bfloat16(v0), h1 = __float2bfloat16(v1);
    __nv_bfloat16 l0 = __float2bfloat16(v0 - __bfloat162float(h0));
    __nv_bfloat16 l1 = __float2bfloat16(v1 - __bfloat162float(h1));
    lo = ((uint32_t)__bfloat16_as_ushort(l1) << 16) | __bfloat16_as_ushort(l0);
    return ((uint32_t)__bfloat16_as_ushort(h1) << 16) | __bfloat16_as_ushort(h0);
}

// ================= split fp32 -> fp16 hi/lo =================
__global__ void __launch_bounds__(256) split_rows(const float4* __restrict__ X,
                                                  uint2* __restrict__ hi,
                                                  uint2* __restrict__ lo) {
    int i = blockIdx.x * 256 + threadIdx.x;
    float4 x = X[i];
    __half h0 = __float2half_rn(x.x), h1 = __float2half_rn(x.y);
    __half h2 = __float2half_rn(x.z), h3 = __float2half_rn(x.w);
    __half l0 = __float2half_rn(x.x - __half2float(h0));
    __half l1 = __float2half_rn(x.y - __half2float(h1));
    __half l2 = __float2half_rn(x.z - __half2float(h2));
    __half l3 = __float2half_rn(x.w - __half2float(h3));
    uint2 hv, lv;
    hv.x = ((uint32_t)__half_as_ushort(h1) << 16) | __half_as_ushort(h0);
    hv.y = ((uint32_t)__half_as_ushort(h3) << 16) | __half_as_ushort(h2);
    lv.x = ((uint32_t)__half_as_ushort(l1) << 16) | __half_as_ushort(l0);
    lv.y = ((uint32_t)__half_as_ushort(l3) << 16) | __half_as_ushort(l2);
    hi[i] = hv;
    lo[i] = lv;
}

// transpose weights: W[k][n] fp32 -> Wt[n][k] fp16 (grid.z selects matrix)
__global__ void __launch_bounds__(256) split_transpose(
    const float* __restrict__ W0, const float* __restrict__ W1,
    const float* __restrict__ W2, const float* __restrict__ W3,
    __half* __restrict__ wt) {
    __shared__ float t[32][33];
    const float* W = (blockIdx.z == 0) ? W0 : (blockIdx.z == 1) ? W1
                   : (blockIdx.z == 2) ? W2 : W3;
    __half* ho = wt + (size_t)blockIdx.z * D_ * D_;
    const int n = blockIdx.x * 32 + threadIdx.x;
    const int k0 = blockIdx.y * 32;
#pragma unroll
    for (int i = threadIdx.y; i < 32; i += 8)
        t[i][threadIdx.x] = W[(size_t)(k0 + i) * D_ + n];
    __syncthreads();
#pragma unroll
    for (int i = threadIdx.y; i < 32; i += 8) {
        const int nn = blockIdx.x * 32 + i;
        ho[(size_t)nn * D_ + k0 + threadIdx.x] = __float2half_rn(t[threadIdx.x][i]);
    }
}

// ================= fp16 2-combo GEMM: Ah@B + Al@B, 4-stage, 1 sync/chunk =====
#define BM 128
#define BN 128
#define BK 32
#define LDS_ 40
#define TILE_B (128 * LDS_ * 2)       // 10240
#define STAGE_B (3 * TILE_B)          // Ah, Al, B = 30720
#define NSTAGE 4
#define SMEM_DYN (NSTAGE * STAGE_B)   // 122880
#define NCHUNK (D_ / BK)

struct GemmArgs {
    const __half* Bw[3];
    float* C[3];
    int mode[3];
};

__device__ __forceinline__ void load_chunk(uint32_t sbase, int stage,
    const __half* Ahi, const __half* Alo, const __half* Bw,
    int m0, int n0, int kc, int tid) {
    const int r  = tid >> 1;
    const int c0 = (tid & 1) * 2;
    const uint32_t st = sbase + stage * STAGE_B;
    const size_t koff = (size_t)kc * BK;
    const __half* srcs[3] = {
        Ahi + (size_t)(m0 + r) * D_ + koff,
        Alo + (size_t)(m0 + r) * D_ + koff,
        Bw  + (size_t)(n0 + r) * D_ + koff };
#pragma unroll
    for (int t = 0; t < 3; t++) {
        uint32_t rowb = st + t * TILE_B + r * (LDS_ * 2);
        cp16(rowb + (c0 + 0) * 16, srcs[t] + (c0 + 0) * 8);
        cp16(rowb + (c0 + 1) * 16, srcs[t] + (c0 + 1) * 8);
    }
    CP_COMMIT();
}

__global__ void __launch_bounds__(256, 1) gemm_f16split(
    const __half* __restrict__ Ahi, const __half* __restrict__ Alo,
    GemmArgs args) {
    extern __shared__ char smem_raw[];
    const int z = blockIdx.z;
    const __half* Bw = args.Bw[z];
    float* C = args.C[z];
    const int mode = args.mode[z];

    const int m0 = blockIdx.y * BM;
    const int n0 = blockIdx.x * BN;
    const int tid = threadIdx.x;
    const int wid = tid >> 5;
    const int lane = tid & 31;
    const int wm = (wid & 1) * 64;
    const int wn = (wid >> 1) * 32;
    const uint32_t sbase = smem_u32(smem_raw);

    const uint32_t a_row  = wm + (lane & 15);
    const uint32_t a_colb = ((lane >> 4) << 4);
    const uint32_t b_row  = wn + (lane & 7);
    const uint32_t b_colb = (((lane >> 3) & 1) << 4);

    float acc[4][4][4];
#pragma unroll
    for (int mi = 0; mi < 4; mi++)
#pragma unroll
        for (int ni = 0; ni < 4; ni++)
#pragma unroll
            for (int t = 0; t < 4; t++) acc[mi][ni][t] = 0.f;

    load_chunk(sbase, 0, Ahi, Alo, Bw, m0, n0, 0, tid);
    load_chunk(sbase, 1, Ahi, Alo, Bw, m0, n0, 1, tid);
    load_chunk(sbase, 2, Ahi, Alo, Bw, m0, n0, 2, tid);

    for (int c = 0; c < NCHUNK; c++) {
        CP_WAIT(2);
        __syncthreads();
        if (c + 3 < NCHUNK)
            load_chunk(sbase, (c + 3) & (NSTAGE - 1), Ahi, Alo, Bw, m0, n0, c + 3, tid);
        else
            CP_COMMIT();

        const uint32_t st  = sbase + (c & (NSTAGE - 1)) * STAGE_B;
        const uint32_t tAh = st;
        const uint32_t tAl = st + TILE_B;
        const uint32_t tB  = st + 2 * TILE_B;

#pragma unroll
        for (int ks = 0; ks < 2; ks++) {
            const uint32_t kb = ks * 32;
            uint32_t ah[4][4], al[4][4], bf[4][2];
#pragma unroll
            for (int mi = 0; mi < 4; mi++) {
                uint32_t off = (a_row + mi * 16) * (LDS_ * 2) + a_colb + kb;
                LDSM_X4(ah[mi][0], ah[mi][1], ah[mi][2], ah[mi][3], tAh + off);
                LDSM_X4(al[mi][0], al[mi][1], al[mi][2], al[mi][3], tAl + off);
            }
#pragma unroll
            for (int ni = 0; ni < 4; ni++) {
                uint32_t off = (b_row + ni * 8) * (LDS_ * 2) + b_colb + kb;
                LDSM_X2(bf[ni][0], bf[ni][1], tB + off);
            }
#pragma unroll
            for (int mi = 0; mi < 4; mi++)
#pragma unroll
                for (int ni = 0; ni < 4; ni++) {
                    mma_f16(acc[mi][ni], ah[mi], bf[ni]);
                    mma_f16(acc[mi][ni], al[mi], bf[ni]);
                }
        }
    }

    const int orow = m0 + wm + (lane >> 2);
    const int ocol = n0 + wn + 2 * (lane & 3);
#pragma unroll
    for (int mi = 0; mi < 4; mi++)
#pragma unroll
        for (int ni = 0; ni < 4; ni++) {
            float v0 = acc[mi][ni][0], v1 = acc[mi][ni][1];
            float v2 = acc[mi][ni][2], v3 = acc[mi][ni][3];
            if (mode == 1) {
                v0 = v0 / (1.f + expf(-v0));
                v1 = v1 / (1.f + expf(-v1));
                v2 = v2 / (1.f + expf(-v2));
                v3 = v3 / (1.f + expf(-v3));
            }
            float* p0 = C + (size_t)(orow + mi * 16) * D_ + ocol + ni * 8;
            float* p1 = C + (size_t)(orow + mi * 16 + 8) * D_ + ocol + ni * 8;
            *(float2*)p0 = make_float2(v0, v1);
            *(float2*)p1 = make_float2(v2, v3);
        }
}

// ================= beta projection: tiled GEMM [M,2048]@[2048,16] ==========
__global__ void __launch_bounds__(256) beta_gemm(const float* __restrict__ X,
                                                 const float* __restrict__ Wb,
                                                 float* __restrict__ beta) {
    __shared__ float Xs[16][132];
    __shared__ float Ws[128][16];
    const int m0 = blockIdx.x * 16;
    const int tid = threadIdx.x;
    const int row = tid >> 4, n = tid & 15;
    float acc = 0.f;
    for (int kt = 0; kt < D_; kt += 128) {
        for (int i = tid; i < 16 * 32; i += 256) {
            int r = i >> 5, c4 = (i & 31) * 4;
            *(float4*)&Xs[r][c4] = *(const float4*)(X + (size_t)(m0 + r) * D_ + kt + c4);
        }
        for (int i = tid; i < 128 * 4; i += 256) {
            int r = i >> 2, c4 = (i & 3) * 4;
            *(float4*)&Ws[r][c4] = *(const float4*)(Wb + (size_t)(kt + r) * H_ + c4);
        }
        __syncthreads();
#pragma unroll 16
        for (int k = 0; k < 128; k++) acc += Xs[row][k] * Ws[k][n];
        __syncthreads();
    }
    beta[(size_t)(m0 + row) * H_ + n] = 1.f / (1.f + expf(-acc));
}

// ================= PRE: l2norm fused + per-chunk WY precompute ==============
__global__ void __launch_bounds__(128) pre_chunk(
    const float* __restrict__ q, const float* __restrict__ k,
    const float* __restrict__ v, const float* __restrict__ beta,
    float* __restrict__ W0g,
    __nv_bfloat16* __restrict__ TKh, __nv_bfloat16* __restrict__ TKl,
    __nv_bfloat16* __restrict__ Qh,  __nv_bfloat16* __restrict__ Ql,
    __nv_bfloat16* __restrict__ KTh, __nv_bfloat16* __restrict__ KTl,
    __nv_bfloat16* __restrict__ Ph,  __nv_bfloat16* __restrict__ Pl) {
    extern __shared__ float sm[];
    float* Kc  = sm;               // [32][128]
    float* Qc  = Kc + 32 * 128;    // [32][128]
    float* X   = Qc + 32 * 128;    // [32][256]  [bV | bK]
    float* Asm = X + 32 * 256;     // [32][32]
    float* bsm = Asm + 32 * 32;    // [32]

    const int ch = blockIdx.x;
    const int c  = ch & (NC_ - 1);
    const int bh = ch >> 6;
    const int b  = bh >> 4;
    const int h  = bh & 15;
    const int t0 = c * C_;
    const int tid = threadIdx.x;
    const size_t base0 = (size_t)b * L_ * D_ + (size_t)h * DH_;

    if (tid < 32) bsm[tid] = beta[((size_t)b * L_ + t0 + tid) * H_ + h];
    for (int i = tid; i < 32 * 32; i += 128) {
        int r = i >> 5, c4 = (i & 31) * 4;
        const size_t g = base0 + (size_t)(t0 + r) * D_ + c4;
        *(float4*)(Kc + r * 128 + c4) = *(const float4*)(k + g);
        *(float4*)(Qc + r * 128 + c4) = *(const float4*)(q + g);
        *(float4*)(X + r * 256 + c4)  = *(const float4*)(v + g);
    }
    __syncthreads();

    {
        const int w = tid >> 5, lane = tid & 31;
#pragma unroll
        for (int r = w * 8; r < w * 8 + 8; r++) {
            float4 kv = *(float4*)(Kc + r * 128 + lane * 4);
            float4 qv = *(float4*)(Qc + r * 128 + lane * 4);
            float sk = kv.x * kv.x + kv.y * kv.y + kv.z * kv.z + kv.w * kv.w;
            float sq = qv.x * qv.x + qv.y * qv.y + qv.z * qv.z + qv.w * qv.w;
#pragma unroll
            for (int off = 16; off; off >>= 1) {
                sk += __shfl_xor_sync(0xffffffffu, sk, off);
                sq += __shfl_xor_sync(0xffffffffu, sq, off);
            }
            float ik = 1.0f / fmaxf(sqrtf(sk), 1e-12f);
            float iq = 0.08838834764831845f / fmaxf(sqrtf(sq), 1e-12f);
            kv.x *= ik; kv.y *= ik; kv.z *= ik; kv.w *= ik;
            qv.x *= iq; qv.y *= iq; qv.z *= iq; qv.w *= iq;
            *(float4*)(Kc + r * 128 + lane * 4) = kv;
            *(float4*)(Qc + r * 128 + lane * 4) = qv;
        }
    }
    __syncthreads();

    for (int i = tid; i < 32 * 32; i += 128) {
        int r = i >> 5, c4 = (i & 31) * 4;
        float bt = bsm[r];
        float4 kv = *(float4*)(Kc + r * 128 + c4);
        kv.x *= bt; kv.y *= bt; kv.z *= bt; kv.w *= bt;
        *(float4*)(X + r * 256 + 128 + c4) = kv;
        float4 vv = *(float4*)(X + r * 256 + c4);
        vv.x *= bt; vv.y *= bt; vv.z *= bt; vv.w *= bt;
        *(float4*)(X + r * 256 + c4) = vv;
    }

    const int i_ = tid >> 2, j0 = (tid & 3) * 8;
    float accA[8], accP[8];
#pragma unroll
    for (int e = 0; e < 8; e++) { accA[e] = 0.f; accP[e] = 0.f; }
    for (int d4 = 0; d4 < 128; d4 += 4) {
        float4 ki = *(const float4*)(Kc + i_ * 128 + d4);
        float4 qi = *(const float4*)(Qc + i_ * 128 + d4);
#pragma unroll
        for (int e = 0; e < 8; e++) {
            float4 kj = *(const float4*)(Kc + (j0 + e) * 128 + d4);
            accA[e] += ki.x * kj.x + ki.y * kj.y + ki.z * kj.z + ki.w * kj.w;
            accP[e] += qi.x * kj.x + qi.y * kj.y + qi.z * kj.z + qi.w * kj.w;
        }
    }
    const float bi = bsm[i_];
#pragma unroll
    for (int e = 0; e < 8; e++) {
        int j = j0 + e;
        Asm[i_ * 32 + j] = (j < i_) ? bi * accA[e] : 0.f;
        float pv = (j <= i_) ? accP[e] : 0.f;
        __nv_bfloat16 phv = __float2bfloat16(pv);
        Ph[(size_t)ch * 1024 + i_ * 32 + j] = phv;
        Pl[(size_t)ch * 1024 + i_ * 32 + j] = __float2bfloat16(pv - __bfloat162float(phv));
    }
    __syncthreads();

    for (int i = 1; i < 32; i++) {
        float f0 = 0.f, f1 = 0.f;
        for (int j = 0; j < i; j++) {
            float a = Asm[i * 32 + j];
            f0 += a * X[j * 256 + tid];
            f1 += a * X[j * 256 + 128 + tid];
        }
        X[i * 256 + tid]       -= f0;
        X[i * 256 + 128 + tid] -= f1;
        __syncthreads();
    }

    for (int i = tid; i < 32 * 128; i += 128) {
        int n = i >> 7, m = i & 127;
        W0g[(size_t)ch * 4096 + i] = X[n * 256 + m];
        float tkv = X[n * 256 + 128 + m];
        __nv_bfloat16 th_ = __float2bfloat16(tkv);
        TKh[(size_t)ch * 4096 + i] = th_;
        TKl[(size_t)ch * 4096 + i] = __float2bfloat16(tkv - __bfloat162float(th_));
        float qv = Qc[n * 128 + m];
        __nv_bfloat16 qh_ = __float2bfloat16(qv);
        Qh[(size_t)ch * 4096 + i] = qh_;
        Ql[(size_t)ch * 4096 + i] = __float2bfloat16(qv - __bfloat162float(qh_));
    }
#pragma unroll
    for (int n = 0; n < 32; n++) {
        float kv = Kc[n * 128 + tid];
        __nv_bfloat16 kh_ = __float2bfloat16(kv);
        KTh[(size_t)ch * 4096 + tid * 32 + n] = kh_;
        KTl[(size_t)ch * 4096 + tid * 32 + n] = __float2bfloat16(kv - __bfloat162float(kh_));
    }
}

// ================= SEQ: sequential chunk chain, MMA-based ===================
#define OS_SHI 0
#define OS_SLO 34816
#define OS_WTH 69632
#define OS_WTL 79872
#define OS_TKH 90112
#define OS_TKL 98816
#define OS_QH  107520
#define OS_QL  116224
#define OS_KTH 124928
#define OS_KTL 135168
#define OS_PH  145408
#define OS_PL  147968
#define OS_W0  150528
#define OS_CS  166912
#define SEQ_SMEM 167040
#define SST 272
#define WST 80

__global__ void __launch_bounds__(256, 1) seq_chunk(
    const float* __restrict__ W0g,
    const __nv_bfloat16* __restrict__ TKh, const __nv_bfloat16* __restrict__ TKl,
    const __nv_bfloat16* __restrict__ Qh,  const __nv_bfloat16* __restrict__ Ql,
    const __nv_bfloat16* __restrict__ KTh, const __nv_bfloat16* __restrict__ KTl,
    const __nv_bfloat16* __restrict__ Ph,  const __nv_bfloat16* __restrict__ Pl,
    const float* __restrict__ wnorm, float* __restrict__ o) {
    extern __shared__ char smraw[];
    const int bh = blockIdx.x;
    const int b = bh >> 4, h = bh & 15;
    const int tid = threadIdx.x, wid = tid >> 5, lane = tid & 31;
    const uint32_t sb = smem_u32(smraw);
    float* W0s = (float*)(smraw + OS_W0);
    float* colsum = (float*)(smraw + OS_CS);

    for (int i = tid; i < (OS_WTH) / 16; i += 256)
        ((uint4*)smraw)[i] = make_uint4(0, 0, 0, 0);

    float Sfr[2][8][4];
#pragma unroll
    for (int mi = 0; mi < 2; mi++)
#pragma unroll
        for (int ni = 0; ni < 8; ni++)
#pragma unroll
            for (int e = 0; e < 4; e++) Sfr[mi][ni][e] = 0.f;

    const int wm = (wid & 3) * 32;
    const int wn16 = (wid >> 2) * 16;
    const int wn64 = (wid >> 2) * 64;
    const int a_r = lane & 15, a_cB = (lane >> 4) << 4;
    const int b_r = lane & 7,  b_cB = ((lane >> 3) & 1) << 4;
    const int fr = lane >> 2, fc = (lane & 3) * 2;

    float wnr[2][2];
#pragma unroll
    for (int mi = 0; mi < 2; mi++)
#pragma unroll
        for (int pp = 0; pp < 2; pp++)
            wnr[mi][pp] = wnorm[wm + mi * 16 + pp * 8 + fr];

    for (int c = 0; c < NC_; c++) {
        const size_t ch = (size_t)bh * NC_ + c;
        __syncthreads();

        {
            const uint4* gtkh = (const uint4*)(TKh + ch * 4096);
            const uint4* gtkl = (const uint4*)(TKl + ch * 4096);
            const uint4* gqh  = (const uint4*)(Qh + ch * 4096);
            const uint4* gql  = (const uint4*)(Ql + ch * 4096);
            for (int i = tid; i < 512; i += 256) {
                int r = i >> 4, qq = (i & 15) * 16;
                *(uint4*)(smraw + OS_TKH + r * SST + qq) = gtkh[i];
                *(uint4*)(smraw + OS_TKL + r * SST + qq) = gtkl[i];
                *(uint4*)(smraw + OS_QH + r * SST + qq) = gqh[i];
                *(uint4*)(smraw + OS_QL + r * SST + qq) = gql[i];
            }
            const uint4* gkth = (const uint4*)(KTh + ch * 4096);
            const uint4* gktl = (const uint4*)(KTl + ch * 4096);
            for (int i = tid; i < 512; i += 256) {
                int r = i >> 2, qq = (i & 3) * 16;
                *(uint4*)(smraw + OS_KTH + r * WST + qq) = gkth[i];
                *(uint4*)(smraw + OS_KTL + r * WST + qq) = gktl[i];
            }
            const uint4* gph = (const uint4*)(Ph + ch * 1024);
            const uint4* gpl = (const uint4*)(Pl + ch * 1024);
            if (tid < 128) {
                int r = tid >> 2, qq = (tid & 3) * 16;
                *(uint4*)(smraw + OS_PH + r * WST + qq) = gph[tid];
                *(uint4*)(smraw + OS_PL + r * WST + qq) = gpl[tid];
            }
            const uint4* gw0 = (const uint4*)(W0g + ch * 4096);
            for (int i = tid; i < 1024; i += 256)
                ((uint4*)(smraw + OS_W0))[i] = gw0[i];
            if (tid < 32) colsum[tid] = 0.f;
        }
        __syncthreads();

        // step 1: Wt = W0^T - Ssm @ TK^T
        float acc[2][2][4];
#pragma unroll
        for (int mi = 0; mi < 2; mi++)
#pragma unroll
            for (int ni = 0; ni < 2; ni++)
#pragma unroll
                for (int e = 0; e < 4; e++) acc[mi][ni][e] = 0.f;
#pragma unroll
        for (int ks = 0; ks < 8; ks++) {
            uint32_t ah[2][4], al[2][4], bhf[2][2], blf[2][2];
#pragma unroll
            for (int mi = 0; mi < 2; mi++) {
                uint32_t off = (wm + mi * 16 + a_r) * SST + a_cB + ks * 32;
                LDSM_X4(ah[mi][0], ah[mi][1], ah[mi][2], ah[mi][3], sb + OS_SHI + off);
                LDSM_X4(al[mi][0], al[mi][1], al[mi][2], al[mi][3], sb + OS_SLO + off);
            }
#pragma unroll
            for (int ni = 0; ni < 2; ni++) {
                uint32_t off = (wn16 + ni * 8 + b_r) * SST + b_cB + ks * 32;
                LDSM_X2(bhf[ni][0], bhf[ni][1], sb + OS_TKH + off);
                LDSM_X2(blf[ni][0], blf[ni][1], sb + OS_TKL + off);
            }
#pragma unroll
            for (int mi = 0; mi < 2; mi++)
#pragma unroll
                for (int ni = 0; ni < 2; ni++) {
                    mma_bf16(acc[mi][ni], ah[mi], bhf[ni]);
                    mma_bf16(acc[mi][ni], ah[mi], blf[ni]);
                    mma_bf16(acc[mi][ni], al[mi], bhf[ni]);
                }
        }
#pragma unroll
        for (int mi = 0; mi < 2; mi++)
#pragma unroll
            for (int ni = 0; ni < 2; ni++)
#pragma unroll
                for (int pp = 0; pp < 2; pp++) {
                    int m = wm + mi * 16 + fr + pp * 8;
                    int n0 = wn16 + ni * 8 + fc;
                    float v0 = W0s[n0 * 128 + m] - acc[mi][ni][pp * 2 + 0];
                    float v1 = W0s[(n0 + 1) * 128 + m] - acc[mi][ni][pp * 2 + 1];
                    uint32_t lo, hi = pack_split(v0, v1, lo);
                    *(uint32_t*)(smraw + OS_WTH + m * WST + n0 * 2) = hi;
                    *(uint32_t*)(smraw + OS_WTL + m * WST + n0 * 2) = lo;
                }
        __syncthreads();

        // step 2: Ot = Ssm @ Q^T + Wt @ P^T
        float oacc[2][2][4];
#pragma unroll
        for (int mi = 0; mi < 2; mi++)
#pragma unroll
            for (int ni = 0; ni < 2; ni++)
#pragma unroll
                for (int e = 0; e < 4; e++) oacc[mi][ni][e] = 0.f;
#pragma unroll
        for (int ks = 0; ks < 8; ks++) {
            uint32_t ah[2][4], al[2][4], bhf[2][2], blf[2][2];
#pragma unroll
            for (int mi = 0; mi < 2; mi++) {
                uint32_t off = (wm + mi * 16 + a_r) * SST + a_cB + ks * 32;
                LDSM_X4(ah[mi][0], ah[mi][1], ah[mi][2], ah[mi][3], sb + OS_SHI + off);
                LDSM_X4(al[mi][0], al[mi][1], al[mi][2], al[mi][3], sb + OS_SLO + off);
            }
#pragma unroll
            for (int ni = 0; ni < 2; ni++) {
                uint32_t off = (wn16 + ni * 8 + b_r) * SST + b_cB + ks * 32;
                LDSM_X2(bhf[ni][0], bhf[ni][1], sb + OS_QH + off);
                LDSM_X2(blf[ni][0], blf[ni][1], sb + OS_QL + off);
            }
#pragma unroll
            for (int mi = 0; mi < 2; mi++)
#pragma unroll
                for (int ni = 0; ni < 2; ni++) {
                    mma_bf16(oacc[mi][ni], ah[mi], bhf[ni]);
                    mma_bf16(oacc[mi][ni], ah[mi], blf[ni]);
                    mma_bf16(oacc[mi][ni], al[mi], bhf[ni]);
                }
        }
#pragma unroll
        for (int ks = 0; ks < 2; ks++) {
            uint32_t ah[2][4], al[2][4], bhf[2][2], blf[2][2];
#pragma unroll
            for (int mi = 0; mi < 2; mi++) {
                uint32_t off = (wm + mi * 16 + a_r) * WST + a_cB + ks * 32;
                LDSM_X4(ah[mi][0], ah[mi][1], ah[mi][2], ah[mi][3], sb + OS_WTH + off);
                LDSM_X4(al[mi][0], al[mi][1], al[mi][2], al[mi][3], sb + OS_WTL + off);
            }
#pragma unroll
            for (int ni = 0; ni < 2; ni++) {
                uint32_t off = (wn16 + ni * 8 + b_r) * WST + b_cB + ks * 32;
                LDSM_X2(bhf[ni][0], bhf[ni][1], sb + OS_PH + off);
                LDSM_X2(blf[ni][0], blf[ni][1], sb + OS_PL + off);
            }
#pragma unroll
            for (int mi = 0; mi < 2; mi++)
#pragma unroll
                for (int ni = 0; ni < 2; ni++) {
                    mma_bf16(oacc[mi][ni], ah[mi], bhf[ni]);
                    mma_bf16(oacc[mi][ni], ah[mi], blf[ni]);
                    mma_bf16(oacc[mi][ni], al[mi], bhf[ni]);
                }
        }
#pragma unroll
        for (int ni = 0; ni < 2; ni++) {
            float s0 = oacc[0][ni][0] * oacc[0][ni][0] + oacc[0][ni][2] * oacc[0][ni][2]
                     + oacc[1][ni][0] * oacc[1][ni][0] + oacc[1][ni][2] * oacc[1][ni][2];
            float s1 = oacc[0][ni][1] * oacc[0][ni][1] + oacc[0][ni][3] * oacc[0][ni][3]
                     + oacc[1][ni][1] * oacc[1][ni][1] + oacc[1][ni][3] * oacc[1][ni][3];
#pragma unroll
            for (int off = 4; off <= 16; off <<= 1) {
                s0 += __shfl_xor_sync(0xffffffffu, s0, off);
                s1 += __shfl_xor_sync(0xffffffffu, s1, off);
            }
            if (lane < 4) {
                atomicAdd(&colsum[wn16 + ni * 8 + 2 * lane], s0);
                atomicAdd(&colsum[wn16 + ni * 8 + 2 * lane + 1], s1);
            }
        }
        __syncthreads();

        {
            const size_t obase = (size_t)b * L_ * D_ + (size_t)h * DH_ + (size_t)(c * C_) * D_;
#pragma unroll
            for (int ni = 0; ni < 2; ni++) {
                int n0 = wn16 + ni * 8 + fc;
                float r0 = rsqrtf(colsum[n0] * (1.f / 128.f) + 1e-5f);
                float r1 = rsqrtf(colsum[n0 + 1] * (1.f / 128.f) + 1e-5f);
#pragma unroll
                for (int mi = 0; mi < 2; mi++)
#pragma unroll
                    for (int pp = 0; pp < 2; pp++) {
                        int m = wm + mi * 16 + fr + pp * 8;
                        o[obase + (size_t)n0 * D_ + m] = oacc[mi][ni][pp * 2] * r0 * wnr[mi][pp];
                        o[obase + (size_t)(n0 + 1) * D_ + m] = oacc[mi][ni][pp * 2 + 1] * r1 * wnr[mi][pp];
                    }
            }
        }

        // step 3: Ssm += Wt @ K
#pragma unroll
        for (int ks = 0; ks < 2; ks++) {
            uint32_t ah[2][4], al[2][4];
#pragma unroll
            for (int mi = 0; mi < 2; mi++) {
                uint32_t off = (wm + mi * 16 + a_r) * WST + a_cB + ks * 32;
                LDSM_X4(ah[mi][0], ah[mi][1], ah[mi][2], ah[mi][3], sb + OS_WTH + off);
                LDSM_X4(al[mi][0], al[mi][1], al[mi][2], al[mi][3], sb + OS_WTL + off);
            }
#pragma unroll
            for (int ni = 0; ni < 8; ni++) {
                uint32_t bhf[2], blf[2];
                uint32_t off = (wn64 + ni * 8 + b_r) * WST + b_cB + ks * 32;
                LDSM_X2(bhf[0], bhf[1], sb + OS_KTH + off);
                LDSM_X2(blf[0], blf[1], sb + OS_KTL + off);
#pragma unroll
                for (int mi = 0; mi < 2; mi++) {
                    mma_bf16(Sfr[mi][ni], ah[mi], bhf);
                    mma_bf16(Sfr[mi][ni], ah[mi], blf);
                    mma_bf16(Sfr[mi][ni], al[mi], bhf);
                }
            }
        }
#pragma unroll
        for (int mi = 0; mi < 2; mi++)
#pragma unroll
            for (int ni = 0; ni < 8; ni++)
#pragma unroll
                for (int pp = 0; pp < 2; pp++) {
                    int m = wm + mi * 16 + fr + pp * 8;
                    int n0 = wn64 + ni * 8 + fc;
                    uint32_t lo, hi = pack_split(Sfr[mi][ni][pp * 2], Sfr[mi][ni][pp * 2 + 1], lo);
                    *(uint32_t*)(smraw + OS_SHI + m * SST + n0 * 2) = hi;
                    *(uint32_t*)(smraw + OS_SLO + m * SST + n0 * 2) = lo;
                }
    }
}

// ================= launch =================
extern "C" void kernel_launch(void* const* d_in, const int* in_sizes, int n_in,
                              void* d_out, int out_size) {
    const float* X  = (const float*)d_in[0];
    const float* Wq = (const float*)d_in[1];
    const float* Wk = (const float*)d_in[2];
    const float* Wv = (const float*)d_in[3];
    const float* Wb = (const float*)d_in[4];
    const float* wn = (const float*)d_in[5];
    const float* Wo = (const float*)d_in[6];
    float* out = (float*)d_out;

    float *gq, *gk, *gv, *go, *gb, *gW0;
    __half *ahi, *alo, *wt;
    __nv_bfloat16 *tkh, *tkl, *qch, *qcl, *kth, *ktl, *ph, *pl;
    cudaGetSymbolAddress((void**)&gq, g_q);
    cudaGetSymbolAddress((void**)&gk, g_k);
    cudaGetSymbolAddress((void**)&gv, g_v);
    cudaGetSymbolAddress((void**)&go, g_o);
    cudaGetSymbolAddress((void**)&gb, g_beta);
    cudaGetSymbolAddress((void**)&ahi, g_Ahi);
    cudaGetSymbolAddress((void**)&alo, g_Alo);
    cudaGetSymbolAddress((void**)&wt, g_Wt);
    cudaGetSymbolAddress((void**)&gW0, g_W0);
    cudaGetSymbolAddress((void**)&tkh, g_TKh);
    cudaGetSymbolAddress((void**)&tkl, g_TKl);
    cudaGetSymbolAddress((void**)&qch, g_Qch);
    cudaGetSymbolAddress((void**)&qcl, g_Qcl);
    cudaGetSymbolAddress((void**)&kth, g_KTh);
    cudaGetSymbolAddress((void**)&ktl, g_KTl);
    cudaGetSymbolAddress((void**)&ph, g_Ph);
    cudaGetSymbolAddress((void**)&pl, g_Pl);

    cudaFuncSetAttribute(gemm_f16split, cudaFuncAttributeMaxDynamicSharedMemorySize, SMEM_DYN);
    cudaFuncSetAttribute(pre_chunk, cudaFuncAttributeMaxDynamicSharedMemorySize, 69760);
    cudaFuncSetAttribute(seq_chunk, cudaFuncAttributeMaxDynamicSharedMemorySize, SEQ_SMEM);

    const int NSPLIT = M_ * D_ / 4 / 256;

    split_rows<<<NSPLIT, 256>>>((const float4*)X, (uint2*)ahi, (uint2*)alo);
    split_transpose<<<dim3(D_ / 32, D_ / 32, 4), dim3(32, 8)>>>(Wq, Wk, Wv, Wo, wt);

    GemmArgs qa;
    qa.Bw[0] = wt;
    qa.Bw[1] = wt + (size_t)D_ * D_;
    qa.Bw[2] = wt + (size_t)2 * D_ * D_;
    qa.C[0] = gq; qa.C[1] = gk; qa.C[2] = gv;
    qa.mode[0] = 0; qa.mode[1] = 0; qa.mode[2] = 1;
    gemm_f16split<<<dim3(D_ / BN, M_ / BM, 3), 256, SMEM_DYN>>>(ahi, alo, qa);

    beta_gemm<<<M_ / 16, 256>>>(X, Wb, gb);

    pre_chunk<<<NCH_, 128, 69760>>>(gq, gk, gv, gb, gW0, tkh, tkl, qch, qcl, kth, ktl, ph, pl);
    seq_chunk<<<B_ * H_, 256, SEQ_SMEM>>>(gW0, tkh, tkl, qch, qcl, kth, ktl, ph, pl, wn, go);

    split_rows<<<NSPLIT, 256>>>((const float4*)go, (uint2*)ahi, (uint2*)alo);
    GemmArgs oa;
    oa.Bw[0] = wt + (size_t)3 * D_ * D_;
    oa.Bw[1] = oa.Bw[0];
    oa.Bw[2] = oa.Bw[0];
    oa.C[0] = out; oa.C[1] = out; oa.C[2] = out;
    oa.mode[0] = 0; oa.mode[1] = 0; oa.mode[2] = 0;
    gemm_f16split<<<dim3(D_ / BN, M_ / BM, 1), 256, SMEM_DYN>>>(ahi, alo, oa);
}

// round 7
// speedup vs baseline: 3.1589x; 1.0721x over previous
#include <cuda_runtime.h>
#include <cuda_bf16.h>
#include <cuda_fp16.h>
#include <math.h>
#include <stdint.h>

#define B_  2
#define L_  2048
#define D_  2048
#define H_  16
#define DH_ 128
#define M_  (B_ * L_)   // 4096
#define C_  32          // chunk length
#define NC_ (L_ / C_)   // 64 chunks per (b,h)
#define NCH_ (B_ * H_ * NC_)  // 2048 chunk-heads

// ================= scratch (device globals; no allocations) =================
__device__ float g_q[M_ * D_];
__device__ float g_k[M_ * D_];
__device__ float g_v[M_ * D_];
__device__ float g_o[M_ * D_];
__device__ float g_beta[M_ * H_];
__device__ __half g_Ahi[M_ * D_];        // fp16 hi/lo split of GEMM A operand
__device__ __half g_Alo[M_ * D_];
__device__ __half g_Wt[4 * D_ * D_];     // transposed weights [N,K] fp16, order q,k,v,o
// chunked delta-rule precompute (bf16 3-combo)
__device__ float g_W0[NCH_ * C_ * DH_];
__device__ __nv_bfloat16 g_TKh[NCH_ * C_ * DH_];
__device__ __nv_bfloat16 g_TKl[NCH_ * C_ * DH_];
__device__ __nv_bfloat16 g_Qch[NCH_ * C_ * DH_];
__device__ __nv_bfloat16 g_Qcl[NCH_ * C_ * DH_];
__device__ __nv_bfloat16 g_KTh[NCH_ * DH_ * C_];
__device__ __nv_bfloat16 g_KTl[NCH_ * DH_ * C_];
__device__ __nv_bfloat16 g_Ph[NCH_ * C_ * C_];
__device__ __nv_bfloat16 g_Pl[NCH_ * C_ * C_];

// ================= helpers =================
__device__ __forceinline__ uint32_t smem_u32(const void* p) {
    uint32_t a;
    asm("{ .reg .u64 t; cvta.to.shared.u64 t, %1; cvt.u32.u64 %0, t; }" : "=r"(a) : "l"(p));
    return a;
}
__device__ __forceinline__ void cp16(uint32_t dst, const void* src) {
    asm volatile("cp.async.cg.shared.global [%0], [%1], 16;" :: "r"(dst), "l"(src));
}
#define CP_COMMIT() asm volatile("cp.async.commit_group;" ::: "memory")
#define CP_WAIT(n)  asm volatile("cp.async.wait_group %0;" :: "n"(n) : "memory")

#define LDSM_X4(r0, r1, r2, r3, addr)                                            \
    asm volatile("ldmatrix.sync.aligned.m8n8.x4.shared.b16 {%0,%1,%2,%3}, [%4];" \
        : "=r"(r0), "=r"(r1), "=r"(r2), "=r"(r3) : "r"(addr))
#define LDSM_X2(r0, r1, addr)                                                    \
    asm volatile("ldmatrix.sync.aligned.m8n8.x2.shared.b16 {%0,%1}, [%2];"       \
        : "=r"(r0), "=r"(r1) : "r"(addr))

__device__ __forceinline__ void mma_bf16(float* d, const uint32_t* a, const uint32_t* b) {
    asm volatile(
        "mma.sync.aligned.m16n8k16.row.col.f32.bf16.bf16.f32 "
        "{%0,%1,%2,%3}, {%4,%5,%6,%7}, {%8,%9}, {%0,%1,%2,%3};"
        : "+f"(d[0]), "+f"(d[1]), "+f"(d[2]), "+f"(d[3])
        : "r"(a[0]), "r"(a[1]), "r"(a[2]), "r"(a[3]), "r"(b[0]), "r"(b[1]));
}
__device__ __forceinline__ void mma_f16(float* d, const uint32_t* a, const uint32_t* b) {
    asm volatile(
        "mma.sync.aligned.m16n8k16.row.col.f32.f16.f16.f32 "
        "{%0,%1,%2,%3}, {%4,%5,%6,%7}, {%8,%9}, {%0,%1,%2,%3};"
        : "+f"(d[0]), "+f"(d[1]), "+f"(d[2]), "+f"(d[3])
        : "r"(a[0]), "r"(a[1]), "r"(a[2]), "r"(a[3]), "r"(b[0]), "r"(b[1]));
}
__device__ __forceinline__ uint32_t pack_split(float v0, float v1, uint32_t& lo) {
    __nv_bfloat16 h0 = __float2bfloat16(v0), h1 = __float2bfloat16(v1);
    __nv_bfloat16 l0 = __float2bfloat16(v0 - __bfloat162float(h0));
    __nv_bfloat16 l1 = __float2bfloat16(v1 - __bfloat162float(h1));
    lo = ((uint32_t)__bfloat16_as_ushort(l1) << 16) | __bfloat16_as_ushort(l0);
    return ((uint32_t)__bfloat16_as_ushort(h1) << 16) | __bfloat16_as_ushort(h0);
}

// ================= split fp32 -> fp16 hi/lo =================
__global__ void __launch_bounds__(256) split_rows(const float4* __restrict__ X,
                                                  uint2* __restrict__ hi,
                                                  uint2* __restrict__ lo) {
    int i = blockIdx.x * 256 + threadIdx.x;
    float4 x = X[i];
    __half h0 = __float2half_rn(x.x), h1 = __float2half_rn(x.y);
    __half h2 = __float2half_rn(x.z), h3 = __float2half_rn(x.w);
    __half l0 = __float2half_rn(x.x - __half2float(h0));
    __half l1 = __float2half_rn(x.y - __half2float(h1));
    __half l2 = __float2half_rn(x.z - __half2float(h2));
    __half l3 = __float2half_rn(x.w - __half2float(h3));
    uint2 hv, lv;
    hv.x = ((uint32_t)__half_as_ushort(h1) << 16) | __half_as_ushort(h0);
    hv.y = ((uint32_t)__half_as_ushort(h3) << 16) | __half_as_ushort(h2);
    lv.x = ((uint32_t)__half_as_ushort(l1) << 16) | __half_as_ushort(l0);
    lv.y = ((uint32_t)__half_as_ushort(l3) << 16) | __half_as_ushort(l2);
    hi[i] = hv;
    lo[i] = lv;
}

// transpose weights: W[k][n] fp32 -> Wt[n][k] fp16 (grid.z selects matrix)
__global__ void __launch_bounds__(256) split_transpose(
    const float* __restrict__ W0, const float* __restrict__ W1,
    const float* __restrict__ W2, const float* __restrict__ W3,
    __half* __restrict__ wt) {
    __shared__ float t[32][33];
    const float* W = (blockIdx.z == 0) ? W0 : (blockIdx.z == 1) ? W1
                   : (blockIdx.z == 2) ? W2 : W3;
    __half* ho = wt + (size_t)blockIdx.z * D_ * D_;
    const int n = blockIdx.x * 32 + threadIdx.x;
    const int k0 = blockIdx.y * 32;
#pragma unroll
    for (int i = threadIdx.y; i < 32; i += 8)
        t[i][threadIdx.x] = W[(size_t)(k0 + i) * D_ + n];
    __syncthreads();
#pragma unroll
    for (int i = threadIdx.y; i < 32; i += 8) {
        const int nn = blockIdx.x * 32 + i;
        ho[(size_t)nn * D_ + k0 + threadIdx.x] = __float2half_rn(t[threadIdx.x][i]);
    }
}

// ====== fp16 2-combo GEMM: 3-stage, 2 CTAs/SM, hi/lo sweeps separated =======
#define BM 128
#define BN 128
#define BK 32
#define LDS_ 40
#define TILE_B (128 * LDS_ * 2)       // 10240
#define STAGE_B (3 * TILE_B)          // Ah, Al, B = 30720
#define NSTAGE 3
#define SMEM_DYN (NSTAGE * STAGE_B)   // 92160
#define NCHUNK (D_ / BK)

struct GemmArgs {
    const __half* Bw[3];
    float* C[3];
    int mode[3];
};

__device__ __forceinline__ void load_chunk(uint32_t sbase, int stage,
    const __half* Ahi, const __half* Alo, const __half* Bw,
    int m0, int n0, int kc, int tid) {
    const int r  = tid >> 1;
    const int c0 = (tid & 1) * 2;
    const uint32_t st = sbase + stage * STAGE_B;
    const size_t koff = (size_t)kc * BK;
    const __half* srcs[3] = {
        Ahi + (size_t)(m0 + r) * D_ + koff,
        Alo + (size_t)(m0 + r) * D_ + koff,
        Bw  + (size_t)(n0 + r) * D_ + koff };
#pragma unroll
    for (int t = 0; t < 3; t++) {
        uint32_t rowb = st + t * TILE_B + r * (LDS_ * 2);
        cp16(rowb + (c0 + 0) * 16, srcs[t] + (c0 + 0) * 8);
        cp16(rowb + (c0 + 1) * 16, srcs[t] + (c0 + 1) * 8);
    }
    CP_COMMIT();
}

__global__ void __launch_bounds__(256, 2) gemm_f16split(
    const __half* __restrict__ Ahi, const __half* __restrict__ Alo,
    GemmArgs args) {
    extern __shared__ char smem_raw[];
    const int z = blockIdx.z;
    const __half* Bw = args.Bw[z];
    float* C = args.C[z];
    const int mode = args.mode[z];

    const int m0 = blockIdx.y * BM;
    const int n0 = blockIdx.x * BN;
    const int tid = threadIdx.x;
    const int wid = tid >> 5;
    const int lane = tid & 31;
    const int wm = (wid & 1) * 64;
    const int wn = (wid >> 1) * 32;
    const uint32_t sbase = smem_u32(smem_raw);

    const uint32_t a_row  = wm + (lane & 15);
    const uint32_t a_colb = ((lane >> 4) << 4);
    const uint32_t b_row  = wn + (lane & 7);
    const uint32_t b_colb = (((lane >> 3) & 1) << 4);

    float acc[4][4][4];
#pragma unroll
    for (int mi = 0; mi < 4; mi++)
#pragma unroll
        for (int ni = 0; ni < 4; ni++)
#pragma unroll
            for (int t = 0; t < 4; t++) acc[mi][ni][t] = 0.f;

    // prologue: 2 chunks in flight
    load_chunk(sbase, 0, Ahi, Alo, Bw, m0, n0, 0, tid);
    load_chunk(sbase, 1, Ahi, Alo, Bw, m0, n0, 1, tid);

    for (int c = 0; c < NCHUNK; c++) {
        CP_WAIT(1);          // chunk c resident
        __syncthreads();
        if (c + 2 < NCHUNK) {
            int s = (c + 2) % NSTAGE;
            load_chunk(sbase, s, Ahi, Alo, Bw, m0, n0, c + 2, tid);
        } else {
            CP_COMMIT();     // keep group-count invariant
        }

        const uint32_t st  = sbase + (c % NSTAGE) * STAGE_B;
        const uint32_t tAh = st;
        const uint32_t tAl = st + TILE_B;
        const uint32_t tB  = st + 2 * TILE_B;

#pragma unroll
        for (int ks = 0; ks < 2; ks++) {
            const uint32_t kb = ks * 32;
            uint32_t ah[4][4], al[4][4], bf[4][2];
#pragma unroll
            for (int mi = 0; mi < 4; mi++) {
                uint32_t off = (a_row + mi * 16) * (LDS_ * 2) + a_colb + kb;
                LDSM_X4(ah[mi][0], ah[mi][1], ah[mi][2], ah[mi][3], tAh + off);
                LDSM_X4(al[mi][0], al[mi][1], al[mi][2], al[mi][3], tAl + off);
            }
#pragma unroll
            for (int ni = 0; ni < 4; ni++) {
                uint32_t off = (b_row + ni * 8) * (LDS_ * 2) + b_colb + kb;
                LDSM_X2(bf[ni][0], bf[ni][1], tB + off);
            }
            // hi sweep (16 independent MMAs), then lo sweep
#pragma unroll
            for (int mi = 0; mi < 4; mi++)
#pragma unroll
                for (int ni = 0; ni < 4; ni++)
                    mma_f16(acc[mi][ni], ah[mi], bf[ni]);
#pragma unroll
            for (int mi = 0; mi < 4; mi++)
#pragma unroll
                for (int ni = 0; ni < 4; ni++)
                    mma_f16(acc[mi][ni], al[mi], bf[ni]);
        }
    }

    const int orow = m0 + wm + (lane >> 2);
    const int ocol = n0 + wn + 2 * (lane & 3);
#pragma unroll
    for (int mi = 0; mi < 4; mi++)
#pragma unroll
        for (int ni = 0; ni < 4; ni++) {
            float v0 = acc[mi][ni][0], v1 = acc[mi][ni][1];
            float v2 = acc[mi][ni][2], v3 = acc[mi][ni][3];
            if (mode == 1) {
                v0 = v0 / (1.f + expf(-v0));
                v1 = v1 / (1.f + expf(-v1));
                v2 = v2 / (1.f + expf(-v2));
                v3 = v3 / (1.f + expf(-v3));
            }
            float* p0 = C + (size_t)(orow + mi * 16) * D_ + ocol + ni * 8;
            float* p1 = C + (size_t)(orow + mi * 16 + 8) * D_ + ocol + ni * 8;
            *(float2*)p0 = make_float2(v0, v1);
            *(float2*)p1 = make_float2(v2, v3);
        }
}

// ========== beta projection: cp.async double-buffered tiled GEMM ===========
__global__ void __launch_bounds__(256) beta_gemm(const float* __restrict__ X,
                                                 const float* __restrict__ Wb,
                                                 float* __restrict__ beta) {
    __shared__ float Xs[2][16][132];   // row stride 528B (33 x 16B)
    __shared__ float Ws[2][128][16];   // row stride 64B
    const int m0 = blockIdx.x * 16;
    const int tid = threadIdx.x;
    const int row = tid >> 4, n = tid & 15;
    const uint32_t xb = smem_u32(&Xs[0][0][0]);
    const uint32_t wb = smem_u32(&Ws[0][0][0]);

    auto load_tile = [&](int buf, int kt) {
        const uint32_t xs = xb + buf * (16 * 132 * 4);
        const uint32_t ws = wb + buf * (128 * 16 * 4);
#pragma unroll
        for (int i = tid; i < 512; i += 256) {
            int r = i >> 5, c16 = i & 31;
            cp16(xs + r * 528 + c16 * 16, X + (size_t)(m0 + r) * D_ + kt + c16 * 4);
        }
#pragma unroll
        for (int i = tid; i < 512; i += 256) {
            int r = i >> 2, cc = i & 3;
            cp16(ws + r * 64 + cc * 16, Wb + (size_t)(kt + r) * H_ + cc * 4);
        }
        CP_COMMIT();
    };

    float acc = 0.f;
    load_tile(0, 0);
    for (int t = 0; t < 16; t++) {
        if (t + 1 < 16) load_tile((t + 1) & 1, (t + 1) * 128);
        else            CP_COMMIT();
        CP_WAIT(1);
        __syncthreads();
        const int buf = t & 1;
#pragma unroll 16
        for (int k = 0; k < 128; k++) acc += Xs[buf][row][k] * Ws[buf][k][n];
        __syncthreads();
    }
    beta[(size_t)(m0 + row) * H_ + n] = 1.f / (1.f + expf(-acc));
}

// ================= PRE: l2norm fused + per-chunk WY precompute ==============
__global__ void __launch_bounds__(128) pre_chunk(
    const float* __restrict__ q, const float* __restrict__ k,
    const float* __restrict__ v, const float* __restrict__ beta,
    float* __restrict__ W0g,
    __nv_bfloat16* __restrict__ TKh, __nv_bfloat16* __restrict__ TKl,
    __nv_bfloat16* __restrict__ Qh,  __nv_bfloat16* __restrict__ Ql,
    __nv_bfloat16* __restrict__ KTh, __nv_bfloat16* __restrict__ KTl,
    __nv_bfloat16* __restrict__ Ph,  __nv_bfloat16* __restrict__ Pl) {
    extern __shared__ float sm[];
    float* Kc  = sm;               // [32][128]
    float* Qc  = Kc + 32 * 128;    // [32][128]
    float* X   = Qc + 32 * 128;    // [32][256]  [bV | bK]
    float* Asm = X + 32 * 256;     // [32][32]
    float* bsm = Asm + 32 * 32;    // [32]

    const int ch = blockIdx.x;
    const int c  = ch & (NC_ - 1);
    const int bh = ch >> 6;
    const int b  = bh >> 4;
    const int h  = bh & 15;
    const int t0 = c * C_;
    const int tid = threadIdx.x;
    const size_t base0 = (size_t)b * L_ * D_ + (size_t)h * DH_;

    if (tid < 32) bsm[tid] = beta[((size_t)b * L_ + t0 + tid) * H_ + h];
    for (int i = tid; i < 32 * 32; i += 128) {
        int r = i >> 5, c4 = (i & 31) * 4;
        const size_t g = base0 + (size_t)(t0 + r) * D_ + c4;
        *(float4*)(Kc + r * 128 + c4) = *(const float4*)(k + g);
        *(float4*)(Qc + r * 128 + c4) = *(const float4*)(q + g);
        *(float4*)(X + r * 256 + c4)  = *(const float4*)(v + g);
    }
    __syncthreads();

    {
        const int w = tid >> 5, lane = tid & 31;
#pragma unroll
        for (int r = w * 8; r < w * 8 + 8; r++) {
            float4 kv = *(float4*)(Kc + r * 128 + lane * 4);
            float4 qv = *(float4*)(Qc + r * 128 + lane * 4);
            float sk = kv.x * kv.x + kv.y * kv.y + kv.z * kv.z + kv.w * kv.w;
            float sq = qv.x * qv.x + qv.y * qv.y + qv.z * qv.z + qv.w * qv.w;
#pragma unroll
            for (int off = 16; off; off >>= 1) {
                sk += __shfl_xor_sync(0xffffffffu, sk, off);
                sq += __shfl_xor_sync(0xffffffffu, sq, off);
            }
            float ik = 1.0f / fmaxf(sqrtf(sk), 1e-12f);
            float iq = 0.08838834764831845f / fmaxf(sqrtf(sq), 1e-12f);
            kv.x *= ik; kv.y *= ik; kv.z *= ik; kv.w *= ik;
            qv.x *= iq; qv.y *= iq; qv.z *= iq; qv.w *= iq;
            *(float4*)(Kc + r * 128 + lane * 4) = kv;
            *(float4*)(Qc + r * 128 + lane * 4) = qv;
        }
    }
    __syncthreads();

    for (int i = tid; i < 32 * 32; i += 128) {
        int r = i >> 5, c4 = (i & 31) * 4;
        float bt = bsm[r];
        float4 kv = *(float4*)(Kc + r * 128 + c4);
        kv.x *= bt; kv.y *= bt; kv.z *= bt; kv.w *= bt;
        *(float4*)(X + r * 256 + 128 + c4) = kv;
        float4 vv = *(float4*)(X + r * 256 + c4);
        vv.x *= bt; vv.y *= bt; vv.z *= bt; vv.w *= bt;
        *(float4*)(X + r * 256 + c4) = vv;
    }

    const int i_ = tid >> 2, j0 = (tid & 3) * 8;
    float accA[8], accP[8];
#pragma unroll
    for (int e = 0; e < 8; e++) { accA[e] = 0.f; accP[e] = 0.f; }
    for (int d4 = 0; d4 < 128; d4 += 4) {
        float4 ki = *(const float4*)(Kc + i_ * 128 + d4);
        float4 qi = *(const float4*)(Qc + i_ * 128 + d4);
#pragma unroll
        for (int e = 0; e < 8; e++) {
            float4 kj = *(const float4*)(Kc + (j0 + e) * 128 + d4);
            accA[e] += ki.x * kj.x + ki.y * kj.y + ki.z * kj.z + ki.w * kj.w;
            accP[e] += qi.x * kj.x + qi.y * kj.y + qi.z * kj.z + qi.w * kj.w;
        }
    }
    const float bi = bsm[i_];
#pragma unroll
    for (int e = 0; e < 8; e++) {
        int j = j0 + e;
        Asm[i_ * 32 + j] = (j < i_) ? bi * accA[e] : 0.f;
        float pv = (j <= i_) ? accP[e] : 0.f;
        __nv_bfloat16 phv = __float2bfloat16(pv);
        Ph[(size_t)ch * 1024 + i_ * 32 + j] = phv;
        Pl[(size_t)ch * 1024 + i_ * 32 + j] = __float2bfloat16(pv - __bfloat162float(phv));
    }
    __syncthreads();

    for (int i = 1; i < 32; i++) {
        float f0 = 0.f, f1 = 0.f;
        for (int j = 0; j < i; j++) {
            float a = Asm[i * 32 + j];
            f0 += a * X[j * 256 + tid];
            f1 += a * X[j * 256 + 128 + tid];
        }
        X[i * 256 + tid]       -= f0;
        X[i * 256 + 128 + tid] -= f1;
        __syncthreads();
    }

    for (int i = tid; i < 32 * 128; i += 128) {
        int n = i >> 7, m = i & 127;
        W0g[(size_t)ch * 4096 + i] = X[n * 256 + m];
        float tkv = X[n * 256 + 128 + m];
        __nv_bfloat16 th_ = __float2bfloat16(tkv);
        TKh[(size_t)ch * 4096 + i] = th_;
        TKl[(size_t)ch * 4096 + i] = __float2bfloat16(tkv - __bfloat162float(th_));
        float qv = Qc[n * 128 + m];
        __nv_bfloat16 qh_ = __float2bfloat16(qv);
        Qh[(size_t)ch * 4096 + i] = qh_;
        Ql[(size_t)ch * 4096 + i] = __float2bfloat16(qv - __bfloat162float(qh_));
    }
#pragma unroll
    for (int n = 0; n < 32; n++) {
        float kv = Kc[n * 128 + tid];
        __nv_bfloat16 kh_ = __float2bfloat16(kv);
        KTh[(size_t)ch * 4096 + tid * 32 + n] = kh_;
        KTl[(size_t)ch * 4096 + tid * 32 + n] = __float2bfloat16(kv - __bfloat162float(kh_));
    }
}

// ================= SEQ: sequential chunk chain, MMA-based ===================
#define OS_SHI 0
#define OS_SLO 34816
#define OS_WTH 69632
#define OS_WTL 79872
#define OS_TKH 90112
#define OS_TKL 98816
#define OS_QH  107520
#define OS_QL  116224
#define OS_KTH 124928
#define OS_KTL 135168
#define OS_PH  145408
#define OS_PL  147968
#define OS_W0  150528
#define OS_CS  166912
#define SEQ_SMEM 167040
#define SST 272
#define WST 80

__global__ void __launch_bounds__(256, 1) seq_chunk(
    const float* __restrict__ W0g,
    const __nv_bfloat16* __restrict__ TKh, const __nv_bfloat16* __restrict__ TKl,
    const __nv_bfloat16* __restrict__ Qh,  const __nv_bfloat16* __restrict__ Ql,
    const __nv_bfloat16* __restrict__ KTh, const __nv_bfloat16* __restrict__ KTl,
    const __nv_bfloat16* __restrict__ Ph,  const __nv_bfloat16* __restrict__ Pl,
    const float* __restrict__ wnorm, float* __restrict__ o) {
    extern __shared__ char smraw[];
    const int bh = blockIdx.x;
    const int b = bh >> 4, h = bh & 15;
    const int tid = threadIdx.x, wid = tid >> 5, lane = tid & 31;
    const uint32_t sb = smem_u32(smraw);
    float* W0s = (float*)(smraw + OS_W0);
    float* colsum = (float*)(smraw + OS_CS);

    for (int i = tid; i < (OS_WTH) / 16; i += 256)
        ((uint4*)smraw)[i] = make_uint4(0, 0, 0, 0);

    float Sfr[2][8][4];
#pragma unroll
    for (int mi = 0; mi < 2; mi++)
#pragma unroll
        for (int ni = 0; ni < 8; ni++)
#pragma unroll
            for (int e = 0; e < 4; e++) Sfr[mi][ni][e] = 0.f;

    const int wm = (wid & 3) * 32;
    const int wn16 = (wid >> 2) * 16;
    const int wn64 = (wid >> 2) * 64;
    const int a_r = lane & 15, a_cB = (lane >> 4) << 4;
    const int b_r = lane & 7,  b_cB = ((lane >> 3) & 1) << 4;
    const int fr = lane >> 2, fc = (lane & 3) * 2;

    float wnr[2][2];
#pragma unroll
    for (int mi = 0; mi < 2; mi++)
#pragma unroll
        for (int pp = 0; pp < 2; pp++)
            wnr[mi][pp] = wnorm[wm + mi * 16 + pp * 8 + fr];

    for (int c = 0; c < NC_; c++) {
        const size_t ch = (size_t)bh * NC_ + c;
        __syncthreads();

        {
            const uint4* gtkh = (const uint4*)(TKh + ch * 4096);
            const uint4* gtkl = (const uint4*)(TKl + ch * 4096);
            const uint4* gqh  = (const uint4*)(Qh + ch * 4096);
            const uint4* gql  = (const uint4*)(Ql + ch * 4096);
            for (int i = tid; i < 512; i += 256) {
                int r = i >> 4, qq = (i & 15) * 16;
                *(uint4*)(smraw + OS_TKH + r * SST + qq) = gtkh[i];
                *(uint4*)(smraw + OS_TKL + r * SST + qq) = gtkl[i];
                *(uint4*)(smraw + OS_QH + r * SST + qq) = gqh[i];
                *(uint4*)(smraw + OS_QL + r * SST + qq) = gql[i];
            }
            const uint4* gkth = (const uint4*)(KTh + ch * 4096);
            const uint4* gktl = (const uint4*)(KTl + ch * 4096);
            for (int i = tid; i < 512; i += 256) {
                int r = i >> 2, qq = (i & 3) * 16;
                *(uint4*)(smraw + OS_KTH + r * WST + qq) = gkth[i];
                *(uint4*)(smraw + OS_KTL + r * WST + qq) = gktl[i];
            }
            const uint4* gph = (const uint4*)(Ph + ch * 1024);
            const uint4* gpl = (const uint4*)(Pl + ch * 1024);
            if (tid < 128) {
                int r = tid >> 2, qq = (tid & 3) * 16;
                *(uint4*)(smraw + OS_PH + r * WST + qq) = gph[tid];
                *(uint4*)(smraw + OS_PL + r * WST + qq) = gpl[tid];
            }
            const uint4* gw0 = (const uint4*)(W0g + ch * 4096);
            for (int i = tid; i < 1024; i += 256)
                ((uint4*)(smraw + OS_W0))[i] = gw0[i];
            if (tid < 32) colsum[tid] = 0.f;
        }
        __syncthreads();

        // step 1: Wt = W0^T - Ssm @ TK^T
        float acc[2][2][4];
#pragma unroll
        for (int mi = 0; mi < 2; mi++)
#pragma unroll
            for (int ni = 0; ni < 2; ni++)
#pragma unroll
                for (int e = 0; e < 4; e++) acc[mi][ni][e] = 0.f;
#pragma unroll
        for (int ks = 0; ks < 8; ks++) {
            uint32_t ah[2][4], al[2][4], bhf[2][2], blf[2][2];
#pragma unroll
            for (int mi = 0; mi < 2; mi++) {
                uint32_t off = (wm + mi * 16 + a_r) * SST + a_cB + ks * 32;
                LDSM_X4(ah[mi][0], ah[mi][1], ah[mi][2], ah[mi][3], sb + OS_SHI + off);
                LDSM_X4(al[mi][0], al[mi][1], al[mi][2], al[mi][3], sb + OS_SLO + off);
            }
#pragma unroll
            for (int ni = 0; ni < 2; ni++) {
                uint32_t off = (wn16 + ni * 8 + b_r) * SST + b_cB + ks * 32;
                LDSM_X2(bhf[ni][0], bhf[ni][1], sb + OS_TKH + off);
                LDSM_X2(blf[ni][0], blf[ni][1], sb + OS_TKL + off);
            }
#pragma unroll
            for (int mi = 0; mi < 2; mi++)
#pragma unroll
                for (int ni = 0; ni < 2; ni++) {
                    mma_bf16(acc[mi][ni], ah[mi], bhf[ni]);
                    mma_bf16(acc[mi][ni], ah[mi], blf[ni]);
                    mma_bf16(acc[mi][ni], al[mi], bhf[ni]);
                }
        }
#pragma unroll
        for (int mi = 0; mi < 2; mi++)
#pragma unroll
            for (int ni = 0; ni < 2; ni++)
#pragma unroll
                for (int pp = 0; pp < 2; pp++) {
                    int m = wm + mi * 16 + fr + pp * 8;
                    int n0 = wn16 + ni * 8 + fc;
                    float v0 = W0s[n0 * 128 + m] - acc[mi][ni][pp * 2 + 0];
                    float v1 = W0s[(n0 + 1) * 128 + m] - acc[mi][ni][pp * 2 + 1];
                    uint32_t lo, hi = pack_split(v0, v1, lo);
                    *(uint32_t*)(smraw + OS_WTH + m * WST + n0 * 2) = hi;
                    *(uint32_t*)(smraw + OS_WTL + m * WST + n0 * 2) = lo;
                }
        __syncthreads();

        // step 2: Ot = Ssm @ Q^T + Wt @ P^T
        float oacc[2][2][4];
#pragma unroll
        for (int mi = 0; mi < 2; mi++)
#pragma unroll
            for (int ni = 0; ni < 2; ni++)
#pragma unroll
                for (int e = 0; e < 4; e++) oacc[mi][ni][e] = 0.f;
#pragma unroll
        for (int ks = 0; ks < 8; ks++) {
            uint32_t ah[2][4], al[2][4], bhf[2][2], blf[2][2];
#pragma unroll
            for (int mi = 0; mi < 2; mi++) {
                uint32_t off = (wm + mi * 16 + a_r) * SST + a_cB + ks * 32;
                LDSM_X4(ah[mi][0], ah[mi][1], ah[mi][2], ah[mi][3], sb + OS_SHI + off);
                LDSM_X4(al[mi][0], al[mi][1], al[mi][2], al[mi][3], sb + OS_SLO + off);
            }
#pragma unroll
            for (int ni = 0; ni < 2; ni++) {
                uint32_t off = (wn16 + ni * 8 + b_r) * SST + b_cB + ks * 32;
                LDSM_X2(bhf[ni][0], bhf[ni][1], sb + OS_QH + off);
                LDSM_X2(blf[ni][0], blf[ni][1], sb + OS_QL + off);
            }
#pragma unroll
            for (int mi = 0; mi < 2; mi++)
#pragma unroll
                for (int ni = 0; ni < 2; ni++) {
                    mma_bf16(oacc[mi][ni], ah[mi], bhf[ni]);
                    mma_bf16(oacc[mi][ni], ah[mi], blf[ni]);
                    mma_bf16(oacc[mi][ni], al[mi], bhf[ni]);
                }
        }
#pragma unroll
        for (int ks = 0; ks < 2; ks++) {
            uint32_t ah[2][4], al[2][4], bhf[2][2], blf[2][2];
#pragma unroll
            for (int mi = 0; mi < 2; mi++) {
                uint32_t off = (wm + mi * 16 + a_r) * WST + a_cB + ks * 32;
                LDSM_X4(ah[mi][0], ah[mi][1], ah[mi][2], ah[mi][3], sb + OS_WTH + off);
                LDSM_X4(al[mi][0], al[mi][1], al[mi][2], al[mi][3], sb + OS_WTL + off);
            }
#pragma unroll
            for (int ni = 0; ni < 2; ni++) {
                uint32_t off = (wn16 + ni * 8 + b_r) * WST + b_cB + ks * 32;
                LDSM_X2(bhf[ni][0], bhf[ni][1], sb + OS_PH + off);
                LDSM_X2(blf[ni][0], blf[ni][1], sb + OS_PL + off);
            }
#pragma unroll
            for (int mi = 0; mi < 2; mi++)
#pragma unroll
                for (int ni = 0; ni < 2; ni++) {
                    mma_bf16(oacc[mi][ni], ah[mi], bhf[ni]);
                    mma_bf16(oacc[mi][ni], ah[mi], blf[ni]);
                    mma_bf16(oacc[mi][ni], al[mi], bhf[ni]);
                }
        }
#pragma unroll
        for (int ni = 0; ni < 2; ni++) {
            float s0 = oacc[0][ni][0] * oacc[0][ni][0] + oacc[0][ni][2] * oacc[0][ni][2]
                     + oacc[1][ni][0] * oacc[1][ni][0] + oacc[1][ni][2] * oacc[1][ni][2];
            float s1 = oacc[0][ni][1] * oacc[0][ni][1] + oacc[0][ni][3] * oacc[0][ni][3]
                     + oacc[1][ni][1] * oacc[1][ni][1] + oacc[1][ni][3] * oacc[1][ni][3];
#pragma unroll
            for (int off = 4; off <= 16; off <<= 1) {
                s0 += __shfl_xor_sync(0xffffffffu, s0, off);
                s1 += __shfl_xor_sync(0xffffffffu, s1, off);
            }
            if (lane < 4) {
                atomicAdd(&colsum[wn16 + ni * 8 + 2 * lane], s0);
                atomicAdd(&colsum[wn16 + ni * 8 + 2 * lane + 1], s1);
            }
        }
        __syncthreads();

        {
            const size_t obase = (size_t)b * L_ * D_ + (size_t)h * DH_ + (size_t)(c * C_) * D_;
#pragma unroll
            for (int ni = 0; ni < 2; ni++) {
                int n0 = wn16 + ni * 8 + fc;
                float r0 = rsqrtf(colsum[n0] * (1.f / 128.f) + 1e-5f);
                float r1 = rsqrtf(colsum[n0 + 1] * (1.f / 128.f) + 1e-5f);
#pragma unroll
                for (int mi = 0; mi < 2; mi++)
#pragma unroll
                    for (int pp = 0; pp < 2; pp++) {
                        int m = wm + mi * 16 + fr + pp * 8;
                        o[obase + (size_t)n0 * D_ + m] = oacc[mi][ni][pp * 2] * r0 * wnr[mi][pp];
                        o[obase + (size_t)(n0 + 1) * D_ + m] = oacc[mi][ni][pp * 2 + 1] * r1 * wnr[mi][pp];
                    }
            }
        }

        // step 3: Ssm += Wt @ K
#pragma unroll
        for (int ks = 0; ks < 2; ks++) {
            uint32_t ah[2][4], al[2][4];
#pragma unroll
            for (int mi = 0; mi < 2; mi++) {
                uint32_t off = (wm + mi * 16 + a_r) * WST + a_cB + ks * 32;
                LDSM_X4(ah[mi][0], ah[mi][1], ah[mi][2], ah[mi][3], sb + OS_WTH + off);
                LDSM_X4(al[mi][0], al[mi][1], al[mi][2], al[mi][3], sb + OS_WTL + off);
            }
#pragma unroll
            for (int ni = 0; ni < 8; ni++) {
                uint32_t bhf[2], blf[2];
                uint32_t off = (wn64 + ni * 8 + b_r) * WST + b_cB + ks * 32;
                LDSM_X2(bhf[0], bhf[1], sb + OS_KTH + off);
                LDSM_X2(blf[0], blf[1], sb + OS_KTL + off);
#pragma unroll
                for (int mi = 0; mi < 2; mi++) {
                    mma_bf16(Sfr[mi][ni], ah[mi], bhf);
                    mma_bf16(Sfr[mi][ni], ah[mi], blf);
                    mma_bf16(Sfr[mi][ni], al[mi], bhf);
                }
            }
        }
#pragma unroll
        for (int mi = 0; mi < 2; mi++)
#pragma unroll
            for (int ni = 0; ni < 8; ni++)
#pragma unroll
                for (int pp = 0; pp < 2; pp++) {
                    int m = wm + mi * 16 + fr + pp * 8;
                    int n0 = wn64 + ni * 8 + fc;
                    uint32_t lo, hi = pack_split(Sfr[mi][ni][pp * 2], Sfr[mi][ni][pp * 2 + 1], lo);
                    *(uint32_t*)(smraw + OS_SHI + m * SST + n0 * 2) = hi;
                    *(uint32_t*)(smraw + OS_SLO + m * SST + n0 * 2) = lo;
                }
    }
}

// ================= launch =================
extern "C" void kernel_launch(void* const* d_in, const int* in_sizes, int n_in,
                              void* d_out, int out_size) {
    const float* X  = (const float*)d_in[0];
    const float* Wq = (const float*)d_in[1];
    const float* Wk = (const float*)d_in[2];
    const float* Wv = (const float*)d_in[3];
    const float* Wb = (const float*)d_in[4];
    const float* wn = (const float*)d_in[5];
    const float* Wo = (const float*)d_in[6];
    float* out = (float*)d_out;

    float *gq, *gk, *gv, *go, *gb, *gW0;
    __half *ahi, *alo, *wt;
    __nv_bfloat16 *tkh, *tkl, *qch, *qcl, *kth, *ktl, *ph, *pl;
    cudaGetSymbolAddress((void**)&gq, g_q);
    cudaGetSymbolAddress((void**)&gk, g_k);
    cudaGetSymbolAddress((void**)&gv, g_v);
    cudaGetSymbolAddress((void**)&go, g_o);
    cudaGetSymbolAddress((void**)&gb, g_beta);
    cudaGetSymbolAddress((void**)&ahi, g_Ahi);
    cudaGetSymbolAddress((void**)&alo, g_Alo);
    cudaGetSymbolAddress((void**)&wt, g_Wt);
    cudaGetSymbolAddress((void**)&gW0, g_W0);
    cudaGetSymbolAddress((void**)&tkh, g_TKh);
    cudaGetSymbolAddress((void**)&tkl, g_TKl);
    cudaGetSymbolAddress((void**)&qch, g_Qch);
    cudaGetSymbolAddress((void**)&qcl, g_Qcl);
    cudaGetSymbolAddress((void**)&kth, g_KTh);
    cudaGetSymbolAddress((void**)&ktl, g_KTl);
    cudaGetSymbolAddress((void**)&ph, g_Ph);
    cudaGetSymbolAddress((void**)&pl, g_Pl);

    cudaFuncSetAttribute(gemm_f16split, cudaFuncAttributeMaxDynamicSharedMemorySize, SMEM_DYN);
    cudaFuncSetAttribute(pre_chunk, cudaFuncAttributeMaxDynamicSharedMemorySize, 69760);
    cudaFuncSetAttribute(seq_chunk, cudaFuncAttributeMaxDynamicSharedMemorySize, SEQ_SMEM);

    const int NSPLIT = M_ * D_ / 4 / 256;

    split_rows<<<NSPLIT, 256>>>((const float4*)X, (uint2*)ahi, (uint2*)alo);
    split_transpose<<<dim3(D_ / 32, D_ / 32, 4), dim3(32, 8)>>>(Wq, Wk, Wv, Wo, wt);

    GemmArgs qa;
    qa.Bw[0] = wt;
    qa.Bw[1] = wt + (size_t)D_ * D_;
    qa.Bw[2] = wt + (size_t)2 * D_ * D_;
    qa.C[0] = gq; qa.C[1] = gk; qa.C[2] = gv;
    qa.mode[0] = 0; qa.mode[1] = 0; qa.mode[2] = 1;
    gemm_f16split<<<dim3(D_ / BN, M_ / BM, 3), 256, SMEM_DYN>>>(ahi, alo, qa);

    beta_gemm<<<M_ / 16, 256>>>(X, Wb, gb);

    pre_chunk<<<NCH_, 128, 69760>>>(gq, gk, gv, gb, gW0, tkh, tkl, qch, qcl, kth, ktl, ph, pl);
    seq_chunk<<<B_ * H_, 256, SEQ_SMEM>>>(gW0, tkh, tkl, qch, qcl, kth, ktl, ph, pl, wn, go);

    split_rows<<<NSPLIT, 256>>>((const float4*)go, (uint2*)ahi, (uint2*)alo);
    GemmArgs oa;
    oa.Bw[0] = wt + (size_t)3 * D_ * D_;
    oa.Bw[1] = oa.Bw[0];
    oa.Bw[2] = oa.Bw[0];
    oa.C[0] = out; oa.C[1] = out; oa.C[2] = out;
    oa.mode[0] = 0; oa.mode[1] = 0; oa.mode[2] = 0;
    gemm_f16split<<<dim3(D_ / BN, M_ / BM, 1), 256, SMEM_DYN>>>(ahi, alo, oa);
}

// round 8
// speedup vs baseline: 3.4571x; 1.0944x over previous
#include <cuda_runtime.h>
#include <cuda_bf16.h>
#include <cuda_fp16.h>
#include <math.h>
#include <stdint.h>

#define B_  2
#define L_  2048
#define D_  2048
#define H_  16
#define DH_ 128
#define M_  (B_ * L_)   // 4096
#define C_  32          // chunk length
#define NC_ (L_ / C_)   // 64 chunks per (b,h)
#define NCH_ (B_ * H_ * NC_)  // 2048 chunk-heads

// ================= scratch (device globals; no allocations) =================
__device__ float g_q[M_ * D_];
__device__ float g_k[M_ * D_];
__device__ float g_v[M_ * D_];
__device__ float g_o[M_ * D_];
__device__ float g_beta[M_ * H_];
__device__ float g_ss[2 * M_ * H_];      // partial sumsq per dv-half
__device__ __half g_Ahi[M_ * D_];        // fp16 hi/lo split of GEMM A operand
__device__ __half g_Alo[M_ * D_];
__device__ __half g_Wt[4 * D_ * D_];     // transposed weights [N,K] fp16, order q,k,v,o
// chunked delta-rule precompute (bf16 3-combo)
__device__ float g_W0[NCH_ * C_ * DH_];
__device__ __nv_bfloat16 g_TKh[NCH_ * C_ * DH_];
__device__ __nv_bfloat16 g_TKl[NCH_ * C_ * DH_];
__device__ __nv_bfloat16 g_Qch[NCH_ * C_ * DH_];
__device__ __nv_bfloat16 g_Qcl[NCH_ * C_ * DH_];
__device__ __nv_bfloat16 g_KTh[NCH_ * DH_ * C_];
__device__ __nv_bfloat16 g_KTl[NCH_ * DH_ * C_];
__device__ __nv_bfloat16 g_Ph[NCH_ * C_ * C_];
__device__ __nv_bfloat16 g_Pl[NCH_ * C_ * C_];

// ================= helpers =================
__device__ __forceinline__ uint32_t smem_u32(const void* p) {
    uint32_t a;
    asm("{ .reg .u64 t; cvta.to.shared.u64 t, %1; cvt.u32.u64 %0, t; }" : "=r"(a) : "l"(p));
    return a;
}
__device__ __forceinline__ void cp16(uint32_t dst, const void* src) {
    asm volatile("cp.async.cg.shared.global [%0], [%1], 16;" :: "r"(dst), "l"(src));
}
#define CP_COMMIT() asm volatile("cp.async.commit_group;" ::: "memory")
#define CP_WAIT(n)  asm volatile("cp.async.wait_group %0;" :: "n"(n) : "memory")

#define LDSM_X4(r0, r1, r2, r3, addr)                                            \
    asm volatile("ldmatrix.sync.aligned.m8n8.x4.shared.b16 {%0,%1,%2,%3}, [%4];" \
        : "=r"(r0), "=r"(r1), "=r"(r2), "=r"(r3) : "r"(addr))
#define LDSM_X2(r0, r1, addr)                                                    \
    asm volatile("ldmatrix.sync.aligned.m8n8.x2.shared.b16 {%0,%1}, [%2];"       \
        : "=r"(r0), "=r"(r1) : "r"(addr))

__device__ __forceinline__ void mma_bf16(float* d, const uint32_t* a, const uint32_t* b) {
    asm volatile(
        "mma.sync.aligned.m16n8k16.row.col.f32.bf16.bf16.f32 "
        "{%0,%1,%2,%3}, {%4,%5,%6,%7}, {%8,%9}, {%0,%1,%2,%3};"
        : "+f"(d[0]), "+f"(d[1]), "+f"(d[2]), "+f"(d[3])
        : "r"(a[0]), "r"(a[1]), "r"(a[2]), "r"(a[3]), "r"(b[0]), "r"(b[1]));
}
__device__ __forceinline__ void mma_f16(float* d, const uint32_t* a, const uint32_t* b) {
    asm volatile(
        "mma.sync.aligned.m16n8k16.row.col.f32.f16.f16.f32 "
        "{%0,%1,%2,%3}, {%4,%5,%6,%7}, {%8,%9}, {%0,%1,%2,%3};"
        : "+f"(d[0]), "+f"(d[1]), "+f"(d[2]), "+f"(d[3])
        : "r"(a[0]), "r"(a[1]), "r"(a[2]), "r"(a[3]), "r"(b[0]), "r"(b[1]));
}
__device__ __forceinline__ uint32_t pack_split(float v0, float v1, uint32_t& lo) {
    __nv_bfloat16 h0 = __float2bfloat16(v0), h1 = __float2bfloat16(v1);
    __nv_bfloat16 l0 = __float2bfloat16(v0 - __bfloat162float(h0));
    __nv_bfloat16 l1 = __float2bfloat16(v1 - __bfloat162float(h1));
    lo = ((uint32_t)__bfloat16_as_ushort(l1) << 16) | __bfloat16_as_ushort(l0);
    return ((uint32_t)__bfloat16_as_ushort(h1) << 16) | __bfloat16_as_ushort(h0);
}

// ================= split fp32 -> fp16 hi/lo =================
__global__ void __launch_bounds__(256) split_rows(const float4* __restrict__ X,
                                                  uint2* __restrict__ hi,
                                                  uint2* __restrict__ lo) {
    int i = blockIdx.x * 256 + threadIdx.x;
    float4 x = X[i];
    __half h0 = __float2half_rn(x.x), h1 = __float2half_rn(x.y);
    __half h2 = __float2half_rn(x.z), h3 = __float2half_rn(x.w);
    __half l0 = __float2half_rn(x.x - __half2float(h0));
    __half l1 = __float2half_rn(x.y - __half2float(h1));
    __half l2 = __float2half_rn(x.z - __half2float(h2));
    __half l3 = __float2half_rn(x.w - __half2float(h3));
    uint2 hv, lv;
    hv.x = ((uint32_t)__half_as_ushort(h1) << 16) | __half_as_ushort(h0);
    hv.y = ((uint32_t)__half_as_ushort(h3) << 16) | __half_as_ushort(h2);
    lv.x = ((uint32_t)__half_as_ushort(l1) << 16) | __half_as_ushort(l0);
    lv.y = ((uint32_t)__half_as_ushort(l3) << 16) | __half_as_ushort(l2);
    hi[i] = hv;
    lo[i] = lv;
}

// split + deferred RMSNorm scale (for o): x *= rsqrt(mean(ss)+eps)
__global__ void __launch_bounds__(256) split_rows_norm(const float4* __restrict__ X,
                                                       uint2* __restrict__ hi,
                                                       uint2* __restrict__ lo,
                                                       const float* __restrict__ ss) {
    int i = blockIdx.x * 256 + threadIdx.x;
    int m = i >> 9;                 // row (D_/4 = 512 float4 per row)
    int h = (i & 511) >> 5;         // head = (col*4)/128
    float s = ss[(size_t)m * H_ + h] + ss[(size_t)M_ * H_ + (size_t)m * H_ + h];
    float r = rsqrtf(s * (1.0f / 128.0f) + 1e-5f);
    float4 x = X[i];
    x.x *= r; x.y *= r; x.z *= r; x.w *= r;
    __half h0 = __float2half_rn(x.x), h1 = __float2half_rn(x.y);
    __half h2 = __float2half_rn(x.z), h3 = __float2half_rn(x.w);
    __half l0 = __float2half_rn(x.x - __half2float(h0));
    __half l1 = __float2half_rn(x.y - __half2float(h1));
    __half l2 = __float2half_rn(x.z - __half2float(h2));
    __half l3 = __float2half_rn(x.w - __half2float(h3));
    uint2 hv, lv;
    hv.x = ((uint32_t)__half_as_ushort(h1) << 16) | __half_as_ushort(h0);
    hv.y = ((uint32_t)__half_as_ushort(h3) << 16) | __half_as_ushort(h2);
    lv.x = ((uint32_t)__half_as_ushort(l1) << 16) | __half_as_ushort(l0);
    lv.y = ((uint32_t)__half_as_ushort(l3) << 16) | __half_as_ushort(l2);
    hi[i] = hv;
    lo[i] = lv;
}

// transpose weights: W[k][n] fp32 -> Wt[n][k] fp16 (grid.z selects matrix)
__global__ void __launch_bounds__(256) split_transpose(
    const float* __restrict__ W0, const float* __restrict__ W1,
    const float* __restrict__ W2, const float* __restrict__ W3,
    __half* __restrict__ wt) {
    __shared__ float t[32][33];
    const float* W = (blockIdx.z == 0) ? W0 : (blockIdx.z == 1) ? W1
                   : (blockIdx.z == 2) ? W2 : W3;
    __half* ho = wt + (size_t)blockIdx.z * D_ * D_;
    const int n = blockIdx.x * 32 + threadIdx.x;
    const int k0 = blockIdx.y * 32;
#pragma unroll
    for (int i = threadIdx.y; i < 32; i += 8)
        t[i][threadIdx.x] = W[(size_t)(k0 + i) * D_ + n];
    __syncthreads();
#pragma unroll
    for (int i = threadIdx.y; i < 32; i += 8) {
        const int nn = blockIdx.x * 32 + i;
        ho[(size_t)nn * D_ + k0 + threadIdx.x] = __float2half_rn(t[threadIdx.x][i]);
    }
}

// ====== fp16 2-combo GEMM: 3-stage, 2 CTAs/SM, hi/lo sweeps separated =======
#define BM 128
#define BN 128
#define BK 32
#define LDS_ 40
#define TILE_B (128 * LDS_ * 2)       // 10240
#define STAGE_B (3 * TILE_B)          // Ah, Al, B = 30720
#define NSTAGE 3
#define SMEM_DYN (NSTAGE * STAGE_B)   // 92160
#define NCHUNK (D_ / BK)

struct GemmArgs {
    const __half* Bw[3];
    float* C[3];
    int mode[3];
};

__device__ __forceinline__ void load_chunk(uint32_t sbase, int stage,
    const __half* Ahi, const __half* Alo, const __half* Bw,
    int m0, int n0, int kc, int tid) {
    const int r  = tid >> 1;
    const int c0 = (tid & 1) * 2;
    const uint32_t st = sbase + stage * STAGE_B;
    const size_t koff = (size_t)kc * BK;
    const __half* srcs[3] = {
        Ahi + (size_t)(m0 + r) * D_ + koff,
        Alo + (size_t)(m0 + r) * D_ + koff,
        Bw  + (size_t)(n0 + r) * D_ + koff };
#pragma unroll
    for (int t = 0; t < 3; t++) {
        uint32_t rowb = st + t * TILE_B + r * (LDS_ * 2);
        cp16(rowb + (c0 + 0) * 16, srcs[t] + (c0 + 0) * 8);
        cp16(rowb + (c0 + 1) * 16, srcs[t] + (c0 + 1) * 8);
    }
    CP_COMMIT();
}

__global__ void __launch_bounds__(256, 2) gemm_f16split(
    const __half* __restrict__ Ahi, const __half* __restrict__ Alo,
    GemmArgs args) {
    extern __shared__ char smem_raw[];
    const int z = blockIdx.z;
    const __half* Bw = args.Bw[z];
    float* C = args.C[z];
    const int mode = args.mode[z];

    const int m0 = blockIdx.y * BM;
    const int n0 = blockIdx.x * BN;
    const int tid = threadIdx.x;
    const int wid = tid >> 5;
    const int lane = tid & 31;
    const int wm = (wid & 1) * 64;
    const int wn = (wid >> 1) * 32;
    const uint32_t sbase = smem_u32(smem_raw);

    const uint32_t a_row  = wm + (lane & 15);
    const uint32_t a_colb = ((lane >> 4) << 4);
    const uint32_t b_row  = wn + (lane & 7);
    const uint32_t b_colb = (((lane >> 3) & 1) << 4);

    float acc[4][4][4];
#pragma unroll
    for (int mi = 0; mi < 4; mi++)
#pragma unroll
        for (int ni = 0; ni < 4; ni++)
#pragma unroll
            for (int t = 0; t < 4; t++) acc[mi][ni][t] = 0.f;

    load_chunk(sbase, 0, Ahi, Alo, Bw, m0, n0, 0, tid);
    load_chunk(sbase, 1, Ahi, Alo, Bw, m0, n0, 1, tid);

    for (int c = 0; c < NCHUNK; c++) {
        CP_WAIT(1);
        __syncthreads();
        if (c + 2 < NCHUNK) {
            int s = (c + 2) % NSTAGE;
            load_chunk(sbase, s, Ahi, Alo, Bw, m0, n0, c + 2, tid);
        } else {
            CP_COMMIT();
        }

        const uint32_t st  = sbase + (c % NSTAGE) * STAGE_B;
        const uint32_t tAh = st;
        const uint32_t tAl = st + TILE_B;
        const uint32_t tB  = st + 2 * TILE_B;

#pragma unroll
        for (int ks = 0; ks < 2; ks++) {
            const uint32_t kb = ks * 32;
            uint32_t ah[4][4], al[4][4], bf[4][2];
#pragma unroll
            for (int mi = 0; mi < 4; mi++) {
                uint32_t off = (a_row + mi * 16) * (LDS_ * 2) + a_colb + kb;
                LDSM_X4(ah[mi][0], ah[mi][1], ah[mi][2], ah[mi][3], tAh + off);
                LDSM_X4(al[mi][0], al[mi][1], al[mi][2], al[mi][3], tAl + off);
            }
#pragma unroll
            for (int ni = 0; ni < 4; ni++) {
                uint32_t off = (b_row + ni * 8) * (LDS_ * 2) + b_colb + kb;
                LDSM_X2(bf[ni][0], bf[ni][1], tB + off);
            }
#pragma unroll
            for (int mi = 0; mi < 4; mi++)
#pragma unroll
                for (int ni = 0; ni < 4; ni++)
                    mma_f16(acc[mi][ni], ah[mi], bf[ni]);
#pragma unroll
            for (int mi = 0; mi < 4; mi++)
#pragma unroll
                for (int ni = 0; ni < 4; ni++)
                    mma_f16(acc[mi][ni], al[mi], bf[ni]);
        }
    }

    const int orow = m0 + wm + (lane >> 2);
    const int ocol = n0 + wn + 2 * (lane & 3);
#pragma unroll
    for (int mi = 0; mi < 4; mi++)
#pragma unroll
        for (int ni = 0; ni < 4; ni++) {
            float v0 = acc[mi][ni][0], v1 = acc[mi][ni][1];
            float v2 = acc[mi][ni][2], v3 = acc[mi][ni][3];
            if (mode == 1) {
                v0 = v0 / (1.f + expf(-v0));
                v1 = v1 / (1.f + expf(-v1));
                v2 = v2 / (1.f + expf(-v2));
                v3 = v3 / (1.f + expf(-v3));
            }
            float* p0 = C + (size_t)(orow + mi * 16) * D_ + ocol + ni * 8;
            float* p1 = C + (size_t)(orow + mi * 16 + 8) * D_ + ocol + ni * 8;
            *(float2*)p0 = make_float2(v0, v1);
            *(float2*)p1 = make_float2(v2, v3);
        }
}

// ========== beta projection: cp.async double-buffered tiled GEMM ===========
__global__ void __launch_bounds__(256) beta_gemm(const float* __restrict__ X,
                                                 const float* __restrict__ Wb,
                                                 float* __restrict__ beta) {
    __shared__ float Xs[2][16][132];
    __shared__ float Ws[2][128][16];
    const int m0 = blockIdx.x * 16;
    const int tid = threadIdx.x;
    const int row = tid >> 4, n = tid & 15;
    const uint32_t xb = smem_u32(&Xs[0][0][0]);
    const uint32_t wb = smem_u32(&Ws[0][0][0]);

    auto load_tile = [&](int buf, int kt) {
        const uint32_t xs = xb + buf * (16 * 132 * 4);
        const uint32_t ws = wb + buf * (128 * 16 * 4);
#pragma unroll
        for (int i = tid; i < 512; i += 256) {
            int r = i >> 5, c16 = i & 31;
            cp16(xs + r * 528 + c16 * 16, X + (size_t)(m0 + r) * D_ + kt + c16 * 4);
        }
#pragma unroll
        for (int i = tid; i < 512; i += 256) {
            int r = i >> 2, cc = i & 3;
            cp16(ws + r * 64 + cc * 16, Wb + (size_t)(kt + r) * H_ + cc * 4);
        }
        CP_COMMIT();
    };

    float acc = 0.f;
    load_tile(0, 0);
    for (int t = 0; t < 16; t++) {
        if (t + 1 < 16) load_tile((t + 1) & 1, (t + 1) * 128);
        else            CP_COMMIT();
        CP_WAIT(1);
        __syncthreads();
        const int buf = t & 1;
#pragma unroll 16
        for (int k = 0; k < 128; k++) acc += Xs[buf][row][k] * Ws[buf][k][n];
        __syncthreads();
    }
    beta[(size_t)(m0 + row) * H_ + n] = 1.f / (1.f + expf(-acc));
}

// ================= PRE: l2norm fused + per-chunk WY precompute ==============
__global__ void __launch_bounds__(128) pre_chunk(
    const float* __restrict__ q, const float* __restrict__ k,
    const float* __restrict__ v, const float* __restrict__ beta,
    float* __restrict__ W0g,
    __nv_bfloat16* __restrict__ TKh, __nv_bfloat16* __restrict__ TKl,
    __nv_bfloat16* __restrict__ Qh,  __nv_bfloat16* __restrict__ Ql,
    __nv_bfloat16* __restrict__ KTh, __nv_bfloat16* __restrict__ KTl,
    __nv_bfloat16* __restrict__ Ph,  __nv_bfloat16* __restrict__ Pl) {
    extern __shared__ float sm[];
    float* Kc  = sm;               // [32][128]
    float* Qc  = Kc + 32 * 128;    // [32][128]
    float* X   = Qc + 32 * 128;    // [32][256]  [bV | bK]
    float* Asm = X + 32 * 256;     // [32][32]
    float* bsm = Asm + 32 * 32;    // [32]

    const int ch = blockIdx.x;
    const int c  = ch & (NC_ - 1);
    const int bh = ch >> 6;
    const int b  = bh >> 4;
    const int h  = bh & 15;
    const int t0 = c * C_;
    const int tid = threadIdx.x;
    const size_t base0 = (size_t)b * L_ * D_ + (size_t)h * DH_;

    if (tid < 32) bsm[tid] = beta[((size_t)b * L_ + t0 + tid) * H_ + h];
    for (int i = tid; i < 32 * 32; i += 128) {
        int r = i >> 5, c4 = (i & 31) * 4;
        const size_t g = base0 + (size_t)(t0 + r) * D_ + c4;
        *(float4*)(Kc + r * 128 + c4) = *(const float4*)(k + g);
        *(float4*)(Qc + r * 128 + c4) = *(const float4*)(q + g);
        *(float4*)(X + r * 256 + c4)  = *(const float4*)(v + g);
    }
    __syncthreads();

    {
        const int w = tid >> 5, lane = tid & 31;
#pragma unroll
        for (int r = w * 8; r < w * 8 + 8; r++) {
            float4 kv = *(float4*)(Kc + r * 128 + lane * 4);
            float4 qv = *(float4*)(Qc + r * 128 + lane * 4);
            float sk = kv.x * kv.x + kv.y * kv.y + kv.z * kv.z + kv.w * kv.w;
            float sq = qv.x * qv.x + qv.y * qv.y + qv.z * qv.z + qv.w * qv.w;
#pragma unroll
            for (int off = 16; off; off >>= 1) {
                sk += __shfl_xor_sync(0xffffffffu, sk, off);
                sq += __shfl_xor_sync(0xffffffffu, sq, off);
            }
            float ik = 1.0f / fmaxf(sqrtf(sk), 1e-12f);
            float iq = 0.08838834764831845f / fmaxf(sqrtf(sq), 1e-12f);
            kv.x *= ik; kv.y *= ik; kv.z *= ik; kv.w *= ik;
            qv.x *= iq; qv.y *= iq; qv.z *= iq; qv.w *= iq;
            *(float4*)(Kc + r * 128 + lane * 4) = kv;
            *(float4*)(Qc + r * 128 + lane * 4) = qv;
        }
    }
    __syncthreads();

    for (int i = tid; i < 32 * 32; i += 128) {
        int r = i >> 5, c4 = (i & 31) * 4;
        float bt = bsm[r];
        float4 kv = *(float4*)(Kc + r * 128 + c4);
        kv.x *= bt; kv.y *= bt; kv.z *= bt; kv.w *= bt;
        *(float4*)(X + r * 256 + 128 + c4) = kv;
        float4 vv = *(float4*)(X + r * 256 + c4);
        vv.x *= bt; vv.y *= bt; vv.z *= bt; vv.w *= bt;
        *(float4*)(X + r * 256 + c4) = vv;
    }

    const int i_ = tid >> 2, j0 = (tid & 3) * 8;
    float accA[8], accP[8];
#pragma unroll
    for (int e = 0; e < 8; e++) { accA[e] = 0.f; accP[e] = 0.f; }
    for (int d4 = 0; d4 < 128; d4 += 4) {
        float4 ki = *(const float4*)(Kc + i_ * 128 + d4);
        float4 qi = *(const float4*)(Qc + i_ * 128 + d4);
#pragma unroll
        for (int e = 0; e < 8; e++) {
            float4 kj = *(const float4*)(Kc + (j0 + e) * 128 + d4);
            accA[e] += ki.x * kj.x + ki.y * kj.y + ki.z * kj.z + ki.w * kj.w;
            accP[e] += qi.x * kj.x + qi.y * kj.y + qi.z * kj.z + qi.w * kj.w;
        }
    }
    const float bi = bsm[i_];
#pragma unroll
    for (int e = 0; e < 8; e++) {
        int j = j0 + e;
        Asm[i_ * 32 + j] = (j < i_) ? bi * accA[e] : 0.f;
        float pv = (j <= i_) ? accP[e] : 0.f;
        __nv_bfloat16 phv = __float2bfloat16(pv);
        Ph[(size_t)ch * 1024 + i_ * 32 + j] = phv;
        Pl[(size_t)ch * 1024 + i_ * 32 + j] = __float2bfloat16(pv - __bfloat162float(phv));
    }
    __syncthreads();

    for (int i = 1; i < 32; i++) {
        float f0 = 0.f, f1 = 0.f;
        for (int j = 0; j < i; j++) {
            float a = Asm[i * 32 + j];
            f0 += a * X[j * 256 + tid];
            f1 += a * X[j * 256 + 128 + tid];
        }
        X[i * 256 + tid]       -= f0;
        X[i * 256 + 128 + tid] -= f1;
        __syncthreads();
    }

    for (int i = tid; i < 32 * 128; i += 128) {
        int n = i >> 7, m = i & 127;
        W0g[(size_t)ch * 4096 + i] = X[n * 256 + m];
        float tkv = X[n * 256 + 128 + m];
        __nv_bfloat16 th_ = __float2bfloat16(tkv);
        TKh[(size_t)ch * 4096 + i] = th_;
        TKl[(size_t)ch * 4096 + i] = __float2bfloat16(tkv - __bfloat162float(th_));
        float qv = Qc[n * 128 + m];
        __nv_bfloat16 qh_ = __float2bfloat16(qv);
        Qh[(size_t)ch * 4096 + i] = qh_;
        Ql[(size_t)ch * 4096 + i] = __float2bfloat16(qv - __bfloat162float(qh_));
    }
#pragma unroll
    for (int n = 0; n < 32; n++) {
        float kv = Kc[n * 128 + tid];
        __nv_bfloat16 kh_ = __float2bfloat16(kv);
        KTh[(size_t)ch * 4096 + tid * 32 + n] = kh_;
        KTl[(size_t)ch * 4096 + tid * 32 + n] = __float2bfloat16(kv - __bfloat162float(kh_));
    }
}

// ====== SEQ: sequential chunk chain, dv-split x2 (2 CTAs per (b,h)) =========
// CTA owns 64 of 128 dv columns. S^T [64][128] in MMA accumulators.
#define OS_SHI 0
#define OS_SLO 17408
#define OS_WTH 34816
#define OS_WTL 39936
#define OS_TKH 45056
#define OS_TKL 53760
#define OS_QH  62464
#define OS_QL  71168
#define OS_KTH 79872
#define OS_KTL 90112
#define OS_PH  100352
#define OS_PL  102912
#define OS_W0  105472
#define OS_CS  113664
#define SEQ_SMEM 113792
#define SST 272   // S/TK/Q row stride bytes (128 halves + pad)
#define WST 80    // Wt/KT/P row stride bytes (32 halves + pad)

__global__ void __launch_bounds__(256, 1) seq_chunk(
    const float* __restrict__ W0g,
    const __nv_bfloat16* __restrict__ TKh, const __nv_bfloat16* __restrict__ TKl,
    const __nv_bfloat16* __restrict__ Qh,  const __nv_bfloat16* __restrict__ Ql,
    const __nv_bfloat16* __restrict__ KTh, const __nv_bfloat16* __restrict__ KTl,
    const __nv_bfloat16* __restrict__ Ph,  const __nv_bfloat16* __restrict__ Pl,
    const float* __restrict__ wnorm, float* __restrict__ o,
    float* __restrict__ oss) {
    extern __shared__ char smraw[];
    const int bh  = blockIdx.x >> 1;
    const int dvh = blockIdx.x & 1;          // which 64-wide dv half
    const int b = bh >> 4, h = bh & 15;
    const int tid = threadIdx.x, wid = tid >> 5, lane = tid & 31;
    const uint32_t sb = smem_u32(smraw);
    float* W0s = (float*)(smraw + OS_W0);    // [32 tokens][64 dv]
    float* colsum = (float*)(smraw + OS_CS);

    // zero S hi/lo
    for (int i = tid; i < OS_WTH / 16; i += 256)
        ((uint4*)smraw)[i] = make_uint4(0, 0, 0, 0);

    float Sfr[2][4][4];                      // [mi dv16][ni dk8]
#pragma unroll
    for (int mi = 0; mi < 2; mi++)
#pragma unroll
        for (int ni = 0; ni < 4; ni++)
#pragma unroll
            for (int e = 0; e < 4; e++) Sfr[mi][ni][e] = 0.f;

    const int wm   = (wid & 1) * 32;         // dv offset within 64
    const int tg   = wid >> 1;               // 0..3
    const int wn8  = tg * 8;                 // token group (steps 1/2)
    const int wn32 = tg * 32;                // dk group (step 3)
    const int a_r = lane & 15, a_cB = (lane >> 4) << 4;
    const int b_r = lane & 7,  b_cB = ((lane >> 3) & 1) << 4;
    const int fr = lane >> 2, fc = (lane & 3) * 2;

    float wnr[2][2];
#pragma unroll
    for (int mi = 0; mi < 2; mi++)
#pragma unroll
        for (int pp = 0; pp < 2; pp++)
            wnr[mi][pp] = wnorm[dvh * 64 + wm + mi * 16 + pp * 8 + fr];

    for (int c = 0; c < NC_; c++) {
        const size_t ch = (size_t)bh * NC_ + c;
        __syncthreads();

        // ---- load chunk operands ----
        {
            const uint4* gtkh = (const uint4*)(TKh + ch * 4096);
            const uint4* gtkl = (const uint4*)(TKl + ch * 4096);
            const uint4* gqh  = (const uint4*)(Qh + ch * 4096);
            const uint4* gql  = (const uint4*)(Ql + ch * 4096);
            for (int i = tid; i < 512; i += 256) {
                int r = i >> 4, qq = (i & 15) * 16;
                *(uint4*)(smraw + OS_TKH + r * SST + qq) = gtkh[i];
                *(uint4*)(smraw + OS_TKL + r * SST + qq) = gtkl[i];
                *(uint4*)(smraw + OS_QH + r * SST + qq) = gqh[i];
                *(uint4*)(smraw + OS_QL + r * SST + qq) = gql[i];
            }
            const uint4* gkth = (const uint4*)(KTh + ch * 4096);
            const uint4* gktl = (const uint4*)(KTl + ch * 4096);
            for (int i = tid; i < 512; i += 256) {
                int r = i >> 2, qq = (i & 3) * 16;
                *(uint4*)(smraw + OS_KTH + r * WST + qq) = gkth[i];
                *(uint4*)(smraw + OS_KTL + r * WST + qq) = gktl[i];
            }
            const uint4* gph = (const uint4*)(Ph + ch * 1024);
            const uint4* gpl = (const uint4*)(Pl + ch * 1024);
            if (tid < 128) {
                int r = tid >> 2, qq = (tid & 3) * 16;
                *(uint4*)(smraw + OS_PH + r * WST + qq) = gph[tid];
                *(uint4*)(smraw + OS_PL + r * WST + qq) = gpl[tid];
            }
            // W0 half: rows 32 tokens x 64 dv (columns dvh*64..)
            const float4* gw0 = (const float4*)(W0g + ch * 4096);
            for (int i = tid; i < 512; i += 256) {
                int r = i >> 4, qq = i & 15;
                *(float4*)(smraw + OS_W0 + r * 256 + qq * 16) = gw0[r * 32 + dvh * 16 + qq];
            }
            if (tid < 32) colsum[tid] = 0.f;
        }
        __syncthreads();

        // ---- step 1: Wt = W0^T - Ssm @ TK^T  (m=dv 32/warp, n=8 tokens) ----
        float acc[2][4];
#pragma unroll
        for (int mi = 0; mi < 2; mi++)
#pragma unroll
            for (int e = 0; e < 4; e++) acc[mi][e] = 0.f;
#pragma unroll
        for (int ks = 0; ks < 8; ks++) {
            uint32_t ah[2][4], al[2][4], bhf[2], blf[2];
#pragma unroll
            for (int mi = 0; mi < 2; mi++) {
                uint32_t off = (wm + mi * 16 + a_r) * SST + a_cB + ks * 32;
                LDSM_X4(ah[mi][0], ah[mi][1], ah[mi][2], ah[mi][3], sb + OS_SHI + off);
                LDSM_X4(al[mi][0], al[mi][1], al[mi][2], al[mi][3], sb + OS_SLO + off);
            }
            {
                uint32_t off = (wn8 + b_r) * SST + b_cB + ks * 32;
                LDSM_X2(bhf[0], bhf[1], sb + OS_TKH + off);
                LDSM_X2(blf[0], blf[1], sb + OS_TKL + off);
            }
#pragma unroll
            for (int mi = 0; mi < 2; mi++) {
                mma_bf16(acc[mi], ah[mi], bhf);
                mma_bf16(acc[mi], ah[mi], blf);
                mma_bf16(acc[mi], al[mi], bhf);
            }
        }
#pragma unroll
        for (int mi = 0; mi < 2; mi++)
#pragma unroll
            for (int pp = 0; pp < 2; pp++) {
                int m = wm + mi * 16 + fr + pp * 8;   // dv 0..63
                int n0 = wn8 + fc;                    // token
                float v0 = W0s[n0 * 64 + m] - acc[mi][pp * 2 + 0];
                float v1 = W0s[(n0 + 1) * 64 + m] - acc[mi][pp * 2 + 1];
                uint32_t lo, hi = pack_split(v0, v1, lo);
                *(uint32_t*)(smraw + OS_WTH + m * WST + n0 * 2) = hi;
                *(uint32_t*)(smraw + OS_WTL + m * WST + n0 * 2) = lo;
            }
        __syncthreads();

        // ---- step 2: Ot = Ssm @ Q^T + Wt @ P^T ----
        float oacc[2][4];
#pragma unroll
        for (int mi = 0; mi < 2; mi++)
#pragma unroll
            for (int e = 0; e < 4; e++) oacc[mi][e] = 0.f;
#pragma unroll
        for (int ks = 0; ks < 8; ks++) {
            uint32_t ah[2][4], al[2][4], bhf[2], blf[2];
#pragma unroll
            for (int mi = 0; mi < 2; mi++) {
                uint32_t off = (wm + mi * 16 + a_r) * SST + a_cB + ks * 32;
                LDSM_X4(ah[mi][0], ah[mi][1], ah[mi][2], ah[mi][3], sb + OS_SHI + off);
                LDSM_X4(al[mi][0], al[mi][1], al[mi][2], al[mi][3], sb + OS_SLO + off);
            }
            {
                uint32_t off = (wn8 + b_r) * SST + b_cB + ks * 32;
                LDSM_X2(bhf[0], bhf[1], sb + OS_QH + off);
                LDSM_X2(blf[0], blf[1], sb + OS_QL + off);
            }
#pragma unroll
            for (int mi = 0; mi < 2; mi++) {
                mma_bf16(oacc[mi], ah[mi], bhf);
                mma_bf16(oacc[mi], ah[mi], blf);
                mma_bf16(oacc[mi], al[mi], bhf);
            }
        }
#pragma unroll
        for (int ks = 0; ks < 2; ks++) {
            uint32_t ah[2][4], al[2][4], bhf[2], blf[2];
#pragma unroll
            for (int mi = 0; mi < 2; mi++) {
                uint32_t off = (wm + mi * 16 + a_r) * WST + a_cB + ks * 32;
                LDSM_X4(ah[mi][0], ah[mi][1], ah[mi][2], ah[mi][3], sb + OS_WTH + off);
                LDSM_X4(al[mi][0], al[mi][1], al[mi][2], al[mi][3], sb + OS_WTL + off);
            }
            {
                uint32_t off = (wn8 + b_r) * WST + b_cB + ks * 32;
                LDSM_X2(bhf[0], bhf[1], sb + OS_PH + off);
                LDSM_X2(blf[0], blf[1], sb + OS_PL + off);
            }
#pragma unroll
            for (int mi = 0; mi < 2; mi++) {
                mma_bf16(oacc[mi], ah[mi], bhf);
                mma_bf16(oacc[mi], ah[mi], blf);
                mma_bf16(oacc[mi], al[mi], bhf);
            }
        }
        // partial sumsq over this CTA's 64 dv
        {
            float s0 = oacc[0][0] * oacc[0][0] + oacc[0][2] * oacc[0][2]
                     + oacc[1][0] * oacc[1][0] + oacc[1][2] * oacc[1][2];
            float s1 = oacc[0][1] * oacc[0][1] + oacc[0][3] * oacc[0][3]
                     + oacc[1][1] * oacc[1][1] + oacc[1][3] * oacc[1][3];
#pragma unroll
            for (int off = 4; off <= 16; off <<= 1) {
                s0 += __shfl_xor_sync(0xffffffffu, s0, off);
                s1 += __shfl_xor_sync(0xffffffffu, s1, off);
            }
            if (lane < 4) {
                atomicAdd(&colsum[wn8 + 2 * lane], s0);
                atomicAdd(&colsum[wn8 + 2 * lane + 1], s1);
            }
        }
        __syncthreads();

        // store o (unnormalized * wn) + publish partial sumsq
        {
            const size_t obase = (size_t)b * L_ * D_ + (size_t)h * DH_ + (size_t)(c * C_) * D_
                               + dvh * 64;
            int n0 = wn8 + fc;
#pragma unroll
            for (int mi = 0; mi < 2; mi++)
#pragma unroll
                for (int pp = 0; pp < 2; pp++) {
                    int m = wm + mi * 16 + fr + pp * 8;
                    o[obase + (size_t)n0 * D_ + m] = oacc[mi][pp * 2] * wnr[mi][pp];
                    o[obase + (size_t)(n0 + 1) * D_ + m] = oacc[mi][pp * 2 + 1] * wnr[mi][pp];
                }
            if (tid < 32)
                oss[(size_t)dvh * (M_ * H_) + ((size_t)b * L_ + c * C_ + tid) * H_ + h] = colsum[tid];
        }

        // ---- step 3: Ssm += Wt @ K  (n = dk, 32/warp) ----
#pragma unroll
        for (int ks = 0; ks < 2; ks++) {
            uint32_t ah[2][4], al[2][4];
#pragma unroll
            for (int mi = 0; mi < 2; mi++) {
                uint32_t off = (wm + mi * 16 + a_r) * WST + a_cB + ks * 32;
                LDSM_X4(ah[mi][0], ah[mi][1], ah[mi][2], ah[mi][3], sb + OS_WTH + off);
                LDSM_X4(al[mi][0], al[mi][1], al[mi][2], al[mi][3], sb + OS_WTL + off);
            }
#pragma unroll
            for (int ni = 0; ni < 4; ni++) {
                uint32_t bhf[2], blf[2];
                uint32_t off = (wn32 + ni * 8 + b_r) * WST + b_cB + ks * 32;
                LDSM_X2(bhf[0], bhf[1], sb + OS_KTH + off);
                LDSM_X2(blf[0], blf[1], sb + OS_KTL + off);
#pragma unroll
                for (int mi = 0; mi < 2; mi++) {
                    mma_bf16(Sfr[mi][ni], ah[mi], bhf);
                    mma_bf16(Sfr[mi][ni], ah[mi], blf);
                    mma_bf16(Sfr[mi][ni], al[mi], bhf);
                }
            }
        }
#pragma unroll
        for (int mi = 0; mi < 2; mi++)
#pragma unroll
            for (int ni = 0; ni < 4; ni++)
#pragma unroll
                for (int pp = 0; pp < 2; pp++) {
                    int m = wm + mi * 16 + fr + pp * 8;
                    int n0 = wn32 + ni * 8 + fc;
                    uint32_t lo, hi = pack_split(Sfr[mi][ni][pp * 2], Sfr[mi][ni][pp * 2 + 1], lo);
                    *(uint32_t*)(smraw + OS_SHI + m * SST + n0 * 2) = hi;
                    *(uint32_t*)(smraw + OS_SLO + m * SST + n0 * 2) = lo;
                }
    }
}

// ================= launch =================
extern "C" void kernel_launch(void* const* d_in, const int* in_sizes, int n_in,
                              void* d_out, int out_size) {
    const float* X  = (const float*)d_in[0];
    const float* Wq = (const float*)d_in[1];
    const float* Wk = (const float*)d_in[2];
    const float* Wv = (const float*)d_in[3];
    const float* Wb = (const float*)d_in[4];
    const float* wn = (const float*)d_in[5];
    const float* Wo = (const float*)d_in[6];
    float* out = (float*)d_out;

    float *gq, *gk, *gv, *go, *gb, *gW0, *gss;
    __half *ahi, *alo, *wt;
    __nv_bfloat16 *tkh, *tkl, *qch, *qcl, *kth, *ktl, *ph, *pl;
    cudaGetSymbolAddress((void**)&gq, g_q);
    cudaGetSymbolAddress((void**)&gk, g_k);
    cudaGetSymbolAddress((void**)&gv, g_v);
    cudaGetSymbolAddress((void**)&go, g_o);
    cudaGetSymbolAddress((void**)&gb, g_beta);
    cudaGetSymbolAddress((void**)&gss, g_ss);
    cudaGetSymbolAddress((void**)&ahi, g_Ahi);
    cudaGetSymbolAddress((void**)&alo, g_Alo);
    cudaGetSymbolAddress((void**)&wt, g_Wt);
    cudaGetSymbolAddress((void**)&gW0, g_W0);
    cudaGetSymbolAddress((void**)&tkh, g_TKh);
    cudaGetSymbolAddress((void**)&tkl, g_TKl);
    cudaGetSymbolAddress((void**)&qch, g_Qch);
    cudaGetSymbolAddress((void**)&qcl, g_Qcl);
    cudaGetSymbolAddress((void**)&kth, g_KTh);
    cudaGetSymbolAddress((void**)&ktl, g_KTl);
    cudaGetSymbolAddress((void**)&ph, g_Ph);
    cudaGetSymbolAddress((void**)&pl, g_Pl);

    cudaFuncSetAttribute(gemm_f16split, cudaFuncAttributeMaxDynamicSharedMemorySize, SMEM_DYN);
    cudaFuncSetAttribute(pre_chunk, cudaFuncAttributeMaxDynamicSharedMemorySize, 69760);
    cudaFuncSetAttribute(seq_chunk, cudaFuncAttributeMaxDynamicSharedMemorySize, SEQ_SMEM);

    const int NSPLIT = M_ * D_ / 4 / 256;

    split_rows<<<NSPLIT, 256>>>((const float4*)X, (uint2*)ahi, (uint2*)alo);
    split_transpose<<<dim3(D_ / 32, D_ / 32, 4), dim3(32, 8)>>>(Wq, Wk, Wv, Wo, wt);

    GemmArgs qa;
    qa.Bw[0] = wt;
    qa.Bw[1] = wt + (size_t)D_ * D_;
    qa.Bw[2] = wt + (size_t)2 * D_ * D_;
    qa.C[0] = gq; qa.C[1] = gk; qa.C[2] = gv;
    qa.mode[0] = 0; qa.mode[1] = 0; qa.mode[2] = 1;
    gemm_f16split<<<dim3(D_ / BN, M_ / BM, 3), 256, SMEM_DYN>>>(ahi, alo, qa);

    beta_gemm<<<M_ / 16, 256>>>(X, Wb, gb);

    pre_chunk<<<NCH_, 128, 69760>>>(gq, gk, gv, gb, gW0, tkh, tkl, qch, qcl, kth, ktl, ph, pl);
    seq_chunk<<<2 * B_ * H_, 256, SEQ_SMEM>>>(gW0, tkh, tkl, qch, qcl, kth, ktl, ph, pl, wn, go, gss);

    split_rows_norm<<<NSPLIT, 256>>>((const float4*)go, (uint2*)ahi, (uint2*)alo, gss);
    GemmArgs oa;
    oa.Bw[0] = wt + (size_t)3 * D_ * D_;
    oa.Bw[1] = oa.Bw[0];
    oa.Bw[2] = oa.Bw[0];
    oa.C[0] = out; oa.C[1] = out; oa.C[2] = out;
    oa.mode[0] = 0; oa.mode[1] = 0; oa.mode[2] = 0;
    gemm_f16split<<<dim3(D_ / BN, M_ / BM, 1), 256, SMEM_DYN>>>(ahi, alo, oa);
}

// round 9
// speedup vs baseline: 4.1274x; 1.1939x over previous
#include <cuda_runtime.h>
#include <cuda_bf16.h>
#include <cuda_fp16.h>
#include <math.h>
#include <stdint.h>

#define B_  2
#define L_  2048
#define D_  2048
#define H_  16
#define DH_ 128
#define M_  (B_ * L_)   // 4096
#define C_  32          // chunk length
#define NC_ (L_ / C_)   // 64 chunks per (b,h)
#define NCH_ (B_ * H_ * NC_)  // 2048 chunk-heads

// ================= scratch (device globals; no allocations) =================
__device__ float g_q[M_ * D_];
__device__ float g_k[M_ * D_];
__device__ float g_v[M_ * D_];
__device__ float g_o[M_ * D_];
__device__ float g_beta[M_ * H_];
__device__ float g_ss[4 * M_ * H_];      // partial sumsq per dv-quarter
__device__ __half g_Ahi[M_ * D_];        // fp16 hi/lo split of GEMM A operand
__device__ __half g_Alo[M_ * D_];
__device__ __half g_Wt[4 * D_ * D_];     // transposed weights [N,K] fp16, order q,k,v,o
// chunked delta-rule precompute (bf16 3-combo)
__device__ float g_W0[NCH_ * C_ * DH_];
__device__ __nv_bfloat16 g_TKh[NCH_ * C_ * DH_];
__device__ __nv_bfloat16 g_TKl[NCH_ * C_ * DH_];
__device__ __nv_bfloat16 g_Qch[NCH_ * C_ * DH_];
__device__ __nv_bfloat16 g_Qcl[NCH_ * C_ * DH_];
__device__ __nv_bfloat16 g_KTh[NCH_ * DH_ * C_];
__device__ __nv_bfloat16 g_KTl[NCH_ * DH_ * C_];
__device__ __nv_bfloat16 g_Ph[NCH_ * C_ * C_];
__device__ __nv_bfloat16 g_Pl[NCH_ * C_ * C_];

// ================= helpers =================
__device__ __forceinline__ uint32_t smem_u32(const void* p) {
    uint32_t a;
    asm("{ .reg .u64 t; cvta.to.shared.u64 t, %1; cvt.u32.u64 %0, t; }" : "=r"(a) : "l"(p));
    return a;
}
__device__ __forceinline__ void cp16(uint32_t dst, const void* src) {
    asm volatile("cp.async.cg.shared.global [%0], [%1], 16;" :: "r"(dst), "l"(src));
}
#define CP_COMMIT() asm volatile("cp.async.commit_group;" ::: "memory")
#define CP_WAIT(n)  asm volatile("cp.async.wait_group %0;" :: "n"(n) : "memory")

#define LDSM_X4(r0, r1, r2, r3, addr)                                            \
    asm volatile("ldmatrix.sync.aligned.m8n8.x4.shared.b16 {%0,%1,%2,%3}, [%4];" \
        : "=r"(r0), "=r"(r1), "=r"(r2), "=r"(r3) : "r"(addr))
#define LDSM_X2(r0, r1, addr)                                                    \
    asm volatile("ldmatrix.sync.aligned.m8n8.x2.shared.b16 {%0,%1}, [%2];"       \
        : "=r"(r0), "=r"(r1) : "r"(addr))

__device__ __forceinline__ void mma_bf16(float* d, const uint32_t* a, const uint32_t* b) {
    asm volatile(
        "mma.sync.aligned.m16n8k16.row.col.f32.bf16.bf16.f32 "
        "{%0,%1,%2,%3}, {%4,%5,%6,%7}, {%8,%9}, {%0,%1,%2,%3};"
        : "+f"(d[0]), "+f"(d[1]), "+f"(d[2]), "+f"(d[3])
        : "r"(a[0]), "r"(a[1]), "r"(a[2]), "r"(a[3]), "r"(b[0]), "r"(b[1]));
}
__device__ __forceinline__ void mma_f16(float* d, const uint32_t* a, const uint32_t* b) {
    asm volatile(
        "mma.sync.aligned.m16n8k16.row.col.f32.f16.f16.f32 "
        "{%0,%1,%2,%3}, {%4,%5,%6,%7}, {%8,%9}, {%0,%1,%2,%3};"
        : "+f"(d[0]), "+f"(d[1]), "+f"(d[2]), "+f"(d[3])
        : "r"(a[0]), "r"(a[1]), "r"(a[2]), "r"(a[3]), "r"(b[0]), "r"(b[1]));
}
__device__ __forceinline__ uint32_t pack_split(float v0, float v1, uint32_t& lo) {
    __nv_bfloat16 h0 = __float2bfloat16(v0), h1 = __float2bfloat16(v1);
    __nv_bfloat16 l0 = __float2bfloat16(v0 - __bfloat162float(h0));
    __nv_bfloat16 l1 = __float2bfloat16(v1 - __bfloat162float(h1));
    lo = ((uint32_t)__bfloat16_as_ushort(l1) << 16) | __bfloat16_as_ushort(l0);
    return ((uint32_t)__bfloat16_as_ushort(h1) << 16) | __bfloat16_as_ushort(h0);
}

// ================= split fp32 -> fp16 hi/lo =================
__global__ void __launch_bounds__(256) split_rows(const float4* __restrict__ X,
                                                  uint2* __restrict__ hi,
                                                  uint2* __restrict__ lo) {
    int i = blockIdx.x * 256 + threadIdx.x;
    float4 x = X[i];
    __half h0 = __float2half_rn(x.x), h1 = __float2half_rn(x.y);
    __half h2 = __float2half_rn(x.z), h3 = __float2half_rn(x.w);
    __half l0 = __float2half_rn(x.x - __half2float(h0));
    __half l1 = __float2half_rn(x.y - __half2float(h1));
    __half l2 = __float2half_rn(x.z - __half2float(h2));
    __half l3 = __float2half_rn(x.w - __half2float(h3));
    uint2 hv, lv;
    hv.x = ((uint32_t)__half_as_ushort(h1) << 16) | __half_as_ushort(h0);
    hv.y = ((uint32_t)__half_as_ushort(h3) << 16) | __half_as_ushort(h2);
    lv.x = ((uint32_t)__half_as_ushort(l1) << 16) | __half_as_ushort(l0);
    lv.y = ((uint32_t)__half_as_ushort(l3) << 16) | __half_as_ushort(l2);
    hi[i] = hv;
    lo[i] = lv;
}

// split + deferred RMSNorm scale (for o): x *= rsqrt(mean(ss)+eps)
__global__ void __launch_bounds__(256) split_rows_norm(const float4* __restrict__ X,
                                                       uint2* __restrict__ hi,
                                                       uint2* __restrict__ lo,
                                                       const float* __restrict__ ss) {
    int i = blockIdx.x * 256 + threadIdx.x;
    int m = i >> 9;
    int h = (i & 511) >> 5;
    size_t idx = (size_t)m * H_ + h;
    float s = ss[idx] + ss[(size_t)M_ * H_ + idx]
            + ss[(size_t)2 * M_ * H_ + idx] + ss[(size_t)3 * M_ * H_ + idx];
    float r = rsqrtf(s * (1.0f / 128.0f) + 1e-5f);
    float4 x = X[i];
    x.x *= r; x.y *= r; x.z *= r; x.w *= r;
    __half h0 = __float2half_rn(x.x), h1 = __float2half_rn(x.y);
    __half h2 = __float2half_rn(x.z), h3 = __float2half_rn(x.w);
    __half l0 = __float2half_rn(x.x - __half2float(h0));
    __half l1 = __float2half_rn(x.y - __half2float(h1));
    __half l2 = __float2half_rn(x.z - __half2float(h2));
    __half l3 = __float2half_rn(x.w - __half2float(h3));
    uint2 hv, lv;
    hv.x = ((uint32_t)__half_as_ushort(h1) << 16) | __half_as_ushort(h0);
    hv.y = ((uint32_t)__half_as_ushort(h3) << 16) | __half_as_ushort(h2);
    lv.x = ((uint32_t)__half_as_ushort(l1) << 16) | __half_as_ushort(l0);
    lv.y = ((uint32_t)__half_as_ushort(l3) << 16) | __half_as_ushort(l2);
    hi[i] = hv;
    lo[i] = lv;
}

// transpose weights: W[k][n] fp32 -> Wt[n][k] fp16 (grid.z selects matrix)
__global__ void __launch_bounds__(256) split_transpose(
    const float* __restrict__ W0, const float* __restrict__ W1,
    const float* __restrict__ W2, const float* __restrict__ W3,
    __half* __restrict__ wt) {
    __shared__ float t[32][33];
    const float* W = (blockIdx.z == 0) ? W0 : (blockIdx.z == 1) ? W1
                   : (blockIdx.z == 2) ? W2 : W3;
    __half* ho = wt + (size_t)blockIdx.z * D_ * D_;
    const int n = blockIdx.x * 32 + threadIdx.x;
    const int k0 = blockIdx.y * 32;
#pragma unroll
    for (int i = threadIdx.y; i < 32; i += 8)
        t[i][threadIdx.x] = W[(size_t)(k0 + i) * D_ + n];
    __syncthreads();
#pragma unroll
    for (int i = threadIdx.y; i < 32; i += 8) {
        const int nn = blockIdx.x * 32 + i;
        ho[(size_t)nn * D_ + k0 + threadIdx.x] = __float2half_rn(t[threadIdx.x][i]);
    }
}

// ====== fp16 2-combo GEMM: 3-stage, 2 CTAs/SM, hi/lo sweeps separated =======
#define BM 128
#define BN 128
#define BK 32
#define LDS_ 40
#define TILE_B (128 * LDS_ * 2)
#define STAGE_B (3 * TILE_B)
#define NSTAGE 3
#define SMEM_DYN (NSTAGE * STAGE_B)
#define NCHUNK (D_ / BK)

struct GemmArgs {
    const __half* Bw[3];
    float* C[3];
    int mode[3];
};

__device__ __forceinline__ void load_chunk(uint32_t sbase, int stage,
    const __half* Ahi, const __half* Alo, const __half* Bw,
    int m0, int n0, int kc, int tid) {
    const int r  = tid >> 1;
    const int c0 = (tid & 1) * 2;
    const uint32_t st = sbase + stage * STAGE_B;
    const size_t koff = (size_t)kc * BK;
    const __half* srcs[3] = {
        Ahi + (size_t)(m0 + r) * D_ + koff,
        Alo + (size_t)(m0 + r) * D_ + koff,
        Bw  + (size_t)(n0 + r) * D_ + koff };
#pragma unroll
    for (int t = 0; t < 3; t++) {
        uint32_t rowb = st + t * TILE_B + r * (LDS_ * 2);
        cp16(rowb + (c0 + 0) * 16, srcs[t] + (c0 + 0) * 8);
        cp16(rowb + (c0 + 1) * 16, srcs[t] + (c0 + 1) * 8);
    }
    CP_COMMIT();
}

__global__ void __launch_bounds__(256, 2) gemm_f16split(
    const __half* __restrict__ Ahi, const __half* __restrict__ Alo,
    GemmArgs args) {
    extern __shared__ char smem_raw[];
    const int z = blockIdx.z;
    const __half* Bw = args.Bw[z];
    float* C = args.C[z];
    const int mode = args.mode[z];

    const int m0 = blockIdx.y * BM;
    const int n0 = blockIdx.x * BN;
    const int tid = threadIdx.x;
    const int wid = tid >> 5;
    const int lane = tid & 31;
    const int wm = (wid & 1) * 64;
    const int wn = (wid >> 1) * 32;
    const uint32_t sbase = smem_u32(smem_raw);

    const uint32_t a_row  = wm + (lane & 15);
    const uint32_t a_colb = ((lane >> 4) << 4);
    const uint32_t b_row  = wn + (lane & 7);
    const uint32_t b_colb = (((lane >> 3) & 1) << 4);

    float acc[4][4][4];
#pragma unroll
    for (int mi = 0; mi < 4; mi++)
#pragma unroll
        for (int ni = 0; ni < 4; ni++)
#pragma unroll
            for (int t = 0; t < 4; t++) acc[mi][ni][t] = 0.f;

    load_chunk(sbase, 0, Ahi, Alo, Bw, m0, n0, 0, tid);
    load_chunk(sbase, 1, Ahi, Alo, Bw, m0, n0, 1, tid);

    for (int c = 0; c < NCHUNK; c++) {
        CP_WAIT(1);
        __syncthreads();
        if (c + 2 < NCHUNK) {
            int s = (c + 2) % NSTAGE;
            load_chunk(sbase, s, Ahi, Alo, Bw, m0, n0, c + 2, tid);
        } else {
            CP_COMMIT();
        }

        const uint32_t st  = sbase + (c % NSTAGE) * STAGE_B;
        const uint32_t tAh = st;
        const uint32_t tAl = st + TILE_B;
        const uint32_t tB  = st + 2 * TILE_B;

#pragma unroll
        for (int ks = 0; ks < 2; ks++) {
            const uint32_t kb = ks * 32;
            uint32_t ah[4][4], al[4][4], bf[4][2];
#pragma unroll
            for (int mi = 0; mi < 4; mi++) {
                uint32_t off = (a_row + mi * 16) * (LDS_ * 2) + a_colb + kb;
                LDSM_X4(ah[mi][0], ah[mi][1], ah[mi][2], ah[mi][3], tAh + off);
                LDSM_X4(al[mi][0], al[mi][1], al[mi][2], al[mi][3], tAl + off);
            }
#pragma unroll
            for (int ni = 0; ni < 4; ni++) {
                uint32_t off = (b_row + ni * 8) * (LDS_ * 2) + b_colb + kb;
                LDSM_X2(bf[ni][0], bf[ni][1], tB + off);
            }
#pragma unroll
            for (int mi = 0; mi < 4; mi++)
#pragma unroll
                for (int ni = 0; ni < 4; ni++)
                    mma_f16(acc[mi][ni], ah[mi], bf[ni]);
#pragma unroll
            for (int mi = 0; mi < 4; mi++)
#pragma unroll
                for (int ni = 0; ni < 4; ni++)
                    mma_f16(acc[mi][ni], al[mi], bf[ni]);
        }
    }

    const int orow = m0 + wm + (lane >> 2);
    const int ocol = n0 + wn + 2 * (lane & 3);
#pragma unroll
    for (int mi = 0; mi < 4; mi++)
#pragma unroll
        for (int ni = 0; ni < 4; ni++) {
            float v0 = acc[mi][ni][0], v1 = acc[mi][ni][1];
            float v2 = acc[mi][ni][2], v3 = acc[mi][ni][3];
            if (mode == 1) {
                v0 = v0 / (1.f + expf(-v0));
                v1 = v1 / (1.f + expf(-v1));
                v2 = v2 / (1.f + expf(-v2));
                v3 = v3 / (1.f + expf(-v3));
            }
            float* p0 = C + (size_t)(orow + mi * 16) * D_ + ocol + ni * 8;
            float* p1 = C + (size_t)(orow + mi * 16 + 8) * D_ + ocol + ni * 8;
            *(float2*)p0 = make_float2(v0, v1);
            *(float2*)p1 = make_float2(v2, v3);
        }
}

// ========== beta projection: cp.async double-buffered tiled GEMM ===========
__global__ void __launch_bounds__(256) beta_gemm(const float* __restrict__ X,
                                                 const float* __restrict__ Wb,
                                                 float* __restrict__ beta) {
    __shared__ float Xs[2][16][132];
    __shared__ float Ws[2][128][16];
    const int m0 = blockIdx.x * 16;
    const int tid = threadIdx.x;
    const int row = tid >> 4, n = tid & 15;
    const uint32_t xb = smem_u32(&Xs[0][0][0]);
    const uint32_t wb = smem_u32(&Ws[0][0][0]);

    auto load_tile = [&](int buf, int kt) {
        const uint32_t xs = xb + buf * (16 * 132 * 4);
        const uint32_t ws = wb + buf * (128 * 16 * 4);
#pragma unroll
        for (int i = tid; i < 512; i += 256) {
            int r = i >> 5, c16 = i & 31;
            cp16(xs + r * 528 + c16 * 16, X + (size_t)(m0 + r) * D_ + kt + c16 * 4);
        }
#pragma unroll
        for (int i = tid; i < 512; i += 256) {
            int r = i >> 2, cc = i & 3;
            cp16(ws + r * 64 + cc * 16, Wb + (size_t)(kt + r) * H_ + cc * 4);
        }
        CP_COMMIT();
    };

    float acc = 0.f;
    load_tile(0, 0);
    for (int t = 0; t < 16; t++) {
        if (t + 1 < 16) load_tile((t + 1) & 1, (t + 1) * 128);
        else            CP_COMMIT();
        CP_WAIT(1);
        __syncthreads();
        const int buf = t & 1;
#pragma unroll 16
        for (int k = 0; k < 128; k++) acc += Xs[buf][row][k] * Ws[buf][k][n];
        __syncthreads();
    }
    beta[(size_t)(m0 + row) * H_ + n] = 1.f / (1.f + expf(-acc));
}

// ================= PRE: l2norm fused + per-chunk WY precompute ==============
__global__ void __launch_bounds__(128) pre_chunk(
    const float* __restrict__ q, const float* __restrict__ k,
    const float* __restrict__ v, const float* __restrict__ beta,
    float* __restrict__ W0g,
    __nv_bfloat16* __restrict__ TKh, __nv_bfloat16* __restrict__ TKl,
    __nv_bfloat16* __restrict__ Qh,  __nv_bfloat16* __restrict__ Ql,
    __nv_bfloat16* __restrict__ KTh, __nv_bfloat16* __restrict__ KTl,
    __nv_bfloat16* __restrict__ Ph,  __nv_bfloat16* __restrict__ Pl) {
    extern __shared__ float sm[];
    float* Kc  = sm;               // [32][128]
    float* Qc  = Kc + 32 * 128;    // [32][128]
    float* X   = Qc + 32 * 128;    // [32][256]  [bV | bK]
    float* Asm = X + 32 * 256;     // [32][32]
    float* bsm = Asm + 32 * 32;    // [32]

    const int ch = blockIdx.x;
    const int c  = ch & (NC_ - 1);
    const int bh = ch >> 6;
    const int b  = bh >> 4;
    const int h  = bh & 15;
    const int t0 = c * C_;
    const int tid = threadIdx.x;
    const size_t base0 = (size_t)b * L_ * D_ + (size_t)h * DH_;

    if (tid < 32) bsm[tid] = beta[((size_t)b * L_ + t0 + tid) * H_ + h];
    for (int i = tid; i < 32 * 32; i += 128) {
        int r = i >> 5, c4 = (i & 31) * 4;
        const size_t g = base0 + (size_t)(t0 + r) * D_ + c4;
        *(float4*)(Kc + r * 128 + c4) = *(const float4*)(k + g);
        *(float4*)(Qc + r * 128 + c4) = *(const float4*)(q + g);
        *(float4*)(X + r * 256 + c4)  = *(const float4*)(v + g);
    }
    __syncthreads();

    {
        const int w = tid >> 5, lane = tid & 31;
#pragma unroll
        for (int r = w * 8; r < w * 8 + 8; r++) {
            float4 kv = *(float4*)(Kc + r * 128 + lane * 4);
            float4 qv = *(float4*)(Qc + r * 128 + lane * 4);
            float sk = kv.x * kv.x + kv.y * kv.y + kv.z * kv.z + kv.w * kv.w;
            float sq = qv.x * qv.x + qv.y * qv.y + qv.z * qv.z + qv.w * qv.w;
#pragma unroll
            for (int off = 16; off; off >>= 1) {
                sk += __shfl_xor_sync(0xffffffffu, sk, off);
                sq += __shfl_xor_sync(0xffffffffu, sq, off);
            }
            float ik = 1.0f / fmaxf(sqrtf(sk), 1e-12f);
            float iq = 0.08838834764831845f / fmaxf(sqrtf(sq), 1e-12f);
            kv.x *= ik; kv.y *= ik; kv.z *= ik; kv.w *= ik;
            qv.x *= iq; qv.y *= iq; qv.z *= iq; qv.w *= iq;
            *(float4*)(Kc + r * 128 + lane * 4) = kv;
            *(float4*)(Qc + r * 128 + lane * 4) = qv;
        }
    }
    __syncthreads();

    for (int i = tid; i < 32 * 32; i += 128) {
        int r = i >> 5, c4 = (i & 31) * 4;
        float bt = bsm[r];
        float4 kv = *(float4*)(Kc + r * 128 + c4);
        kv.x *= bt; kv.y *= bt; kv.z *= bt; kv.w *= bt;
        *(float4*)(X + r * 256 + 128 + c4) = kv;
        float4 vv = *(float4*)(X + r * 256 + c4);
        vv.x *= bt; vv.y *= bt; vv.z *= bt; vv.w *= bt;
        *(float4*)(X + r * 256 + c4) = vv;
    }

    const int i_ = tid >> 2, j0 = (tid & 3) * 8;
    float accA[8], accP[8];
#pragma unroll
    for (int e = 0; e < 8; e++) { accA[e] = 0.f; accP[e] = 0.f; }
    for (int d4 = 0; d4 < 128; d4 += 4) {
        float4 ki = *(const float4*)(Kc + i_ * 128 + d4);
        float4 qi = *(const float4*)(Qc + i_ * 128 + d4);
#pragma unroll
        for (int e = 0; e < 8; e++) {
            float4 kj = *(const float4*)(Kc + (j0 + e) * 128 + d4);
            accA[e] += ki.x * kj.x + ki.y * kj.y + ki.z * kj.z + ki.w * kj.w;
            accP[e] += qi.x * kj.x + qi.y * kj.y + qi.z * kj.z + qi.w * kj.w;
        }
    }
    const float bi = bsm[i_];
#pragma unroll
    for (int e = 0; e < 8; e++) {
        int j = j0 + e;
        Asm[i_ * 32 + j] = (j < i_) ? bi * accA[e] : 0.f;
        float pv = (j <= i_) ? accP[e] : 0.f;
        __nv_bfloat16 phv = __float2bfloat16(pv);
        Ph[(size_t)ch * 1024 + i_ * 32 + j] = phv;
        Pl[(size_t)ch * 1024 + i_ * 32 + j] = __float2bfloat16(pv - __bfloat162float(phv));
    }
    __syncthreads();

    for (int i = 1; i < 32; i++) {
        float f0 = 0.f, f1 = 0.f;
        for (int j = 0; j < i; j++) {
            float a = Asm[i * 32 + j];
            f0 += a * X[j * 256 + tid];
            f1 += a * X[j * 256 + 128 + tid];
        }
        X[i * 256 + tid]       -= f0;
        X[i * 256 + 128 + tid] -= f1;
        __syncthreads();
    }

    for (int i = tid; i < 32 * 128; i += 128) {
        int n = i >> 7, m = i & 127;
        W0g[(size_t)ch * 4096 + i] = X[n * 256 + m];
        float tkv = X[n * 256 + 128 + m];
        __nv_bfloat16 th_ = __float2bfloat16(tkv);
        TKh[(size_t)ch * 4096 + i] = th_;
        TKl[(size_t)ch * 4096 + i] = __float2bfloat16(tkv - __bfloat162float(th_));
        float qv = Qc[n * 128 + m];
        __nv_bfloat16 qh_ = __float2bfloat16(qv);
        Qh[(size_t)ch * 4096 + i] = qh_;
        Ql[(size_t)ch * 4096 + i] = __float2bfloat16(qv - __bfloat162float(qh_));
    }
#pragma unroll
    for (int n = 0; n < 32; n++) {
        float kv = Kc[n * 128 + tid];
        __nv_bfloat16 kh_ = __float2bfloat16(kv);
        KTh[(size_t)ch * 4096 + tid * 32 + n] = kh_;
        KTl[(size_t)ch * 4096 + tid * 32 + n] = __float2bfloat16(kv - __bfloat162float(kh_));
    }
}

// ====== SEQ: dv-split x4 (4 CTAs per (b,h)), cp.async operand prefetch ======
// CTA owns 32 of 128 dv columns. S^T [32 dv][128 dk] in MMA accumulators.
#define SST 272   // S/TK/Q row stride bytes (128 bf16 + pad)
#define WST 80    // Wt/KT/P row stride bytes (32 bf16 + pad)
#define OS_SHI 0
#define OS_SLO 8704
#define OS_WTH 17408
#define OS_WTL 19968
#define OS_CS  22528   // colsum[2][32] floats
#define OS_OPS 22784
#define OB_TKH 0
#define OB_TKL 8704
#define OB_QH  17408
#define OB_QL  26112
#define OB_KTH 34816
#define OB_KTL 45056
#define OB_PH  55296
#define OB_PL  57856
#define OB_W0  60416
#define OB_SIZE 64512
#define SEQ_SMEM (OS_OPS + 2 * OB_SIZE)   // 151808

__device__ __forceinline__ void seq_load_ops(uint32_t ob, size_t ch, int dvq, int tid,
    const float* W0g,
    const __nv_bfloat16* TKh, const __nv_bfloat16* TKl,
    const __nv_bfloat16* Qh,  const __nv_bfloat16* Ql,
    const __nv_bfloat16* KTh, const __nv_bfloat16* KTl,
    const __nv_bfloat16* Ph,  const __nv_bfloat16* Pl) {
    for (int i = tid; i < 512; i += 256) {
        int r = i >> 4, q = i & 15;
        size_t g = ch * 4096 + (size_t)r * 128 + q * 8;
        cp16(ob + OB_TKH + r * SST + q * 16, TKh + g);
        cp16(ob + OB_TKL + r * SST + q * 16, TKl + g);
        cp16(ob + OB_QH  + r * SST + q * 16, Qh + g);
        cp16(ob + OB_QL  + r * SST + q * 16, Ql + g);
    }
    for (int i = tid; i < 512; i += 256) {
        int r = i >> 2, q = i & 3;
        size_t g = ch * 4096 + (size_t)r * 32 + q * 8;
        cp16(ob + OB_KTH + r * WST + q * 16, KTh + g);
        cp16(ob + OB_KTL + r * WST + q * 16, KTl + g);
    }
    if (tid < 128) {
        int r = tid >> 2, q = tid & 3;
        size_t g = ch * 1024 + (size_t)r * 32 + q * 8;
        cp16(ob + OB_PH + r * WST + q * 16, Ph + g);
        cp16(ob + OB_PL + r * WST + q * 16, Pl + g);
    }
    {
        int r = tid >> 3, q = tid & 7;   // 256 threads = exactly 32 rows x 8 quads
        cp16(ob + OB_W0 + r * 128 + q * 16,
             W0g + ch * 4096 + (size_t)r * 128 + dvq * 32 + q * 4);
    }
    CP_COMMIT();
}

__global__ void __launch_bounds__(256, 1) seq_chunk(
    const float* __restrict__ W0g,
    const __nv_bfloat16* __restrict__ TKh, const __nv_bfloat16* __restrict__ TKl,
    const __nv_bfloat16* __restrict__ Qh,  const __nv_bfloat16* __restrict__ Ql,
    const __nv_bfloat16* __restrict__ KTh, const __nv_bfloat16* __restrict__ KTl,
    const __nv_bfloat16* __restrict__ Ph,  const __nv_bfloat16* __restrict__ Pl,
    const float* __restrict__ wnorm, float* __restrict__ o,
    float* __restrict__ oss) {
    extern __shared__ char smraw[];
    const int bh  = blockIdx.x >> 2;
    const int dvq = blockIdx.x & 3;          // which 32-wide dv quarter
    const int b = bh >> 4, h = bh & 15;
    const int tid = threadIdx.x, wid = tid >> 5, lane = tid & 31;
    const uint32_t sb = smem_u32(smraw);
    float* colsum = (float*)(smraw + OS_CS); // [2][32]

    // prologue: prefetch chunk 0 operands while zeroing S
    seq_load_ops(sb + OS_OPS, (size_t)bh * NC_, dvq, tid,
                 W0g, TKh, TKl, Qh, Ql, KTh, KTl, Ph, Pl);
    for (int i = tid; i < OS_OPS / 16; i += 256)
        ((uint4*)smraw)[i] = make_uint4(0, 0, 0, 0);

    float Sfr[4][4];                         // [ni dk8][frag] ; m = 16 dv rows
#pragma unroll
    for (int ni = 0; ni < 4; ni++)
#pragma unroll
        for (int e = 0; e < 4; e++) Sfr[ni][e] = 0.f;

    const int wm   = (wid & 1) * 16;         // dv offset within 32
    const int tg   = wid >> 1;               // 0..3
    const int wn8  = tg * 8;                 // token group (steps 1/2)
    const int wn32 = tg * 32;                // dk group (step 3)
    const int a_r = lane & 15, a_cB = (lane >> 4) << 4;
    const int b_r = lane & 7,  b_cB = ((lane >> 3) & 1) << 4;
    const int fr = lane >> 2, fc = (lane & 3) * 2;

    float wnr[2];
#pragma unroll
    for (int pp = 0; pp < 2; pp++)
        wnr[pp] = wnorm[dvq * 32 + wm + pp * 8 + fr];

    for (int c = 0; c < NC_; c++) {
        const size_t ch = (size_t)bh * NC_ + c;
        const int cb = c & 1;
        const uint32_t ob = sb + OS_OPS + cb * OB_SIZE;
        float* W0s = (float*)(smraw + OS_OPS + cb * OB_SIZE + OB_W0);

        __syncthreads();                     // prev compute done; other op-buffer free
        if (c + 1 < NC_)
            seq_load_ops(sb + OS_OPS + (1 - cb) * OB_SIZE, ch + 1, dvq, tid,
                         W0g, TKh, TKl, Qh, Ql, KTh, KTl, Ph, Pl);
        else
            CP_COMMIT();
        CP_WAIT(1);                          // chunk c operands resident
        __syncthreads();

        // ---- step 1: Wt = W0^T - Ssm @ TK^T  (m = 16 dv, n = 8 tokens) ----
        float acc[4];
#pragma unroll
        for (int e = 0; e < 4; e++) acc[e] = 0.f;
#pragma unroll
        for (int ks = 0; ks < 8; ks++) {
            uint32_t ah[4], al[4], bhf[2], blf[2];
            uint32_t offa = (wm + a_r) * SST + a_cB + ks * 32;
            LDSM_X4(ah[0], ah[1], ah[2], ah[3], sb + OS_SHI + offa);
            LDSM_X4(al[0], al[1], al[2], al[3], sb + OS_SLO + offa);
            uint32_t offb = (wn8 + b_r) * SST + b_cB + ks * 32;
            LDSM_X2(bhf[0], bhf[1], ob + OB_TKH + offb);
            LDSM_X2(blf[0], blf[1], ob + OB_TKL + offb);
            mma_bf16(acc, ah, bhf);
            mma_bf16(acc, ah, blf);
            mma_bf16(acc, al, bhf);
        }
#pragma unroll
        for (int pp = 0; pp < 2; pp++) {
            int m = wm + fr + pp * 8;        // dv 0..31
            int n0 = wn8 + fc;               // token
            float v0 = W0s[n0 * 32 + m] - acc[pp * 2 + 0];
            float v1 = W0s[(n0 + 1) * 32 + m] - acc[pp * 2 + 1];
            uint32_t lo, hi = pack_split(v0, v1, lo);
            *(uint32_t*)(smraw + OS_WTH + m * WST + n0 * 2) = hi;
            *(uint32_t*)(smraw + OS_WTL + m * WST + n0 * 2) = lo;
        }
        __syncthreads();

        // ---- step 2: Ot = Ssm @ Q^T + Wt @ P^T ----
        float oacc[4];
#pragma unroll
        for (int e = 0; e < 4; e++) oacc[e] = 0.f;
#pragma unroll
        for (int ks = 0; ks < 8; ks++) {
            uint32_t ah[4], al[4], bhf[2], blf[2];
            uint32_t offa = (wm + a_r) * SST + a_cB + ks * 32;
            LDSM_X4(ah[0], ah[1], ah[2], ah[3], sb + OS_SHI + offa);
            LDSM_X4(al[0], al[1], al[2], al[3], sb + OS_SLO + offa);
            uint32_t offb = (wn8 + b_r) * SST + b_cB + ks * 32;
            LDSM_X2(bhf[0], bhf[1], ob + OB_QH + offb);
            LDSM_X2(blf[0], blf[1], ob + OB_QL + offb);
            mma_bf16(oacc, ah, bhf);
            mma_bf16(oacc, ah, blf);
            mma_bf16(oacc, al, bhf);
        }
#pragma unroll
        for (int ks = 0; ks < 2; ks++) {
            uint32_t ah[4], al[4], bhf[2], blf[2];
            uint32_t offa = (wm + a_r) * WST + a_cB + ks * 32;
            LDSM_X4(ah[0], ah[1], ah[2], ah[3], sb + OS_WTH + offa);
            LDSM_X4(al[0], al[1], al[2], al[3], sb + OS_WTL + offa);
            uint32_t offb = (wn8 + b_r) * WST + b_cB + ks * 32;
            LDSM_X2(bhf[0], bhf[1], ob + OB_PH + offb);
            LDSM_X2(blf[0], blf[1], ob + OB_PL + offb);
            mma_bf16(oacc, ah, bhf);
            mma_bf16(oacc, ah, blf);
            mma_bf16(oacc, al, bhf);
        }
        // partial sumsq over this CTA's 32 dv
        {
            float s0 = oacc[0] * oacc[0] + oacc[2] * oacc[2];
            float s1 = oacc[1] * oacc[1] + oacc[3] * oacc[3];
#pragma unroll
            for (int off = 4; off <= 16; off <<= 1) {
                s0 += __shfl_xor_sync(0xffffffffu, s0, off);
                s1 += __shfl_xor_sync(0xffffffffu, s1, off);
            }
            if (lane < 4) {
                atomicAdd(&colsum[cb * 32 + wn8 + 2 * lane], s0);
                atomicAdd(&colsum[cb * 32 + wn8 + 2 * lane + 1], s1);
            }
        }
        __syncthreads();

        // store o (unnormalized * wn) + publish partial sumsq; zero other colsum
        {
            const size_t obase = (size_t)b * L_ * D_ + (size_t)h * DH_ + (size_t)(c * C_) * D_
                               + dvq * 32;
            int n0 = wn8 + fc;
#pragma unroll
            for (int pp = 0; pp < 2; pp++) {
                int m = wm + fr + pp * 8;
                o[obase + (size_t)n0 * D_ + m] = oacc[pp * 2] * wnr[pp];
                o[obase + (size_t)(n0 + 1) * D_ + m] = oacc[pp * 2 + 1] * wnr[pp];
            }
            if (tid < 32) {
                oss[(size_t)dvq * (M_ * H_) + ((size_t)b * L_ + c * C_ + tid) * H_ + h]
                    = colsum[cb * 32 + tid];
                colsum[(1 - cb) * 32 + tid] = 0.f;
            }
        }

        // ---- step 3: Ssm += Wt @ K  (n = 32 dk per warp) ----
#pragma unroll
        for (int ks = 0; ks < 2; ks++) {
            uint32_t ah[4], al[4];
            uint32_t offa = (wm + a_r) * WST + a_cB + ks * 32;
            LDSM_X4(ah[0], ah[1], ah[2], ah[3], sb + OS_WTH + offa);
            LDSM_X4(al[0], al[1], al[2], al[3], sb + OS_WTL + offa);
#pragma unroll
            for (int ni = 0; ni < 4; ni++) {
                uint32_t bhf[2], blf[2];
                uint32_t offb = (wn32 + ni * 8 + b_r) * WST + b_cB + ks * 32;
                LDSM_X2(bhf[0], bhf[1], ob + OB_KTH + offb);
                LDSM_X2(blf[0], blf[1], ob + OB_KTL + offb);
                mma_bf16(Sfr[ni], ah, bhf);
                mma_bf16(Sfr[ni], ah, blf);
                mma_bf16(Sfr[ni], al, bhf);
            }
        }
#pragma unroll
        for (int ni = 0; ni < 4; ni++)
#pragma unroll
            for (int pp = 0; pp < 2; pp++) {
                int m = wm + fr + pp * 8;
                int n0 = wn32 + ni * 8 + fc;
                uint32_t lo, hi = pack_split(Sfr[ni][pp * 2], Sfr[ni][pp * 2 + 1], lo);
                *(uint32_t*)(smraw + OS_SHI + m * SST + n0 * 2) = hi;
                *(uint32_t*)(smraw + OS_SLO + m * SST + n0 * 2) = lo;
            }
    }
}

// ================= launch =================
extern "C" void kernel_launch(void* const* d_in, const int* in_sizes, int n_in,
                              void* d_out, int out_size) {
    const float* X  = (const float*)d_in[0];
    const float* Wq = (const float*)d_in[1];
    const float* Wk = (const float*)d_in[2];
    const float* Wv = (const float*)d_in[3];
    const float* Wb = (const float*)d_in[4];
    const float* wn = (const float*)d_in[5];
    const float* Wo = (const float*)d_in[6];
    float* out = (float*)d_out;

    float *gq, *gk, *gv, *go, *gb, *gW0, *gss;
    __half *ahi, *alo, *wt;
    __nv_bfloat16 *tkh, *tkl, *qch, *qcl, *kth, *ktl, *ph, *pl;
    cudaGetSymbolAddress((void**)&gq, g_q);
    cudaGetSymbolAddress((void**)&gk, g_k);
    cudaGetSymbolAddress((void**)&gv, g_v);
    cudaGetSymbolAddress((void**)&go, g_o);
    cudaGetSymbolAddress((void**)&gb, g_beta);
    cudaGetSymbolAddress((void**)&gss, g_ss);
    cudaGetSymbolAddress((void**)&ahi, g_Ahi);
    cudaGetSymbolAddress((void**)&alo, g_Alo);
    cudaGetSymbolAddress((void**)&wt, g_Wt);
    cudaGetSymbolAddress((void**)&gW0, g_W0);
    cudaGetSymbolAddress((void**)&tkh, g_TKh);
    cudaGetSymbolAddress((void**)&tkl, g_TKl);
    cudaGetSymbolAddress((void**)&qch, g_Qch);
    cudaGetSymbolAddress((void**)&qcl, g_Qcl);
    cudaGetSymbolAddress((void**)&kth, g_KTh);
    cudaGetSymbolAddress((void**)&ktl, g_KTl);
    cudaGetSymbolAddress((void**)&ph, g_Ph);
    cudaGetSymbolAddress((void**)&pl, g_Pl);

    cudaFuncSetAttribute(gemm_f16split, cudaFuncAttributeMaxDynamicSharedMemorySize, SMEM_DYN);
    cudaFuncSetAttribute(pre_chunk, cudaFuncAttributeMaxDynamicSharedMemorySize, 69760);
    cudaFuncSetAttribute(seq_chunk, cudaFuncAttributeMaxDynamicSharedMemorySize, SEQ_SMEM);

    const int NSPLIT = M_ * D_ / 4 / 256;

    split_rows<<<NSPLIT, 256>>>((const float4*)X, (uint2*)ahi, (uint2*)alo);
    split_transpose<<<dim3(D_ / 32, D_ / 32, 4), dim3(32, 8)>>>(Wq, Wk, Wv, Wo, wt);

    GemmArgs qa;
    qa.Bw[0] = wt;
    qa.Bw[1] = wt + (size_t)D_ * D_;
    qa.Bw[2] = wt + (size_t)2 * D_ * D_;
    qa.C[0] = gq; qa.C[1] = gk; qa.C[2] = gv;
    qa.mode[0] = 0; qa.mode[1] = 0; qa.mode[2] = 1;
    gemm_f16split<<<dim3(D_ / BN, M_ / BM, 3), 256, SMEM_DYN>>>(ahi, alo, qa);

    beta_gemm<<<M_ / 16, 256>>>(X, Wb, gb);

    pre_chunk<<<NCH_, 128, 69760>>>(gq, gk, gv, gb, gW0, tkh, tkl, qch, qcl, kth, ktl, ph, pl);
    seq_chunk<<<4 * B_ * H_, 256, SEQ_SMEM>>>(gW0, tkh, tkl, qch, qcl, kth, ktl, ph, pl, wn, go, gss);

    split_rows_norm<<<NSPLIT, 256>>>((const float4*)go, (uint2*)ahi, (uint2*)alo, gss);
    GemmArgs oa;
    oa.Bw[0] = wt + (size_t)3 * D_ * D_;
    oa.Bw[1] = oa.Bw[0];
    oa.Bw[2] = oa.Bw[0];
    oa.C[0] = out; oa.C[1] = out; oa.C[2] = out;
    oa.mode[0] = 0; oa.mode[1] = 0; oa.mode[2] = 0;
    gemm_f16split<<<dim3(D_ / BN, M_ / BM, 1), 256, SMEM_DYN>>>(ahi, alo, oa);
}